// round 1
// baseline (speedup 1.0000x reference)
#include <cuda_runtime.h>
#include <math.h>

// Problem constants
#define SEQ   2048
#define NB    2
#define NH    16
#define HDIM  64
#define DM    1024
#define BHT   (NB*NH)        // 32 batch*heads
#define MROWS (NB*SEQ)       // 4096

// GEMM tile config
#define BM 128
#define BN 64
#define BK 16
#define LDAS 20              // padded smem stride for A (conflict-free frag fetch)
#define LDBS 72              // padded smem stride for B (conflict-free frag fetch)

// ---------------- scratch (device globals: allocation-free) ----------------
__device__ float g_q [BHT*SEQ*HDIM];
__device__ float g_k [BHT*SEQ*HDIM];
__device__ float g_v [BHT*SEQ*HDIM];
__device__ float g_qb[BHT*SEQ*HDIM];
__device__ float g_kb[BHT*SEQ*HDIM];
__device__ float g_vb[BHT*SEQ*HDIM];
__device__ float g_scores[(size_t)BHT*SEQ*SEQ];   // 512 MB
__device__ float g_fwd  [(size_t)MROWS*DM];
__device__ float g_bwd  [(size_t)MROWS*DM];
__device__ float g_gpre [(size_t)MROWS*DM];
__device__ float g_fused[(size_t)MROWS*DM];
__device__ float g_out2 [(size_t)MROWS*DM];

// ---------------- helpers ----------------
__device__ __forceinline__ unsigned f2tf32(float f) {
    unsigned u;
    asm("cvt.rna.tf32.f32 %0, %1;" : "=r"(u) : "f"(f));
    return u;
}

__device__ __forceinline__ void mma8(float* c, const unsigned* a, unsigned b0, unsigned b1) {
    asm volatile(
        "mma.sync.aligned.m16n8k8.row.col.f32.tf32.tf32.f32 "
        "{%0,%1,%2,%3}, {%4,%5,%6,%7}, {%8,%9}, {%0,%1,%2,%3};"
        : "+f"(c[0]), "+f"(c[1]), "+f"(c[2]), "+f"(c[3])
        : "r"(a[0]), "r"(a[1]), "r"(a[2]), "r"(a[3]), "r"(b0), "r"(b1));
}

__device__ __forceinline__ float sigmoidf_(float x) { return 1.f / (1.f + __expf(-x)); }

// ---------------- unified TF32 GEMM ----------------
// mode 0: proj   C[headlayout] = A0[M,K] @ B[K,N] + bias       (A row stride = KA0 = K)
// mode 1: dense  C[M,N]        = concat(A0|A1)[M,K] @ B[K,N] + bias  (split at KA0)
// mode 2: score  C[z][M,N=SEQ] = Q[z][M,64] @ K[z][N,64]^T     (skip fully-causal-masked tiles)
// mode 3: pv     fwd[merge]    = P[z][M,SEQ] @ V[z][SEQ,64]    (K loop limited to m0+BM)
__global__ void __launch_bounds__(128) gemm_kernel(
    const float* __restrict__ A0, const float* __restrict__ A1,
    const float* __restrict__ Bmat, const float* __restrict__ bias,
    float* __restrict__ C, int N, int K, int KA0, int mode)
{
    const int nb = blockIdx.x, mb = blockIdx.y, z = blockIdx.z;
    const int m0 = mb * BM, n0 = nb * BN;

    const float* Ap = A0;
    const float* Bp = Bmat;
    float*       Cp = C;
    int kmax = K;
    if (mode == 2) {
        if (n0 >= m0 + BM) return;                      // fully masked tile
        Ap = A0   + (size_t)z * SEQ * HDIM;
        Bp = Bmat + (size_t)z * SEQ * HDIM;
        Cp = C    + (size_t)z * SEQ * SEQ;
    } else if (mode == 3) {
        Ap = A0   + (size_t)z * SEQ * SEQ;
        Bp = Bmat + (size_t)z * SEQ * HDIM;
        kmax = min(K, m0 + BM);                         // causal K trim
    }

    __shared__ unsigned As[BM * LDAS];
    __shared__ unsigned Bs[BK * LDBS];

    const int tid  = threadIdx.x;
    const int lane = tid & 31;
    const int warp = tid >> 5;
    const int qrow = lane >> 2;       // 0..7
    const int qcol = lane & 3;        // 0..3

    float acc[2][8][4];
#pragma unroll
    for (int i = 0; i < 2; i++)
#pragma unroll
        for (int j = 0; j < 8; j++)
#pragma unroll
            for (int t = 0; t < 4; t++) acc[i][j][t] = 0.f;

    for (int ks = 0; ks < kmax; ks += BK) {
        // --- load A tile (BM x BK), convert to tf32 ---
#pragma unroll
        for (int i = 0; i < (BM * BK) / 128; i++) {
            int e = i * 128 + tid;
            int mm = e >> 4, kk = e & 15;
            int gm = m0 + mm, gk = ks + kk;
            float v;
            if (mode == 2)      v = Ap[gm * HDIM + gk];
            else if (mode == 3) v = Ap[(size_t)gm * SEQ + gk];
            else                v = (gk < KA0) ? A0[(size_t)gm * KA0 + gk]
                                               : A1[(size_t)gm * KA0 + (gk - KA0)];
            As[mm * LDAS + kk] = f2tf32(v);
        }
        // --- load B tile (BK x BN), convert to tf32 ---
#pragma unroll
        for (int i = 0; i < (BK * BN) / 128; i++) {
            int e = i * 128 + tid;
            float v; int kk, nn;
            if (mode == 2) {                 // Bs[k][n] = Kmat[n0+n][ks+k]
                nn = e >> 4; kk = e & 15;
                v = Bp[(size_t)(n0 + nn) * HDIM + ks + kk];
            } else if (mode == 3) {          // V is [k][n] already
                kk = e >> 6; nn = e & 63;
                v = Bp[(size_t)(ks + kk) * HDIM + nn];
            } else {                         // weights row-major [K][N]
                kk = e >> 6; nn = e & 63;
                v = Bp[(size_t)(ks + kk) * N + n0 + nn];
            }
            Bs[kk * LDBS + nn] = f2tf32(v);
        }
        __syncthreads();

        // --- MMA: 2 k8-steps, 2 m-frags x 8 n-frags per warp ---
#pragma unroll
        for (int kk = 0; kk < BK; kk += 8) {
            unsigned a[2][4];
#pragma unroll
            for (int mf = 0; mf < 2; mf++) {
                int r = warp * 32 + mf * 16 + qrow;
                int c = kk + qcol;
                a[mf][0] = As[r * LDAS + c];
                a[mf][1] = As[(r + 8) * LDAS + c];
                a[mf][2] = As[r * LDAS + c + 4];
                a[mf][3] = As[(r + 8) * LDAS + c + 4];
            }
#pragma unroll
            for (int nf = 0; nf < 8; nf++) {
                unsigned b0 = Bs[(kk + qcol) * LDBS + nf * 8 + qrow];
                unsigned b1 = Bs[(kk + 4 + qcol) * LDBS + nf * 8 + qrow];
                mma8(acc[0][nf], a[0], b0, b1);
                mma8(acc[1][nf], a[1], b0, b1);
            }
        }
        __syncthreads();
    }

    // --- epilogue ---
#pragma unroll
    for (int mf = 0; mf < 2; mf++) {
#pragma unroll
        for (int nf = 0; nf < 8; nf++) {
#pragma unroll
            for (int t = 0; t < 4; t++) {
                int r   = m0 + warp * 32 + mf * 16 + qrow + ((t >> 1) << 3);
                int col = n0 + nf * 8 + qcol * 2 + (t & 1);
                float v = acc[mf][nf][t];
                if (bias) v += bias[col];
                if (mode == 0) {             // [B,S,D] row -> [BH,S,HD] head layout
                    int b = r >> 11, s = r & (SEQ - 1);
                    int h = col >> 6, hd = col & 63;
                    Cp[((size_t)(b * NH + h) * SEQ + s) * HDIM + hd] = v;
                } else if (mode == 2) {
                    Cp[(size_t)r * SEQ + col] = v;
                } else if (mode == 3) {      // merge heads -> [B,S,D]
                    int b = z >> 4, h = z & 15;
                    Cp[((size_t)(b * SEQ + r)) * DM + h * HDIM + col] = v;
                } else {
                    Cp[(size_t)r * N + col] = v;
                }
            }
        }
    }
}

// ---------------- causal softmax (single global read + write per row) ----------------
__global__ void softmax_kernel(float* __restrict__ Sc) {
    const int m = blockIdx.x, bh = blockIdx.y;
    float* row = Sc + ((size_t)bh * SEQ + m) * SEQ;
    const int n = m + 1;                   // valid length (causal)
    const int tid = threadIdx.x;
    __shared__ float red[256];

    float r[8];
#pragma unroll
    for (int i = 0; i < 8; i++) {
        int j = tid + i * 256;
        r[i] = (j < n) ? row[j] * 0.125f : -1e30f;   // scale = 1/sqrt(64)
    }
    float mx = r[0];
#pragma unroll
    for (int i = 1; i < 8; i++) mx = fmaxf(mx, r[i]);
    red[tid] = mx; __syncthreads();
    for (int s = 128; s > 0; s >>= 1) { if (tid < s) red[tid] = fmaxf(red[tid], red[tid + s]); __syncthreads(); }
    mx = red[0]; __syncthreads();

    float sum = 0.f;
#pragma unroll
    for (int i = 0; i < 8; i++) { r[i] = __expf(r[i] - mx); sum += r[i]; }
    red[tid] = sum; __syncthreads();
    for (int s = 128; s > 0; s >>= 1) { if (tid < s) red[tid] += red[tid + s]; __syncthreads(); }
    float inv = 1.f / red[0];

#pragma unroll
    for (int i = 0; i < 8; i++) {
        int j = tid + i * 256;
        row[j] = (j < n) ? r[i] * inv : 0.f;         // zero masked region for PV GEMM
    }
}

// ---------------- window-32 backward attention: one warp per query ----------------
__global__ void bwd_attn_kernel(const float* __restrict__ Qb, const float* __restrict__ Kb,
                                const float* __restrict__ Vb, float* __restrict__ bwd) {
    __shared__ float qsh[8][HDIM];
    const int tid = threadIdx.x;
    const int wid = tid >> 5, lane = tid & 31;
    const int idx = blockIdx.x * 8 + wid;         // 0 .. BHT*SEQ-1
    const int bh = idx >> 11, m = idx & (SEQ - 1);
    const float* Qp = Qb + (size_t)bh * SEQ * HDIM;
    const float* Kp = Kb + (size_t)bh * SEQ * HDIM;
    const float* Vp = Vb + (size_t)bh * SEQ * HDIM;
    const int b = bh >> 4, h = bh & 15;
    float* outp = bwd + ((size_t)(b * SEQ + m)) * DM + h * HDIM;

    int w = SEQ - 1 - m; if (w > 32) w = 32;
    float o0, o1;
    if (w == 0) {
        // all-masked row: reference resets scores to 0 -> uniform softmax over ALL S keys
        float s0 = 0.f, s1 = 0.f;
        for (int s = 0; s < SEQ; s++) {
            s0 += Vp[s * HDIM + lane];
            s1 += Vp[s * HDIM + lane + 32];
        }
        o0 = s0 * (1.f / SEQ); o1 = s1 * (1.f / SEQ);
    } else {
        qsh[wid][lane]      = Qp[m * HDIM + lane];
        qsh[wid][lane + 32] = Qp[m * HDIM + lane + 32];
        __syncwarp();
        float sc = -1e30f;
        if (lane < w) {
            const float* kr = Kp + (size_t)(m + 1 + lane) * HDIM;
            float a = 0.f;
#pragma unroll
            for (int d = 0; d < HDIM; d++) a += qsh[wid][d] * kr[d];
            sc = a * 0.125f;
        }
        float mx = sc;
#pragma unroll
        for (int o = 16; o > 0; o >>= 1) mx = fmaxf(mx, __shfl_xor_sync(0xffffffffu, mx, o));
        float e = __expf(sc - mx);                 // invalid lanes -> 0
        float sum = e;
#pragma unroll
        for (int o = 16; o > 0; o >>= 1) sum += __shfl_xor_sync(0xffffffffu, sum, o);
        float p = e / sum;
        o0 = 0.f; o1 = 0.f;
        for (int kk = 0; kk < w; kk++) {
            float pk = __shfl_sync(0xffffffffu, p, kk);
            const float* vr = Vp + (size_t)(m + 1 + kk) * HDIM;
            o0 += pk * vr[lane];
            o1 += pk * vr[lane + 32];
        }
    }
    outp[lane] = o0; outp[lane + 32] = o1;
}

// ---------------- gate LN + sigmoid + fusion ----------------
__global__ void gate_fuse_kernel(const float* __restrict__ gpre, const float* __restrict__ fwd,
                                 const float* __restrict__ bwd, const float* __restrict__ gg,
                                 const float* __restrict__ gb, const float* __restrict__ bstr,
                                 float* __restrict__ fused) {
    const int r = blockIdx.x, tid = threadIdx.x;
    const float* rowp = gpre + (size_t)r * DM;
    __shared__ float red[256];
    float v[4]; float s = 0.f, ss = 0.f;
#pragma unroll
    for (int i = 0; i < 4; i++) { v[i] = rowp[tid + i * 256]; s += v[i]; ss += v[i] * v[i]; }
    red[tid] = s; __syncthreads();
    for (int o = 128; o > 0; o >>= 1) { if (tid < o) red[tid] += red[tid + o]; __syncthreads(); }
    float mean = red[0] * (1.f / DM); __syncthreads();
    red[tid] = ss; __syncthreads();
    for (int o = 128; o > 0; o >>= 1) { if (tid < o) red[tid] += red[tid + o]; __syncthreads(); }
    float var = red[0] * (1.f / DM) - mean * mean;
    float rstd = rsqrtf(var + 1e-5f);
    float strength = 0.3f * sigmoidf_(bstr[0]);
#pragma unroll
    for (int i = 0; i < 4; i++) {
        int j = tid + i * 256;
        float g = sigmoidf_((v[i] - mean) * rstd * gg[j] + gb[j]);
        size_t o = (size_t)r * DM + j;
        fused[o] = fwd[o] + strength * g * bwd[o];
    }
}

// ---------------- final residual + LayerNorm ----------------
__global__ void final_ln_kernel(const float* __restrict__ x, const float* __restrict__ o2,
                                const float* __restrict__ lg, const float* __restrict__ lb,
                                float* __restrict__ out) {
    const int r = blockIdx.x, tid = threadIdx.x;
    __shared__ float red[256];
    float v[4]; float s = 0.f, ss = 0.f;
#pragma unroll
    for (int i = 0; i < 4; i++) {
        size_t o = (size_t)r * DM + tid + i * 256;
        v[i] = x[o] + o2[o];
        s += v[i]; ss += v[i] * v[i];
    }
    red[tid] = s; __syncthreads();
    for (int o = 128; o > 0; o >>= 1) { if (tid < o) red[tid] += red[tid + o]; __syncthreads(); }
    float mean = red[0] * (1.f / DM); __syncthreads();
    red[tid] = ss; __syncthreads();
    for (int o = 128; o > 0; o >>= 1) { if (tid < o) red[tid] += red[tid + o]; __syncthreads(); }
    float var = red[0] * (1.f / DM) - mean * mean;
    float rstd = rsqrtf(var + 1e-5f);
#pragma unroll
    for (int i = 0; i < 4; i++) {
        int j = tid + i * 256;
        size_t o = (size_t)r * DM + j;
        out[o] = (v[i] - mean) * rstd * lg[j] + lb[j];
    }
}

// ---------------- launch ----------------
extern "C" void kernel_launch(void* const* d_in, const int* in_sizes, int n_in,
                              void* d_out, int out_size) {
    const float* x      = (const float*)d_in[0];
    const float* fq_w   = (const float*)d_in[1];
    const float* fq_b   = (const float*)d_in[2];
    const float* fk_w   = (const float*)d_in[3];
    const float* fk_b   = (const float*)d_in[4];
    const float* fv_w   = (const float*)d_in[5];
    const float* fv_b   = (const float*)d_in[6];
    const float* bq_w   = (const float*)d_in[7];
    const float* bq_b   = (const float*)d_in[8];
    const float* bk_w   = (const float*)d_in[9];
    const float* bk_b   = (const float*)d_in[10];
    const float* bv_w   = (const float*)d_in[11];
    const float* bv_b   = (const float*)d_in[12];
    const float* gate_w = (const float*)d_in[13];
    const float* gate_b = (const float*)d_in[14];
    const float* gln_g  = (const float*)d_in[15];
    const float* gln_b  = (const float*)d_in[16];
    const float* bstr   = (const float*)d_in[17];
    const float* out_w  = (const float*)d_in[18];
    const float* out_b  = (const float*)d_in[19];
    const float* ln_g   = (const float*)d_in[20];
    const float* ln_b   = (const float*)d_in[21];

    float *q, *k, *v, *qb, *kb, *vb, *sc, *fwd, *bwd, *gpre, *fused, *out2;
    cudaGetSymbolAddress((void**)&q,     g_q);
    cudaGetSymbolAddress((void**)&k,     g_k);
    cudaGetSymbolAddress((void**)&v,     g_v);
    cudaGetSymbolAddress((void**)&qb,    g_qb);
    cudaGetSymbolAddress((void**)&kb,    g_kb);
    cudaGetSymbolAddress((void**)&vb,    g_vb);
    cudaGetSymbolAddress((void**)&sc,    g_scores);
    cudaGetSymbolAddress((void**)&fwd,   g_fwd);
    cudaGetSymbolAddress((void**)&bwd,   g_bwd);
    cudaGetSymbolAddress((void**)&gpre,  g_gpre);
    cudaGetSymbolAddress((void**)&fused, g_fused);
    cudaGetSymbolAddress((void**)&out2,  g_out2);

    dim3 blk(128);
    dim3 gProj(DM / BN, MROWS / BM, 1);          // (16, 32)

    // 6 projections -> head layout [BH,S,HD]
    gemm_kernel<<<gProj, blk>>>(x, x, fq_w, fq_b, q,  DM, DM, DM, 0);
    gemm_kernel<<<gProj, blk>>>(x, x, fk_w, fk_b, k,  DM, DM, DM, 0);
    gemm_kernel<<<gProj, blk>>>(x, x, fv_w, fv_b, v,  DM, DM, DM, 0);
    gemm_kernel<<<gProj, blk>>>(x, x, bq_w, bq_b, qb, DM, DM, DM, 0);
    gemm_kernel<<<gProj, blk>>>(x, x, bk_w, bk_b, kb, DM, DM, DM, 0);
    gemm_kernel<<<gProj, blk>>>(x, x, bv_w, bv_b, vb, DM, DM, DM, 0);

    // causal attention: scores -> softmax -> PV (merged to [B,S,D])
    gemm_kernel<<<dim3(SEQ / BN, SEQ / BM, BHT), blk>>>(q, q, k, nullptr, sc, SEQ, HDIM, HDIM, 2);
    softmax_kernel<<<dim3(SEQ, BHT), 256>>>(sc);
    gemm_kernel<<<dim3(1, SEQ / BM, BHT), blk>>>(sc, sc, v, nullptr, fwd, HDIM, SEQ, SEQ, 3);

    // window backward attention
    bwd_attn_kernel<<<(BHT * SEQ) / 8, 256>>>(qb, kb, vb, bwd);

    // gated fusion
    gemm_kernel<<<gProj, blk>>>(fwd, bwd, gate_w, gate_b, gpre, DM, 2 * DM, DM, 1);
    gate_fuse_kernel<<<MROWS, 256>>>(gpre, fwd, bwd, gln_g, gln_b, bstr, fused);

    // output projection + residual LN
    gemm_kernel<<<gProj, blk>>>(fused, fused, out_w, out_b, out2, DM, DM, DM, 1);
    final_ln_kernel<<<MROWS, 256>>>(x, out2, ln_g, ln_b, (float*)d_out);
}

// round 4
// speedup vs baseline: 2.4822x; 2.4822x over previous
#include <cuda_runtime.h>
#include <math.h>

// Problem constants
#define SEQ   2048
#define NB    2
#define NH    16
#define HDIM  64
#define DM    1024
#define BHT   (NB*NH)        // 32 batch*heads
#define MROWS (NB*SEQ)       // 4096

// GEMM tile config
#define BM 128
#define BK 16
#define LDA 20               // padded A smem stride (conflict-free, 8B-aligned)

// ---------------- scratch (device globals: allocation-free) ----------------
__device__ float g_q [BHT*SEQ*HDIM];
__device__ float g_k [BHT*SEQ*HDIM];
__device__ float g_v [BHT*SEQ*HDIM];
__device__ float g_qb[BHT*SEQ*HDIM];
__device__ float g_kb[BHT*SEQ*HDIM];
__device__ float g_vb[BHT*SEQ*HDIM];
__device__ float g_scores[(size_t)BHT*SEQ*SEQ];   // 512 MB
__device__ float g_fwd  [(size_t)MROWS*DM];
__device__ float g_bwd  [(size_t)MROWS*DM];
__device__ float g_gpre [(size_t)MROWS*DM];
__device__ float g_fused[(size_t)MROWS*DM];
__device__ float g_out2 [(size_t)MROWS*DM];

// ---------------- helpers ----------------
__device__ __forceinline__ void cpa8(unsigned dst, const float* src) {
    asm volatile("cp.async.ca.shared.global [%0], [%1], 8;" :: "r"(dst), "l"(src));
}
__device__ __forceinline__ void cp_commit() { asm volatile("cp.async.commit_group;"); }
template<int N> __device__ __forceinline__ void cp_wait() {
    asm volatile("cp.async.wait_group %0;" :: "n"(N));
}

__device__ __forceinline__ void mma8(float* c, const unsigned* a, unsigned b0, unsigned b1) {
    asm volatile(
        "mma.sync.aligned.m16n8k8.row.col.f32.tf32.tf32.f32 "
        "{%0,%1,%2,%3}, {%4,%5,%6,%7}, {%8,%9}, {%0,%1,%2,%3};"
        : "+f"(c[0]), "+f"(c[1]), "+f"(c[2]), "+f"(c[3])
        : "r"(a[0]), "r"(a[1]), "r"(a[2]), "r"(a[3]), "r"(b0), "r"(b1));
}

__device__ __forceinline__ float sigmoidf_(float x) { return 1.f / (1.f + __expf(-x)); }

struct GArgs {
    const float *A0, *A1, *B, *bias;
    float* C;
    int N, K, KA0;
    const float* w6[6]; const float* b6[6]; float* o6[6];
};

// MODE 0: proj6   C(head layout) = x @ w6[z] + b6[z]
// MODE 1: dense   C[M,N] = concat(A0|A1) @ B + bias
// MODE 2: scores  C[z] = Q[z] @ K[z]^T  (skip fully-masked tiles)
// MODE 3: pv      fwd(merge) = P[z] @ V[z]  (K trimmed to m0+BM)
template<int MODE, int BNT>
__device__ __forceinline__ void issue_tile(
    const GArgs& g, const float* Ap, const float* Bp,
    float* As, float* Bs, int m0, int n0, int ks, int tid)
{
    constexpr int LDB = BNT + 8;
    unsigned aBase = (unsigned)__cvta_generic_to_shared(As);
    unsigned bBase = (unsigned)__cvta_generic_to_shared(Bs);
    // A tile: BM x BK
#pragma unroll
    for (int i = 0; i < 4; i++) {
        int e = i * 256 + tid, mm = e >> 3, kk = (e & 7) * 2;
        const float* src;
        if (MODE == 0)      src = Ap + (size_t)(m0 + mm) * DM + ks + kk;
        else if (MODE == 1) { int gk = ks + kk;
            src = (gk < g.KA0) ? g.A0 + (size_t)(m0 + mm) * g.KA0 + gk
                               : g.A1 + (size_t)(m0 + mm) * g.KA0 + (gk - g.KA0); }
        else if (MODE == 2) src = Ap + (m0 + mm) * HDIM + ks + kk;
        else                src = Ap + (size_t)(m0 + mm) * SEQ + ks + kk;
        cpa8(aBase + (unsigned)(mm * LDA + kk) * 4u, src);
    }
    // B tile: BK x BNT
    if (MODE == 2) {          // transpose load: Bs[k][n] = K[n][k]
#pragma unroll
        for (int i = 0; i < 4; i++) {
            int e = i * 256 + tid, nn = e >> 3, kk = (e & 7) * 2;
            float2 t = *reinterpret_cast<const float2*>(Bp + (n0 + nn) * HDIM + ks + kk);
            Bs[kk * LDB + nn] = t.x;
            Bs[(kk + 1) * LDB + nn] = t.y;
        }
    } else if (MODE == 3) {   // V: [k][64]
#pragma unroll
        for (int i = 0; i < 2; i++) {
            int e = i * 256 + tid, kk = e >> 5, nn = (e & 31) * 2;
            cpa8(bBase + (unsigned)(kk * LDB + nn) * 4u, Bp + (size_t)(ks + kk) * HDIM + nn);
        }
    } else {                  // weights [k][N]
#pragma unroll
        for (int i = 0; i < 4; i++) {
            int e = i * 256 + tid, kk = e >> 6, nn = (e & 63) * 2;
            cpa8(bBase + (unsigned)(kk * LDB + nn) * 4u, Bp + (size_t)(ks + kk) * g.N + n0 + nn);
        }
    }
}

template<int MODE, int BNT>
__global__ void __launch_bounds__(256, 2) gemm_t(GArgs g)
{
    constexpr int LDB = BNT + 8;
    constexpr int NF  = BNT / 16;     // n-frags per warp (warp tile = 32 x BNT/2)
    const int nb = blockIdx.x, mb = blockIdx.y, z = blockIdx.z;
    const int m0 = mb * BM, n0 = nb * BNT;

    const float *Ap, *Bp, *bias; float* Cp; int kmax;
    if (MODE == 0)      { Ap = g.A0; Bp = g.w6[z]; bias = g.b6[z]; Cp = g.o6[z]; kmax = g.K; }
    else if (MODE == 1) { Ap = g.A0; Bp = g.B; bias = g.bias; Cp = g.C; kmax = g.K; }
    else if (MODE == 2) {
        if (n0 >= m0 + BM) return;
        Ap = g.A0 + (size_t)z * SEQ * HDIM; Bp = g.B + (size_t)z * SEQ * HDIM;
        bias = nullptr; Cp = g.C + (size_t)z * SEQ * SEQ; kmax = HDIM;
    } else {
        Ap = g.A0 + (size_t)z * SEQ * SEQ; Bp = g.B + (size_t)z * SEQ * HDIM;
        bias = nullptr; Cp = g.C; kmax = min(g.K, m0 + BM);
    }

    __shared__ float As[2][BM * LDA];
    __shared__ float Bs[2][BK * LDB];

    const int tid = threadIdx.x, lane = tid & 31, warp = tid >> 5;
    const int wm = (warp & 3) * 32, wn = (warp >> 2) * (BNT / 2);
    const int qrow = lane >> 2, qcol = lane & 3;

    float acc[2][NF][4] = {};
    const int nIter = kmax / BK;

    issue_tile<MODE, BNT>(g, Ap, Bp, As[0], Bs[0], m0, n0, 0, tid);
    cp_commit();

    for (int it = 0; it < nIter; ++it) {
        if (it + 1 < nIter) {
            issue_tile<MODE, BNT>(g, Ap, Bp, As[(it + 1) & 1], Bs[(it + 1) & 1],
                                  m0, n0, (it + 1) * BK, tid);
            cp_commit();
            cp_wait<1>();
        } else cp_wait<0>();
        __syncthreads();

        const float* Ab = As[it & 1];
        const float* Bb = Bs[it & 1];
#pragma unroll
        for (int kk = 0; kk < BK; kk += 8) {
            unsigned a[2][4];
#pragma unroll
            for (int mf = 0; mf < 2; mf++) {
                int r = wm + mf * 16 + qrow;
                a[mf][0] = __float_as_uint(Ab[r * LDA + kk + qcol]);
                a[mf][1] = __float_as_uint(Ab[(r + 8) * LDA + kk + qcol]);
                a[mf][2] = __float_as_uint(Ab[r * LDA + kk + qcol + 4]);
                a[mf][3] = __float_as_uint(Ab[(r + 8) * LDA + kk + qcol + 4]);
            }
#pragma unroll
            for (int nf = 0; nf < NF; nf++) {
                unsigned b0 = __float_as_uint(Bb[(kk + qcol) * LDB + wn + nf * 8 + qrow]);
                unsigned b1 = __float_as_uint(Bb[(kk + 4 + qcol) * LDB + wn + nf * 8 + qrow]);
                mma8(acc[0][nf], a[0], b0, b1);
                mma8(acc[1][nf], a[1], b0, b1);
            }
        }
        __syncthreads();
    }

    // epilogue (float2 stores; cols are even-aligned pairs)
#pragma unroll
    for (int mf = 0; mf < 2; mf++)
#pragma unroll
    for (int nf = 0; nf < NF; nf++)
#pragma unroll
    for (int t2 = 0; t2 < 2; t2++) {
        int r   = m0 + wm + mf * 16 + qrow + t2 * 8;
        int col = n0 + wn + nf * 8 + qcol * 2;
        float v0 = acc[mf][nf][t2 * 2], v1 = acc[mf][nf][t2 * 2 + 1];
        if (MODE <= 1) { v0 += bias[col]; v1 += bias[col + 1]; }
        float2 vv = make_float2(v0, v1);
        if (MODE == 0) {
            int b = r >> 11, s = r & (SEQ - 1), h = col >> 6, hd = col & 63;
            *reinterpret_cast<float2*>(&Cp[((size_t)(b * NH + h) * SEQ + s) * HDIM + hd]) = vv;
        } else if (MODE == 2) {
            *reinterpret_cast<float2*>(&Cp[(size_t)r * SEQ + col]) = vv;
        } else if (MODE == 3) {
            int b = z >> 4, h = z & 15;
            *reinterpret_cast<float2*>(&Cp[((size_t)(b * SEQ + r)) * DM + h * HDIM + col]) = vv;
        } else {
            *reinterpret_cast<float2*>(&Cp[(size_t)r * g.N + col]) = vv;
        }
    }
}

// ---------------- causal softmax (writes only up to 128-aligned boundary) --------
__global__ void softmax_kernel(float* __restrict__ Sc) {
    const int m = blockIdx.x, bh = blockIdx.y;
    float* row = Sc + ((size_t)bh * SEQ + m) * SEQ;
    const int n  = m + 1;                       // valid length
    const int nz = ((m >> 7) + 1) << 7;         // PV never reads past this
    const int tid = threadIdx.x;
    __shared__ float red[256];

    float r[8];
#pragma unroll
    for (int i = 0; i < 8; i++) {
        int j = tid + i * 256;
        r[i] = (j < n) ? row[j] * 0.125f : -1e30f;
    }
    float mx = r[0];
#pragma unroll
    for (int i = 1; i < 8; i++) mx = fmaxf(mx, r[i]);
    red[tid] = mx; __syncthreads();
    for (int s = 128; s > 0; s >>= 1) { if (tid < s) red[tid] = fmaxf(red[tid], red[tid + s]); __syncthreads(); }
    mx = red[0]; __syncthreads();

    float sum = 0.f;
#pragma unroll
    for (int i = 0; i < 8; i++) { r[i] = __expf(r[i] - mx); sum += r[i]; }
    red[tid] = sum; __syncthreads();
    for (int s = 128; s > 0; s >>= 1) { if (tid < s) red[tid] += red[tid + s]; __syncthreads(); }
    float inv = 1.f / red[0];

#pragma unroll
    for (int i = 0; i < 8; i++) {
        int j = tid + i * 256;
        if (j < n)       row[j] = r[i] * inv;
        else if (j < nz) row[j] = 0.f;
    }
}

// ---------------- window-32 backward attention: one warp per query ----------------
__global__ void bwd_attn_kernel(const float* __restrict__ Qb, const float* __restrict__ Kb,
                                const float* __restrict__ Vb, float* __restrict__ bwd) {
    __shared__ float qsh[8][HDIM];
    const int tid = threadIdx.x;
    const int wid = tid >> 5, lane = tid & 31;
    const int idx = blockIdx.x * 8 + wid;
    const int bh = idx >> 11, m = idx & (SEQ - 1);
    const float* Qp = Qb + (size_t)bh * SEQ * HDIM;
    const float* Kp = Kb + (size_t)bh * SEQ * HDIM;
    const float* Vp = Vb + (size_t)bh * SEQ * HDIM;
    const int b = bh >> 4, h = bh & 15;
    float* outp = bwd + ((size_t)(b * SEQ + m)) * DM + h * HDIM;

    int w = SEQ - 1 - m; if (w > 32) w = 32;
    float o0, o1;
    if (w == 0) {
        float s0 = 0.f, s1 = 0.f;
        for (int s = 0; s < SEQ; s++) {
            s0 += Vp[s * HDIM + lane];
            s1 += Vp[s * HDIM + lane + 32];
        }
        o0 = s0 * (1.f / SEQ); o1 = s1 * (1.f / SEQ);
    } else {
        qsh[wid][lane]      = Qp[m * HDIM + lane];
        qsh[wid][lane + 32] = Qp[m * HDIM + lane + 32];
        __syncwarp();
        float sc = -1e30f;
        if (lane < w) {
            const float* kr = Kp + (size_t)(m + 1 + lane) * HDIM;
            float a = 0.f;
#pragma unroll
            for (int d = 0; d < HDIM; d++) a += qsh[wid][d] * kr[d];
            sc = a * 0.125f;
        }
        float mx = sc;
#pragma unroll
        for (int o = 16; o > 0; o >>= 1) mx = fmaxf(mx, __shfl_xor_sync(0xffffffffu, mx, o));
        float e = __expf(sc - mx);
        float sum = e;
#pragma unroll
        for (int o = 16; o > 0; o >>= 1) sum += __shfl_xor_sync(0xffffffffu, sum, o);
        float p = e / sum;
        o0 = 0.f; o1 = 0.f;
        for (int kk = 0; kk < w; kk++) {
            float pk = __shfl_sync(0xffffffffu, p, kk);
            const float* vr = Vp + (size_t)(m + 1 + kk) * HDIM;
            o0 += pk * vr[lane];
            o1 += pk * vr[lane + 32];
        }
    }
    outp[lane] = o0; outp[lane + 32] = o1;
}

// ---------------- gate LN + sigmoid + fusion ----------------
__global__ void gate_fuse_kernel(const float* __restrict__ gpre, const float* __restrict__ fwd,
                                 const float* __restrict__ bwd, const float* __restrict__ gg,
                                 const float* __restrict__ gb, const float* __restrict__ bstr,
                                 float* __restrict__ fused) {
    const int r = blockIdx.x, tid = threadIdx.x;
    const float* rowp = gpre + (size_t)r * DM;
    __shared__ float red[256];
    float v[4]; float s = 0.f, ss = 0.f;
#pragma unroll
    for (int i = 0; i < 4; i++) { v[i] = rowp[tid + i * 256]; s += v[i]; ss += v[i] * v[i]; }
    red[tid] = s; __syncthreads();
    for (int o = 128; o > 0; o >>= 1) { if (tid < o) red[tid] += red[tid + o]; __syncthreads(); }
    float mean = red[0] * (1.f / DM); __syncthreads();
    red[tid] = ss; __syncthreads();
    for (int o = 128; o > 0; o >>= 1) { if (tid < o) red[tid] += red[tid + o]; __syncthreads(); }
    float var = red[0] * (1.f / DM) - mean * mean;
    float rstd = rsqrtf(var + 1e-5f);
    float strength = 0.3f * sigmoidf_(bstr[0]);
#pragma unroll
    for (int i = 0; i < 4; i++) {
        int j = tid + i * 256;
        float g = sigmoidf_((v[i] - mean) * rstd * gg[j] + gb[j]);
        size_t o = (size_t)r * DM + j;
        fused[o] = fwd[o] + strength * g * bwd[o];
    }
}

// ---------------- final residual + LayerNorm ----------------
__global__ void final_ln_kernel(const float* __restrict__ x, const float* __restrict__ o2,
                                const float* __restrict__ lg, const float* __restrict__ lb,
                                float* __restrict__ out) {
    const int r = blockIdx.x, tid = threadIdx.x;
    __shared__ float red[256];
    float v[4]; float s = 0.f, ss = 0.f;
#pragma unroll
    for (int i = 0; i < 4; i++) {
        size_t o = (size_t)r * DM + tid + i * 256;
        v[i] = x[o] + o2[o];
        s += v[i]; ss += v[i] * v[i];
    }
    red[tid] = s; __syncthreads();
    for (int o = 128; o > 0; o >>= 1) { if (tid < o) red[tid] += red[tid + o]; __syncthreads(); }
    float mean = red[0] * (1.f / DM); __syncthreads();
    red[tid] = ss; __syncthreads();
    for (int o = 128; o > 0; o >>= 1) { if (tid < o) red[tid] += red[tid + o]; __syncthreads(); }
    float var = red[0] * (1.f / DM) - mean * mean;
    float rstd = rsqrtf(var + 1e-5f);
#pragma unroll
    for (int i = 0; i < 4; i++) {
        int j = tid + i * 256;
        size_t o = (size_t)r * DM + j;
        out[o] = (v[i] - mean) * rstd * lg[j] + lb[j];
    }
}

// ---------------- launch ----------------
extern "C" void kernel_launch(void* const* d_in, const int* in_sizes, int n_in,
                              void* d_out, int out_size) {
    const float* x      = (const float*)d_in[0];
    const float* fq_w   = (const float*)d_in[1];
    const float* fq_b   = (const float*)d_in[2];
    const float* fk_w   = (const float*)d_in[3];
    const float* fk_b   = (const float*)d_in[4];
    const float* fv_w   = (const float*)d_in[5];
    const float* fv_b   = (const float*)d_in[6];
    const float* bq_w   = (const float*)d_in[7];
    const float* bq_b   = (const float*)d_in[8];
    const float* bk_w   = (const float*)d_in[9];
    const float* bk_b   = (const float*)d_in[10];
    const float* bv_w   = (const float*)d_in[11];
    const float* bv_b   = (const float*)d_in[12];
    const float* gate_w = (const float*)d_in[13];
    const float* gate_b = (const float*)d_in[14];
    const float* gln_g  = (const float*)d_in[15];
    const float* gln_b  = (const float*)d_in[16];
    const float* bstr   = (const float*)d_in[17];
    const float* out_w  = (const float*)d_in[18];
    const float* out_b  = (const float*)d_in[19];
    const float* ln_g   = (const float*)d_in[20];
    const float* ln_b   = (const float*)d_in[21];

    float *q, *k, *v, *qb, *kb, *vb, *sc, *fwd, *bwd, *gpre, *fused, *out2;
    cudaGetSymbolAddress((void**)&q,     g_q);
    cudaGetSymbolAddress((void**)&k,     g_k);
    cudaGetSymbolAddress((void**)&v,     g_v);
    cudaGetSymbolAddress((void**)&qb,    g_qb);
    cudaGetSymbolAddress((void**)&kb,    g_kb);
    cudaGetSymbolAddress((void**)&vb,    g_vb);
    cudaGetSymbolAddress((void**)&sc,    g_scores);
    cudaGetSymbolAddress((void**)&fwd,   g_fwd);
    cudaGetSymbolAddress((void**)&bwd,   g_bwd);
    cudaGetSymbolAddress((void**)&gpre,  g_gpre);
    cudaGetSymbolAddress((void**)&fused, g_fused);
    cudaGetSymbolAddress((void**)&out2,  g_out2);

    dim3 blk(256);

    // 6 fused projections -> head layout [BH,S,HD]
    {
        GArgs a = {};
        a.A0 = x; a.K = DM; a.N = DM; a.KA0 = DM;
        const float* W[6] = {fq_w, fk_w, fv_w, bq_w, bk_w, bv_w};
        const float* Bb[6] = {fq_b, fk_b, fv_b, bq_b, bk_b, bv_b};
        float* O[6] = {q, k, v, qb, kb, vb};
        for (int i = 0; i < 6; i++) { a.w6[i] = W[i]; a.b6[i] = Bb[i]; a.o6[i] = O[i]; }
        gemm_t<0, 128><<<dim3(DM / 128, MROWS / BM, 6), blk>>>(a);
    }

    // causal attention: scores -> softmax -> PV
    {
        GArgs a = {};
        a.A0 = q; a.B = k; a.C = sc; a.N = SEQ; a.K = HDIM; a.KA0 = HDIM;
        gemm_t<2, 128><<<dim3(SEQ / 128, SEQ / BM, BHT), blk>>>(a);
    }
    softmax_kernel<<<dim3(SEQ, BHT), 256>>>(sc);
    {
        GArgs a = {};
        a.A0 = sc; a.B = v; a.C = fwd; a.N = HDIM; a.K = SEQ; a.KA0 = SEQ;
        gemm_t<3, 64><<<dim3(1, SEQ / BM, BHT), blk>>>(a);
    }

    // window backward attention
    bwd_attn_kernel<<<(BHT * SEQ) / 8, 256>>>(qb, kb, vb, bwd);

    // gated fusion: gpre = concat(fwd,bwd) @ gate_w + gate_b
    {
        GArgs a = {};
        a.A0 = fwd; a.A1 = bwd; a.B = gate_w; a.bias = gate_b; a.C = gpre;
        a.N = DM; a.K = 2 * DM; a.KA0 = DM;
        gemm_t<1, 128><<<dim3(DM / 128, MROWS / BM, 1), blk>>>(a);
    }
    gate_fuse_kernel<<<MROWS, 256>>>(gpre, fwd, bwd, gln_g, gln_b, bstr, fused);

    // output projection + residual LN
    {
        GArgs a = {};
        a.A0 = fused; a.A1 = fused; a.B = out_w; a.bias = out_b; a.C = out2;
        a.N = DM; a.K = DM; a.KA0 = DM;
        gemm_t<1, 128><<<dim3(DM / 128, MROWS / BM, 1), blk>>>(a);
    }
    final_ln_kernel<<<MROWS, 256>>>(x, out2, ln_g, ln_b, (float*)d_out);
}

// round 5
// speedup vs baseline: 2.7487x; 1.1074x over previous
#include <cuda_runtime.h>
#include <math.h>

// Problem constants
#define SEQ   2048
#define NB    2
#define NH    16
#define HDIM  64
#define DM    1024
#define BHT   (NB*NH)        // 32 batch*heads
#define MROWS (NB*SEQ)       // 4096

// GEMM tile config
#define BM 128
#define BK 16
#define LDA 20               // padded A smem stride (conflict-free, 8B-aligned)

// Flash attention tile config
#define FLD 68               // padded smem stride (conflict-free for all frag patterns)

// ---------------- scratch (device globals: allocation-free) ----------------
__device__ float g_q [BHT*SEQ*HDIM];
__device__ float g_k [BHT*SEQ*HDIM];
__device__ float g_v [BHT*SEQ*HDIM];
__device__ float g_qb[BHT*SEQ*HDIM];
__device__ float g_kb[BHT*SEQ*HDIM];
__device__ float g_vb[BHT*SEQ*HDIM];
__device__ float g_fwd  [(size_t)MROWS*DM];
__device__ float g_bwd  [(size_t)MROWS*DM];
__device__ float g_gpre [(size_t)MROWS*DM];
__device__ float g_fused[(size_t)MROWS*DM];
__device__ float g_out2 [(size_t)MROWS*DM];

// ---------------- helpers ----------------
__device__ __forceinline__ void cpa8(unsigned dst, const float* src) {
    asm volatile("cp.async.ca.shared.global [%0], [%1], 8;" :: "r"(dst), "l"(src));
}
__device__ __forceinline__ void cp_commit() { asm volatile("cp.async.commit_group;"); }
template<int N> __device__ __forceinline__ void cp_wait() {
    asm volatile("cp.async.wait_group %0;" :: "n"(N));
}

__device__ __forceinline__ void mma8(float* c, const unsigned* a, unsigned b0, unsigned b1) {
    asm volatile(
        "mma.sync.aligned.m16n8k8.row.col.f32.tf32.tf32.f32 "
        "{%0,%1,%2,%3}, {%4,%5,%6,%7}, {%8,%9}, {%0,%1,%2,%3};"
        : "+f"(c[0]), "+f"(c[1]), "+f"(c[2]), "+f"(c[3])
        : "r"(a[0]), "r"(a[1]), "r"(a[2]), "r"(a[3]), "r"(b0), "r"(b1));
}

__device__ __forceinline__ float sigmoidf_(float x) { return 1.f / (1.f + __expf(-x)); }

struct GArgs {
    const float *A0, *A1, *B, *bias;
    float* C;
    int N, K, KA0;
    const float* w6[6]; const float* b6[6]; float* o6[6];
};

// MODE 0: proj6   C(head layout) = x @ w6[z] + b6[z]
// MODE 1: dense   C[M,N] = concat(A0|A1) @ B + bias
template<int MODE, int BNT>
__device__ __forceinline__ void issue_tile(
    const GArgs& g, const float* Ap, const float* Bp,
    float* As, float* Bs, int m0, int n0, int ks, int tid)
{
    constexpr int LDB = BNT + 8;
    unsigned aBase = (unsigned)__cvta_generic_to_shared(As);
    unsigned bBase = (unsigned)__cvta_generic_to_shared(Bs);
    // A tile: BM x BK
#pragma unroll
    for (int i = 0; i < 4; i++) {
        int e = i * 256 + tid, mm = e >> 3, kk = (e & 7) * 2;
        const float* src;
        if (MODE == 0)      src = Ap + (size_t)(m0 + mm) * DM + ks + kk;
        else                { int gk = ks + kk;
            src = (gk < g.KA0) ? g.A0 + (size_t)(m0 + mm) * g.KA0 + gk
                               : g.A1 + (size_t)(m0 + mm) * g.KA0 + (gk - g.KA0); }
        cpa8(aBase + (unsigned)(mm * LDA + kk) * 4u, src);
    }
    // B tile: BK x BNT (weights [k][N])
#pragma unroll
    for (int i = 0; i < 4; i++) {
        int e = i * 256 + tid, kk = e >> 6, nn = (e & 63) * 2;
        cpa8(bBase + (unsigned)(kk * LDB + nn) * 4u, Bp + (size_t)(ks + kk) * g.N + n0 + nn);
    }
}

template<int MODE, int BNT>
__global__ void __launch_bounds__(256, 2) gemm_t(GArgs g)
{
    constexpr int LDB = BNT + 8;
    constexpr int NF  = BNT / 16;
    const int nb = blockIdx.x, mb = blockIdx.y, z = blockIdx.z;
    const int m0 = mb * BM, n0 = nb * BNT;

    const float *Ap, *Bp, *bias; float* Cp; int kmax;
    if (MODE == 0)      { Ap = g.A0; Bp = g.w6[z]; bias = g.b6[z]; Cp = g.o6[z]; kmax = g.K; }
    else                { Ap = g.A0; Bp = g.B; bias = g.bias; Cp = g.C; kmax = g.K; }

    __shared__ float As[2][BM * LDA];
    __shared__ float Bs[2][BK * LDB];

    const int tid = threadIdx.x, lane = tid & 31, warp = tid >> 5;
    const int wm = (warp & 3) * 32, wn = (warp >> 2) * (BNT / 2);
    const int qrow = lane >> 2, qcol = lane & 3;

    float acc[2][NF][4] = {};
    const int nIter = kmax / BK;

    issue_tile<MODE, BNT>(g, Ap, Bp, As[0], Bs[0], m0, n0, 0, tid);
    cp_commit();

    for (int it = 0; it < nIter; ++it) {
        if (it + 1 < nIter) {
            issue_tile<MODE, BNT>(g, Ap, Bp, As[(it + 1) & 1], Bs[(it + 1) & 1],
                                  m0, n0, (it + 1) * BK, tid);
            cp_commit();
            cp_wait<1>();
        } else cp_wait<0>();
        __syncthreads();

        const float* Ab = As[it & 1];
        const float* Bb = Bs[it & 1];
#pragma unroll
        for (int kk = 0; kk < BK; kk += 8) {
            unsigned a[2][4];
#pragma unroll
            for (int mf = 0; mf < 2; mf++) {
                int r = wm + mf * 16 + qrow;
                a[mf][0] = __float_as_uint(Ab[r * LDA + kk + qcol]);
                a[mf][1] = __float_as_uint(Ab[(r + 8) * LDA + kk + qcol]);
                a[mf][2] = __float_as_uint(Ab[r * LDA + kk + qcol + 4]);
                a[mf][3] = __float_as_uint(Ab[(r + 8) * LDA + kk + qcol + 4]);
            }
#pragma unroll
            for (int nf = 0; nf < NF; nf++) {
                unsigned b0 = __float_as_uint(Bb[(kk + qcol) * LDB + wn + nf * 8 + qrow]);
                unsigned b1 = __float_as_uint(Bb[(kk + 4 + qcol) * LDB + wn + nf * 8 + qrow]);
                mma8(acc[0][nf], a[0], b0, b1);
                mma8(acc[1][nf], a[1], b0, b1);
            }
        }
        __syncthreads();
    }

#pragma unroll
    for (int mf = 0; mf < 2; mf++)
#pragma unroll
    for (int nf = 0; nf < NF; nf++)
#pragma unroll
    for (int t2 = 0; t2 < 2; t2++) {
        int r   = m0 + wm + mf * 16 + qrow + t2 * 8;
        int col = n0 + wn + nf * 8 + qcol * 2;
        float v0 = acc[mf][nf][t2 * 2] + bias[col];
        float v1 = acc[mf][nf][t2 * 2 + 1] + bias[col + 1];
        float2 vv = make_float2(v0, v1);
        if (MODE == 0) {
            int b = r >> 11, s = r & (SEQ - 1), h = col >> 6, hd = col & 63;
            *reinterpret_cast<float2*>(&Cp[((size_t)(b * NH + h) * SEQ + s) * HDIM + hd]) = vv;
        } else {
            *reinterpret_cast<float2*>(&Cp[(size_t)r * g.N + col]) = vv;
        }
    }
}

// ---------------- fused causal flash attention ----------------
// Grid: (SEQ/128, BHT). Block: 256 threads (8 warps, 16 query rows each).
// Per tile of 64 keys: S = Q@K^T (tf32 mma), online softmax, O += P@V.
// K and V both live in smem in NATURAL [key][hd] layout:
//   QK^T  B-frag (k=hd,n=key):  Ks[key*FLD + hd]   -> conflict-free
//   PV    B-frag (k=key,n=hd):  Vs[key*FLD + hd]   -> conflict-free
__global__ void __launch_bounds__(256, 2) flash_fwd_kernel(
    const float* __restrict__ Q, const float* __restrict__ K,
    const float* __restrict__ V, float* __restrict__ fwd)
{
    extern __shared__ float fsm[];
    float* Ks = fsm;                 // 64 x FLD
    float* Vs = Ks + 64 * FLD;       // 64 x FLD
    float* Ps = Vs + 64 * FLD;       // 128 x FLD (Q staging, then P)

    const int m0 = blockIdx.x * 128;
    const int bh = blockIdx.y;
    const float* Qp = Q + (size_t)bh * SEQ * HDIM;
    const float* Kp = K + (size_t)bh * SEQ * HDIM;
    const float* Vp = V + (size_t)bh * SEQ * HDIM;

    const int tid = threadIdx.x, lane = tid & 31, warp = tid >> 5;
    const int wm = warp * 16;
    const int qrow = lane >> 2, qcol = lane & 3;

    // stage Q coalesced, then lift fragments to registers
#pragma unroll
    for (int i = 0; i < 8; i++) {
        int e = i * 256 + tid, r = e >> 4, c4 = (e & 15) * 4;
        float4 t = *reinterpret_cast<const float4*>(Qp + (size_t)(m0 + r) * HDIM + c4);
        float* d = Ps + r * FLD + c4;
        d[0] = t.x; d[1] = t.y; d[2] = t.z; d[3] = t.w;
    }
    __syncthreads();

    unsigned qf[8][4];
#pragma unroll
    for (int ks = 0; ks < 8; ks++) {
        int r = wm + qrow, c = ks * 8 + qcol;
        qf[ks][0] = __float_as_uint(Ps[r * FLD + c]);
        qf[ks][1] = __float_as_uint(Ps[(r + 8) * FLD + c]);
        qf[ks][2] = __float_as_uint(Ps[r * FLD + c + 4]);
        qf[ks][3] = __float_as_uint(Ps[(r + 8) * FLD + c + 4]);
    }
    __syncthreads();

    float o[8][4] = {};
    float mrow[2] = {-1e30f, -1e30f};
    float lrow[2] = {0.f, 0.f};

    const int ntiles = m0 / 64 + 2;
    for (int kt = 0; kt < ntiles; kt++) {
        const int n0k = kt * 64;
        // load K,V tiles (64x64 each), coalesced float4
#pragma unroll
        for (int i = 0; i < 4; i++) {
            int e = i * 256 + tid, r = e >> 4, c4 = (e & 15) * 4;
            float4 tk = *reinterpret_cast<const float4*>(Kp + (size_t)(n0k + r) * HDIM + c4);
            float4 tv = *reinterpret_cast<const float4*>(Vp + (size_t)(n0k + r) * HDIM + c4);
            float* dk = Ks + r * FLD + c4; dk[0]=tk.x; dk[1]=tk.y; dk[2]=tk.z; dk[3]=tk.w;
            float* dv = Vs + r * FLD + c4; dv[0]=tv.x; dv[1]=tv.y; dv[2]=tv.z; dv[3]=tv.w;
        }
        __syncthreads();

        // S = Q @ K^T  (warp: 16 rows x 64 keys)
        float s[8][4] = {};
#pragma unroll
        for (int ks = 0; ks < 8; ks++) {
#pragma unroll
            for (int nf = 0; nf < 8; nf++) {
                unsigned b0 = __float_as_uint(Ks[(nf * 8 + qrow) * FLD + ks * 8 + qcol]);
                unsigned b1 = __float_as_uint(Ks[(nf * 8 + qrow) * FLD + ks * 8 + qcol + 4]);
                mma8(s[nf], qf[ks], b0, b1);
            }
        }

        // online softmax update
        const bool domask = (n0k + 63 > m0);
#pragma unroll
        for (int t2 = 0; t2 < 2; t2++) {
            const int row = m0 + wm + qrow + t2 * 8;
            float tmax = -1e30f;
#pragma unroll
            for (int nf = 0; nf < 8; nf++)
#pragma unroll
            for (int j = 0; j < 2; j++) {
                float v = s[nf][t2 * 2 + j] * 0.125f;
                if (domask) {
                    int key = n0k + nf * 8 + qcol * 2 + j;
                    if (key > row) v = -1e30f;
                }
                s[nf][t2 * 2 + j] = v;
                tmax = fmaxf(tmax, v);
            }
            tmax = fmaxf(tmax, __shfl_xor_sync(0xffffffffu, tmax, 1));
            tmax = fmaxf(tmax, __shfl_xor_sync(0xffffffffu, tmax, 2));
            float mnew = fmaxf(mrow[t2], tmax);
            float alpha = __expf(mrow[t2] - mnew);
            float psum = 0.f;
#pragma unroll
            for (int nf = 0; nf < 8; nf++)
#pragma unroll
            for (int j = 0; j < 2; j++) {
                float p = __expf(s[nf][t2 * 2 + j] - mnew);
                s[nf][t2 * 2 + j] = p;
                psum += p;
            }
            psum += __shfl_xor_sync(0xffffffffu, psum, 1);
            psum += __shfl_xor_sync(0xffffffffu, psum, 2);
            lrow[t2] = lrow[t2] * alpha + psum;
            mrow[t2] = mnew;
#pragma unroll
            for (int nf = 0; nf < 8; nf++) {
                o[nf][t2 * 2]     *= alpha;
                o[nf][t2 * 2 + 1] *= alpha;
            }
        }

        // write P to smem (A operand for PV)
#pragma unroll
        for (int t2 = 0; t2 < 2; t2++) {
            int r = wm + qrow + t2 * 8;
#pragma unroll
            for (int nf = 0; nf < 8; nf++) {
                *reinterpret_cast<float2*>(&Ps[r * FLD + nf * 8 + qcol * 2]) =
                    make_float2(s[nf][t2 * 2], s[nf][t2 * 2 + 1]);
            }
        }
        __syncthreads();

        // O += P @ V  (k = 64 keys)
#pragma unroll
        for (int ks = 0; ks < 8; ks++) {
            unsigned a[4];
            int r = wm + qrow, c = ks * 8 + qcol;
            a[0] = __float_as_uint(Ps[r * FLD + c]);
            a[1] = __float_as_uint(Ps[(r + 8) * FLD + c]);
            a[2] = __float_as_uint(Ps[r * FLD + c + 4]);
            a[3] = __float_as_uint(Ps[(r + 8) * FLD + c + 4]);
#pragma unroll
            for (int nf = 0; nf < 8; nf++) {
                unsigned b0 = __float_as_uint(Vs[(ks * 8 + qcol) * FLD + nf * 8 + qrow]);
                unsigned b1 = __float_as_uint(Vs[(ks * 8 + qcol + 4) * FLD + nf * 8 + qrow]);
                mma8(o[nf], a, b0, b1);
            }
        }
        __syncthreads();
    }

    // epilogue: normalize and store merged [B,S,D]
    const int b = bh >> 4, h = bh & 15;
#pragma unroll
    for (int t2 = 0; t2 < 2; t2++) {
        int srow = m0 + wm + qrow + t2 * 8;
        float inv = 1.f / lrow[t2];
        float* outp = fwd + ((size_t)(b * SEQ + srow)) * DM + h * HDIM;
#pragma unroll
        for (int nf = 0; nf < 8; nf++) {
            *reinterpret_cast<float2*>(&outp[nf * 8 + qcol * 2]) =
                make_float2(o[nf][t2 * 2] * inv, o[nf][t2 * 2 + 1] * inv);
        }
    }
}

// ---------------- window-32 backward attention: one warp per query ----------------
__global__ void bwd_attn_kernel(const float* __restrict__ Qb, const float* __restrict__ Kb,
                                const float* __restrict__ Vb, float* __restrict__ bwd) {
    __shared__ float qsh[8][HDIM];
    const int tid = threadIdx.x;
    const int wid = tid >> 5, lane = tid & 31;
    const int idx = blockIdx.x * 8 + wid;
    const int bh = idx >> 11, m = idx & (SEQ - 1);
    const float* Qp = Qb + (size_t)bh * SEQ * HDIM;
    const float* Kp = Kb + (size_t)bh * SEQ * HDIM;
    const float* Vp = Vb + (size_t)bh * SEQ * HDIM;
    const int b = bh >> 4, h = bh & 15;
    float* outp = bwd + ((size_t)(b * SEQ + m)) * DM + h * HDIM;

    int w = SEQ - 1 - m; if (w > 32) w = 32;
    float o0, o1;
    if (w == 0) {
        float s0 = 0.f, s1 = 0.f;
        for (int s = 0; s < SEQ; s++) {
            s0 += Vp[s * HDIM + lane];
            s1 += Vp[s * HDIM + lane + 32];
        }
        o0 = s0 * (1.f / SEQ); o1 = s1 * (1.f / SEQ);
    } else {
        qsh[wid][lane]      = Qp[m * HDIM + lane];
        qsh[wid][lane + 32] = Qp[m * HDIM + lane + 32];
        __syncwarp();
        float sc = -1e30f;
        if (lane < w) {
            const float* kr = Kp + (size_t)(m + 1 + lane) * HDIM;
            float a = 0.f;
#pragma unroll
            for (int d = 0; d < HDIM; d++) a += qsh[wid][d] * kr[d];
            sc = a * 0.125f;
        }
        float mx = sc;
#pragma unroll
        for (int o = 16; o > 0; o >>= 1) mx = fmaxf(mx, __shfl_xor_sync(0xffffffffu, mx, o));
        float e = __expf(sc - mx);
        float sum = e;
#pragma unroll
        for (int o = 16; o > 0; o >>= 1) sum += __shfl_xor_sync(0xffffffffu, sum, o);
        float p = e / sum;
        o0 = 0.f; o1 = 0.f;
        for (int kk = 0; kk < w; kk++) {
            float pk = __shfl_sync(0xffffffffu, p, kk);
            const float* vr = Vp + (size_t)(m + 1 + kk) * HDIM;
            o0 += pk * vr[lane];
            o1 += pk * vr[lane + 32];
        }
    }
    outp[lane] = o0; outp[lane + 32] = o1;
}

// ---------------- gate LN + sigmoid + fusion ----------------
__global__ void gate_fuse_kernel(const float* __restrict__ gpre, const float* __restrict__ fwd,
                                 const float* __restrict__ bwd, const float* __restrict__ gg,
                                 const float* __restrict__ gb, const float* __restrict__ bstr,
                                 float* __restrict__ fused) {
    const int r = blockIdx.x, tid = threadIdx.x;
    const float* rowp = gpre + (size_t)r * DM;
    __shared__ float red[256];
    float v[4]; float s = 0.f, ss = 0.f;
#pragma unroll
    for (int i = 0; i < 4; i++) { v[i] = rowp[tid + i * 256]; s += v[i]; ss += v[i] * v[i]; }
    red[tid] = s; __syncthreads();
    for (int o = 128; o > 0; o >>= 1) { if (tid < o) red[tid] += red[tid + o]; __syncthreads(); }
    float mean = red[0] * (1.f / DM); __syncthreads();
    red[tid] = ss; __syncthreads();
    for (int o = 128; o > 0; o >>= 1) { if (tid < o) red[tid] += red[tid + o]; __syncthreads(); }
    float var = red[0] * (1.f / DM) - mean * mean;
    float rstd = rsqrtf(var + 1e-5f);
    float strength = 0.3f * sigmoidf_(bstr[0]);
#pragma unroll
    for (int i = 0; i < 4; i++) {
        int j = tid + i * 256;
        float g = sigmoidf_((v[i] - mean) * rstd * gg[j] + gb[j]);
        size_t o = (size_t)r * DM + j;
        fused[o] = fwd[o] + strength * g * bwd[o];
    }
}

// ---------------- final residual + LayerNorm ----------------
__global__ void final_ln_kernel(const float* __restrict__ x, const float* __restrict__ o2,
                                const float* __restrict__ lg, const float* __restrict__ lb,
                                float* __restrict__ out) {
    const int r = blockIdx.x, tid = threadIdx.x;
    __shared__ float red[256];
    float v[4]; float s = 0.f, ss = 0.f;
#pragma unroll
    for (int i = 0; i < 4; i++) {
        size_t o = (size_t)r * DM + tid + i * 256;
        v[i] = x[o] + o2[o];
        s += v[i]; ss += v[i] * v[i];
    }
    red[tid] = s; __syncthreads();
    for (int o = 128; o > 0; o >>= 1) { if (tid < o) red[tid] += red[tid + o]; __syncthreads(); }
    float mean = red[0] * (1.f / DM); __syncthreads();
    red[tid] = ss; __syncthreads();
    for (int o = 128; o > 0; o >>= 1) { if (tid < o) red[tid] += red[tid + o]; __syncthreads(); }
    float var = red[0] * (1.f / DM) - mean * mean;
    float rstd = rsqrtf(var + 1e-5f);
#pragma unroll
    for (int i = 0; i < 4; i++) {
        int j = tid + i * 256;
        size_t o = (size_t)r * DM + j;
        out[o] = (v[i] - mean) * rstd * lg[j] + lb[j];
    }
}

// ---------------- launch ----------------
extern "C" void kernel_launch(void* const* d_in, const int* in_sizes, int n_in,
                              void* d_out, int out_size) {
    const float* x      = (const float*)d_in[0];
    const float* fq_w   = (const float*)d_in[1];
    const float* fq_b   = (const float*)d_in[2];
    const float* fk_w   = (const float*)d_in[3];
    const float* fk_b   = (const float*)d_in[4];
    const float* fv_w   = (const float*)d_in[5];
    const float* fv_b   = (const float*)d_in[6];
    const float* bq_w   = (const float*)d_in[7];
    const float* bq_b   = (const float*)d_in[8];
    const float* bk_w   = (const float*)d_in[9];
    const float* bk_b   = (const float*)d_in[10];
    const float* bv_w   = (const float*)d_in[11];
    const float* bv_b   = (const float*)d_in[12];
    const float* gate_w = (const float*)d_in[13];
    const float* gate_b = (const float*)d_in[14];
    const float* gln_g  = (const float*)d_in[15];
    const float* gln_b  = (const float*)d_in[16];
    const float* bstr   = (const float*)d_in[17];
    const float* out_w  = (const float*)d_in[18];
    const float* out_b  = (const float*)d_in[19];
    const float* ln_g   = (const float*)d_in[20];
    const float* ln_b   = (const float*)d_in[21];

    float *q, *k, *v, *qb, *kb, *vb, *fwd, *bwd, *gpre, *fused, *out2;
    cudaGetSymbolAddress((void**)&q,     g_q);
    cudaGetSymbolAddress((void**)&k,     g_k);
    cudaGetSymbolAddress((void**)&v,     g_v);
    cudaGetSymbolAddress((void**)&qb,    g_qb);
    cudaGetSymbolAddress((void**)&kb,    g_kb);
    cudaGetSymbolAddress((void**)&vb,    g_vb);
    cudaGetSymbolAddress((void**)&fwd,   g_fwd);
    cudaGetSymbolAddress((void**)&bwd,   g_bwd);
    cudaGetSymbolAddress((void**)&gpre,  g_gpre);
    cudaGetSymbolAddress((void**)&fused, g_fused);
    cudaGetSymbolAddress((void**)&out2,  g_out2);

    const int flashSmem = (2 * 64 + 128) * FLD * (int)sizeof(float);  // 69632 B
    cudaFuncSetAttribute(flash_fwd_kernel,
                         cudaFuncAttributeMaxDynamicSharedMemorySize, flashSmem);

    dim3 blk(256);

    // 6 fused projections -> head layout [BH,S,HD]
    {
        GArgs a = {};
        a.A0 = x; a.K = DM; a.N = DM; a.KA0 = DM;
        const float* W[6] = {fq_w, fk_w, fv_w, bq_w, bk_w, bv_w};
        const float* Bb[6] = {fq_b, fk_b, fv_b, bq_b, bk_b, bv_b};
        float* O[6] = {q, k, v, qb, kb, vb};
        for (int i = 0; i < 6; i++) { a.w6[i] = W[i]; a.b6[i] = Bb[i]; a.o6[i] = O[i]; }
        gemm_t<0, 128><<<dim3(DM / 128, MROWS / BM, 6), blk>>>(a);
    }

    // fused causal flash attention -> fwd (merged [B,S,D])
    flash_fwd_kernel<<<dim3(SEQ / 128, BHT), blk, flashSmem>>>(q, k, v, fwd);

    // window backward attention
    bwd_attn_kernel<<<(BHT * SEQ) / 8, 256>>>(qb, kb, vb, bwd);

    // gated fusion: gpre = concat(fwd,bwd) @ gate_w + gate_b
    {
        GArgs a = {};
        a.A0 = fwd; a.A1 = bwd; a.B = gate_w; a.bias = gate_b; a.C = gpre;
        a.N = DM; a.K = 2 * DM; a.KA0 = DM;
        gemm_t<1, 128><<<dim3(DM / 128, MROWS / BM, 1), blk>>>(a);
    }
    gate_fuse_kernel<<<MROWS, 256>>>(gpre, fwd, bwd, gln_g, gln_b, bstr, fused);

    // output projection + residual LN
    {
        GArgs a = {};
        a.A0 = fused; a.A1 = fused; a.B = out_w; a.bias = out_b; a.C = out2;
        a.N = DM; a.K = DM; a.KA0 = DM;
        gemm_t<1, 128><<<dim3(DM / 128, MROWS / BM, 1), blk>>>(a);
    }
    final_ln_kernel<<<MROWS, 256>>>(x, out2, ln_g, ln_b, (float*)d_out);
}

// round 6
// speedup vs baseline: 2.9141x; 1.0601x over previous
#include <cuda_runtime.h>
#include <math.h>

// Problem constants
#define SEQ   2048
#define NB    2
#define NH    16
#define HDIM  64
#define DM    1024
#define BHT   (NB*NH)        // 32 batch*heads
#define MROWS (NB*SEQ)       // 4096

// GEMM tile config: 128x128 block tile, 4 warps of 64x64 each
#define BM 128
#define BN 128
#define BK 16
#define LDA 20               // padded A smem stride
#define LDB 136              // padded B smem stride

// Flash attention tile config
#define FLD 68               // padded smem stride (conflict-free for all frag patterns)

// ---------------- scratch (device globals: allocation-free) ----------------
__device__ float g_q [BHT*SEQ*HDIM];
__device__ float g_k [BHT*SEQ*HDIM];
__device__ float g_v [BHT*SEQ*HDIM];
__device__ float g_qb[BHT*SEQ*HDIM];
__device__ float g_kb[BHT*SEQ*HDIM];
__device__ float g_vb[BHT*SEQ*HDIM];
__device__ float g_fwd  [(size_t)MROWS*DM];
__device__ float g_bwd  [(size_t)MROWS*DM];
__device__ float g_gpre [(size_t)MROWS*DM];
__device__ float g_fused[(size_t)MROWS*DM];
__device__ float g_out2 [(size_t)MROWS*DM];

// ---------------- helpers ----------------
__device__ __forceinline__ void cpa8(unsigned dst, const float* src) {
    asm volatile("cp.async.ca.shared.global [%0], [%1], 8;" :: "r"(dst), "l"(src));
}
__device__ __forceinline__ void cp_commit() { asm volatile("cp.async.commit_group;"); }
template<int N> __device__ __forceinline__ void cp_wait() {
    asm volatile("cp.async.wait_group %0;" :: "n"(N));
}

__device__ __forceinline__ void mma8(float* c, const unsigned* a, unsigned b0, unsigned b1) {
    asm volatile(
        "mma.sync.aligned.m16n8k8.row.col.f32.tf32.tf32.f32 "
        "{%0,%1,%2,%3}, {%4,%5,%6,%7}, {%8,%9}, {%0,%1,%2,%3};"
        : "+f"(c[0]), "+f"(c[1]), "+f"(c[2]), "+f"(c[3])
        : "r"(a[0]), "r"(a[1]), "r"(a[2]), "r"(a[3]), "r"(b0), "r"(b1));
}

__device__ __forceinline__ float sigmoidf_(float x) { return 1.f / (1.f + __expf(-x)); }

struct GArgs {
    const float *A0, *A1, *B, *bias;
    float* C;
    int N, K, KA0;
    const float* w6[6]; const float* b6[6]; float* o6[6];
};

// MODE 0: proj6   C(head layout) = x @ w6[z] + b6[z]
// MODE 1: dense   C[M,N] = concat(A0|A1) @ B + bias
template<int MODE>
__device__ __forceinline__ void issue_tile(
    const GArgs& g, const float* Ap, const float* Bp,
    float* As, float* Bs, int m0, int n0, int ks, int tid)
{
    unsigned aBase = (unsigned)__cvta_generic_to_shared(As);
    unsigned bBase = (unsigned)__cvta_generic_to_shared(Bs);
    // A tile: BM x BK (2048 floats, 8 x cp.8 per thread @128 threads)
#pragma unroll
    for (int i = 0; i < 8; i++) {
        int e = i * 128 + tid, mm = e >> 3, kk = (e & 7) * 2;
        const float* src;
        if (MODE == 0)      src = Ap + (size_t)(m0 + mm) * DM + ks + kk;
        else                { int gk = ks + kk;
            src = (gk < g.KA0) ? g.A0 + (size_t)(m0 + mm) * g.KA0 + gk
                               : g.A1 + (size_t)(m0 + mm) * g.KA0 + (gk - g.KA0); }
        cpa8(aBase + (unsigned)(mm * LDA + kk) * 4u, src);
    }
    // B tile: BK x BN (weights [k][N])
#pragma unroll
    for (int i = 0; i < 8; i++) {
        int e = i * 128 + tid, kk = e >> 6, nn = (e & 63) * 2;
        cpa8(bBase + (unsigned)(kk * LDB + nn) * 4u, Bp + (size_t)(ks + kk) * g.N + n0 + nn);
    }
}

template<int MODE>
__global__ void __launch_bounds__(128, 2) gemm_t(GArgs g)
{
    const int nb = blockIdx.x, mb = blockIdx.y, z = blockIdx.z;
    const int m0 = mb * BM, n0 = nb * BN;

    const float *Ap, *Bp, *bias; float* Cp; int kmax;
    if (MODE == 0)      { Ap = g.A0; Bp = g.w6[z]; bias = g.b6[z]; Cp = g.o6[z]; kmax = g.K; }
    else                { Ap = g.A0; Bp = g.B; bias = g.bias; Cp = g.C; kmax = g.K; }

    __shared__ float As[2][BM * LDA];
    __shared__ float Bs[2][BK * LDB];

    const int tid = threadIdx.x, lane = tid & 31, warp = tid >> 5;
    const int wm = (warp & 1) * 64, wn = (warp >> 1) * 64;   // 2x2 warp grid, 64x64 tiles
    const int qrow = lane >> 2, qcol = lane & 3;

    float acc[4][8][4] = {};
    const int nIter = kmax / BK;

    issue_tile<MODE>(g, Ap, Bp, As[0], Bs[0], m0, n0, 0, tid);
    cp_commit();

    for (int it = 0; it < nIter; ++it) {
        if (it + 1 < nIter) {
            issue_tile<MODE>(g, Ap, Bp, As[(it + 1) & 1], Bs[(it + 1) & 1],
                             m0, n0, (it + 1) * BK, tid);
            cp_commit();
            cp_wait<1>();
        } else cp_wait<0>();
        __syncthreads();

        const float* Ab = As[it & 1];
        const float* Bb = Bs[it & 1];
#pragma unroll
        for (int kk = 0; kk < BK; kk += 8) {
            unsigned a[4][4];
#pragma unroll
            for (int mf = 0; mf < 4; mf++) {
                int r = wm + mf * 16 + qrow;
                a[mf][0] = __float_as_uint(Ab[r * LDA + kk + qcol]);
                a[mf][1] = __float_as_uint(Ab[(r + 8) * LDA + kk + qcol]);
                a[mf][2] = __float_as_uint(Ab[r * LDA + kk + qcol + 4]);
                a[mf][3] = __float_as_uint(Ab[(r + 8) * LDA + kk + qcol + 4]);
            }
#pragma unroll
            for (int nf = 0; nf < 8; nf++) {
                unsigned b0 = __float_as_uint(Bb[(kk + qcol) * LDB + wn + nf * 8 + qrow]);
                unsigned b1 = __float_as_uint(Bb[(kk + 4 + qcol) * LDB + wn + nf * 8 + qrow]);
#pragma unroll
                for (int mf = 0; mf < 4; mf++)
                    mma8(acc[mf][nf], a[mf], b0, b1);
            }
        }
        __syncthreads();
    }

    // epilogue (float2 stores; cols are even-aligned pairs)
#pragma unroll
    for (int mf = 0; mf < 4; mf++)
#pragma unroll
    for (int nf = 0; nf < 8; nf++)
#pragma unroll
    for (int t2 = 0; t2 < 2; t2++) {
        int r   = m0 + wm + mf * 16 + qrow + t2 * 8;
        int col = n0 + wn + nf * 8 + qcol * 2;
        float v0 = acc[mf][nf][t2 * 2] + bias[col];
        float v1 = acc[mf][nf][t2 * 2 + 1] + bias[col + 1];
        float2 vv = make_float2(v0, v1);
        if (MODE == 0) {
            int b = r >> 11, s = r & (SEQ - 1), h = col >> 6, hd = col & 63;
            *reinterpret_cast<float2*>(&Cp[((size_t)(b * NH + h) * SEQ + s) * HDIM + hd]) = vv;
        } else {
            *reinterpret_cast<float2*>(&Cp[(size_t)r * g.N + col]) = vv;
        }
    }
}

// ---------------- fused causal flash attention ----------------
// Grid: (SEQ/128, BHT). Block: 256 threads (8 warps, 16 query rows each).
__global__ void __launch_bounds__(256, 2) flash_fwd_kernel(
    const float* __restrict__ Q, const float* __restrict__ K,
    const float* __restrict__ V, float* __restrict__ fwd)
{
    extern __shared__ float fsm[];
    float* Ks = fsm;                 // 64 x FLD
    float* Vs = Ks + 64 * FLD;       // 64 x FLD
    float* Ps = Vs + 64 * FLD;       // 128 x FLD (Q staging, then P)

    const int m0 = blockIdx.x * 128;
    const int bh = blockIdx.y;
    const float* Qp = Q + (size_t)bh * SEQ * HDIM;
    const float* Kp = K + (size_t)bh * SEQ * HDIM;
    const float* Vp = V + (size_t)bh * SEQ * HDIM;

    const int tid = threadIdx.x, lane = tid & 31, warp = tid >> 5;
    const int wm = warp * 16;
    const int qrow = lane >> 2, qcol = lane & 3;

    // stage Q coalesced, then lift fragments to registers
#pragma unroll
    for (int i = 0; i < 8; i++) {
        int e = i * 256 + tid, r = e >> 4, c4 = (e & 15) * 4;
        float4 t = *reinterpret_cast<const float4*>(Qp + (size_t)(m0 + r) * HDIM + c4);
        float* d = Ps + r * FLD + c4;
        d[0] = t.x; d[1] = t.y; d[2] = t.z; d[3] = t.w;
    }
    __syncthreads();

    unsigned qf[8][4];
#pragma unroll
    for (int ks = 0; ks < 8; ks++) {
        int r = wm + qrow, c = ks * 8 + qcol;
        qf[ks][0] = __float_as_uint(Ps[r * FLD + c]);
        qf[ks][1] = __float_as_uint(Ps[(r + 8) * FLD + c]);
        qf[ks][2] = __float_as_uint(Ps[r * FLD + c + 4]);
        qf[ks][3] = __float_as_uint(Ps[(r + 8) * FLD + c + 4]);
    }
    __syncthreads();

    float o[8][4] = {};
    float mrow[2] = {-1e30f, -1e30f};
    float lrow[2] = {0.f, 0.f};

    const int ntiles = m0 / 64 + 2;
    for (int kt = 0; kt < ntiles; kt++) {
        const int n0k = kt * 64;
#pragma unroll
        for (int i = 0; i < 4; i++) {
            int e = i * 256 + tid, r = e >> 4, c4 = (e & 15) * 4;
            float4 tk = *reinterpret_cast<const float4*>(Kp + (size_t)(n0k + r) * HDIM + c4);
            float4 tv = *reinterpret_cast<const float4*>(Vp + (size_t)(n0k + r) * HDIM + c4);
            float* dk = Ks + r * FLD + c4; dk[0]=tk.x; dk[1]=tk.y; dk[2]=tk.z; dk[3]=tk.w;
            float* dv = Vs + r * FLD + c4; dv[0]=tv.x; dv[1]=tv.y; dv[2]=tv.z; dv[3]=tv.w;
        }
        __syncthreads();

        // S = Q @ K^T
        float s[8][4] = {};
#pragma unroll
        for (int ks = 0; ks < 8; ks++) {
#pragma unroll
            for (int nf = 0; nf < 8; nf++) {
                unsigned b0 = __float_as_uint(Ks[(nf * 8 + qrow) * FLD + ks * 8 + qcol]);
                unsigned b1 = __float_as_uint(Ks[(nf * 8 + qrow) * FLD + ks * 8 + qcol + 4]);
                mma8(s[nf], qf[ks], b0, b1);
            }
        }

        // online softmax update
        const bool domask = (n0k + 63 > m0);
#pragma unroll
        for (int t2 = 0; t2 < 2; t2++) {
            const int row = m0 + wm + qrow + t2 * 8;
            float tmax = -1e30f;
#pragma unroll
            for (int nf = 0; nf < 8; nf++)
#pragma unroll
            for (int j = 0; j < 2; j++) {
                float v = s[nf][t2 * 2 + j] * 0.125f;
                if (domask) {
                    int key = n0k + nf * 8 + qcol * 2 + j;
                    if (key > row) v = -1e30f;
                }
                s[nf][t2 * 2 + j] = v;
                tmax = fmaxf(tmax, v);
            }
            tmax = fmaxf(tmax, __shfl_xor_sync(0xffffffffu, tmax, 1));
            tmax = fmaxf(tmax, __shfl_xor_sync(0xffffffffu, tmax, 2));
            float mnew = fmaxf(mrow[t2], tmax);
            float alpha = __expf(mrow[t2] - mnew);
            float psum = 0.f;
#pragma unroll
            for (int nf = 0; nf < 8; nf++)
#pragma unroll
            for (int j = 0; j < 2; j++) {
                float p = __expf(s[nf][t2 * 2 + j] - mnew);
                s[nf][t2 * 2 + j] = p;
                psum += p;
            }
            psum += __shfl_xor_sync(0xffffffffu, psum, 1);
            psum += __shfl_xor_sync(0xffffffffu, psum, 2);
            lrow[t2] = lrow[t2] * alpha + psum;
            mrow[t2] = mnew;
#pragma unroll
            for (int nf = 0; nf < 8; nf++) {
                o[nf][t2 * 2]     *= alpha;
                o[nf][t2 * 2 + 1] *= alpha;
            }
        }

        // write P to smem (A operand for PV)
#pragma unroll
        for (int t2 = 0; t2 < 2; t2++) {
            int r = wm + qrow + t2 * 8;
#pragma unroll
            for (int nf = 0; nf < 8; nf++) {
                *reinterpret_cast<float2*>(&Ps[r * FLD + nf * 8 + qcol * 2]) =
                    make_float2(s[nf][t2 * 2], s[nf][t2 * 2 + 1]);
            }
        }
        __syncthreads();

        // O += P @ V
#pragma unroll
        for (int ks = 0; ks < 8; ks++) {
            unsigned a[4];
            int r = wm + qrow, c = ks * 8 + qcol;
            a[0] = __float_as_uint(Ps[r * FLD + c]);
            a[1] = __float_as_uint(Ps[(r + 8) * FLD + c]);
            a[2] = __float_as_uint(Ps[r * FLD + c + 4]);
            a[3] = __float_as_uint(Ps[(r + 8) * FLD + c + 4]);
#pragma unroll
            for (int nf = 0; nf < 8; nf++) {
                unsigned b0 = __float_as_uint(Vs[(ks * 8 + qcol) * FLD + nf * 8 + qrow]);
                unsigned b1 = __float_as_uint(Vs[(ks * 8 + qcol + 4) * FLD + nf * 8 + qrow]);
                mma8(o[nf], a, b0, b1);
            }
        }
        __syncthreads();
    }

    // epilogue: normalize and store merged [B,S,D]
    const int b = bh >> 4, h = bh & 15;
#pragma unroll
    for (int t2 = 0; t2 < 2; t2++) {
        int srow = m0 + wm + qrow + t2 * 8;
        float inv = 1.f / lrow[t2];
        float* outp = fwd + ((size_t)(b * SEQ + srow)) * DM + h * HDIM;
#pragma unroll
        for (int nf = 0; nf < 8; nf++) {
            *reinterpret_cast<float2*>(&outp[nf * 8 + qcol * 2]) =
                make_float2(o[nf][t2 * 2] * inv, o[nf][t2 * 2 + 1] * inv);
        }
    }
}

// ---------------- window-32 backward attention: one warp per query ----------------
__global__ void bwd_attn_kernel(const float* __restrict__ Qb, const float* __restrict__ Kb,
                                const float* __restrict__ Vb, float* __restrict__ bwd) {
    __shared__ float qsh[8][HDIM];
    const int tid = threadIdx.x;
    const int wid = tid >> 5, lane = tid & 31;
    const int idx = blockIdx.x * 8 + wid;
    const int bh = idx >> 11, m = idx & (SEQ - 1);
    const float* Qp = Qb + (size_t)bh * SEQ * HDIM;
    const float* Kp = Kb + (size_t)bh * SEQ * HDIM;
    const float* Vp = Vb + (size_t)bh * SEQ * HDIM;
    const int b = bh >> 4, h = bh & 15;
    float* outp = bwd + ((size_t)(b * SEQ + m)) * DM + h * HDIM;

    int w = SEQ - 1 - m; if (w > 32) w = 32;
    float o0, o1;
    if (w == 0) {
        float s0 = 0.f, s1 = 0.f;
        for (int s = 0; s < SEQ; s++) {
            s0 += Vp[s * HDIM + lane];
            s1 += Vp[s * HDIM + lane + 32];
        }
        o0 = s0 * (1.f / SEQ); o1 = s1 * (1.f / SEQ);
    } else {
        qsh[wid][lane]      = Qp[m * HDIM + lane];
        qsh[wid][lane + 32] = Qp[m * HDIM + lane + 32];
        __syncwarp();
        float sc = -1e30f;
        if (lane < w) {
            const float* kr = Kp + (size_t)(m + 1 + lane) * HDIM;
            float a = 0.f;
#pragma unroll
            for (int d = 0; d < HDIM; d++) a += qsh[wid][d] * kr[d];
            sc = a * 0.125f;
        }
        float mx = sc;
#pragma unroll
        for (int o = 16; o > 0; o >>= 1) mx = fmaxf(mx, __shfl_xor_sync(0xffffffffu, mx, o));
        float e = __expf(sc - mx);
        float sum = e;
#pragma unroll
        for (int o = 16; o > 0; o >>= 1) sum += __shfl_xor_sync(0xffffffffu, sum, o);
        float p = e / sum;
        o0 = 0.f; o1 = 0.f;
        for (int kk = 0; kk < w; kk++) {
            float pk = __shfl_sync(0xffffffffu, p, kk);
            const float* vr = Vp + (size_t)(m + 1 + kk) * HDIM;
            o0 += pk * vr[lane];
            o1 += pk * vr[lane + 32];
        }
    }
    outp[lane] = o0; outp[lane + 32] = o1;
}

// ---------------- gate LN + sigmoid + fusion ----------------
__global__ void gate_fuse_kernel(const float* __restrict__ gpre, const float* __restrict__ fwd,
                                 const float* __restrict__ bwd, const float* __restrict__ gg,
                                 const float* __restrict__ gb, const float* __restrict__ bstr,
                                 float* __restrict__ fused) {
    const int r = blockIdx.x, tid = threadIdx.x;
    const float* rowp = gpre + (size_t)r * DM;
    __shared__ float red[256];
    float v[4]; float s = 0.f, ss = 0.f;
#pragma unroll
    for (int i = 0; i < 4; i++) { v[i] = rowp[tid + i * 256]; s += v[i]; ss += v[i] * v[i]; }
    red[tid] = s; __syncthreads();
    for (int o = 128; o > 0; o >>= 1) { if (tid < o) red[tid] += red[tid + o]; __syncthreads(); }
    float mean = red[0] * (1.f / DM); __syncthreads();
    red[tid] = ss; __syncthreads();
    for (int o = 128; o > 0; o >>= 1) { if (tid < o) red[tid] += red[tid + o]; __syncthreads(); }
    float var = red[0] * (1.f / DM) - mean * mean;
    float rstd = rsqrtf(var + 1e-5f);
    float strength = 0.3f * sigmoidf_(bstr[0]);
#pragma unroll
    for (int i = 0; i < 4; i++) {
        int j = tid + i * 256;
        float g = sigmoidf_((v[i] - mean) * rstd * gg[j] + gb[j]);
        size_t o = (size_t)r * DM + j;
        fused[o] = fwd[o] + strength * g * bwd[o];
    }
}

// ---------------- final residual + LayerNorm ----------------
__global__ void final_ln_kernel(const float* __restrict__ x, const float* __restrict__ o2,
                                const float* __restrict__ lg, const float* __restrict__ lb,
                                float* __restrict__ out) {
    const int r = blockIdx.x, tid = threadIdx.x;
    __shared__ float red[256];
    float v[4]; float s = 0.f, ss = 0.f;
#pragma unroll
    for (int i = 0; i < 4; i++) {
        size_t o = (size_t)r * DM + tid + i * 256;
        v[i] = x[o] + o2[o];
        s += v[i]; ss += v[i] * v[i];
    }
    red[tid] = s; __syncthreads();
    for (int o = 128; o > 0; o >>= 1) { if (tid < o) red[tid] += red[tid + o]; __syncthreads(); }
    float mean = red[0] * (1.f / DM); __syncthreads();
    red[tid] = ss; __syncthreads();
    for (int o = 128; o > 0; o >>= 1) { if (tid < o) red[tid] += red[tid + o]; __syncthreads(); }
    float var = red[0] * (1.f / DM) - mean * mean;
    float rstd = rsqrtf(var + 1e-5f);
#pragma unroll
    for (int i = 0; i < 4; i++) {
        int j = tid + i * 256;
        size_t o = (size_t)r * DM + j;
        out[o] = (v[i] - mean) * rstd * lg[j] + lb[j];
    }
}

// ---------------- launch ----------------
extern "C" void kernel_launch(void* const* d_in, const int* in_sizes, int n_in,
                              void* d_out, int out_size) {
    const float* x      = (const float*)d_in[0];
    const float* fq_w   = (const float*)d_in[1];
    const float* fq_b   = (const float*)d_in[2];
    const float* fk_w   = (const float*)d_in[3];
    const float* fk_b   = (const float*)d_in[4];
    const float* fv_w   = (const float*)d_in[5];
    const float* fv_b   = (const float*)d_in[6];
    const float* bq_w   = (const float*)d_in[7];
    const float* bq_b   = (const float*)d_in[8];
    const float* bk_w   = (const float*)d_in[9];
    const float* bk_b   = (const float*)d_in[10];
    const float* bv_w   = (const float*)d_in[11];
    const float* bv_b   = (const float*)d_in[12];
    const float* gate_w = (const float*)d_in[13];
    const float* gate_b = (const float*)d_in[14];
    const float* gln_g  = (const float*)d_in[15];
    const float* gln_b  = (const float*)d_in[16];
    const float* bstr   = (const float*)d_in[17];
    const float* out_w  = (const float*)d_in[18];
    const float* out_b  = (const float*)d_in[19];
    const float* ln_g   = (const float*)d_in[20];
    const float* ln_b   = (const float*)d_in[21];

    float *q, *k, *v, *qb, *kb, *vb, *fwd, *bwd, *gpre, *fused, *out2;
    cudaGetSymbolAddress((void**)&q,     g_q);
    cudaGetSymbolAddress((void**)&k,     g_k);
    cudaGetSymbolAddress((void**)&v,     g_v);
    cudaGetSymbolAddress((void**)&qb,    g_qb);
    cudaGetSymbolAddress((void**)&kb,    g_kb);
    cudaGetSymbolAddress((void**)&vb,    g_vb);
    cudaGetSymbolAddress((void**)&fwd,   g_fwd);
    cudaGetSymbolAddress((void**)&bwd,   g_bwd);
    cudaGetSymbolAddress((void**)&gpre,  g_gpre);
    cudaGetSymbolAddress((void**)&fused, g_fused);
    cudaGetSymbolAddress((void**)&out2,  g_out2);

    const int flashSmem = (2 * 64 + 128) * FLD * (int)sizeof(float);  // 69632 B
    cudaFuncSetAttribute(flash_fwd_kernel,
                         cudaFuncAttributeMaxDynamicSharedMemorySize, flashSmem);

    dim3 gblk(128);

    // 6 fused projections -> head layout [BH,S,HD]
    {
        GArgs a = {};
        a.A0 = x; a.K = DM; a.N = DM; a.KA0 = DM;
        const float* W[6] = {fq_w, fk_w, fv_w, bq_w, bk_w, bv_w};
        const float* Bb[6] = {fq_b, fk_b, fv_b, bq_b, bk_b, bv_b};
        float* O[6] = {q, k, v, qb, kb, vb};
        for (int i = 0; i < 6; i++) { a.w6[i] = W[i]; a.b6[i] = Bb[i]; a.o6[i] = O[i]; }
        gemm_t<0><<<dim3(DM / BN, MROWS / BM, 6), gblk>>>(a);
    }

    // fused causal flash attention -> fwd (merged [B,S,D])
    flash_fwd_kernel<<<dim3(SEQ / 128, BHT), 256, flashSmem>>>(q, k, v, fwd);

    // window backward attention
    bwd_attn_kernel<<<(BHT * SEQ) / 8, 256>>>(qb, kb, vb, bwd);

    // gated fusion: gpre = concat(fwd,bwd) @ gate_w + gate_b
    {
        GArgs a = {};
        a.A0 = fwd; a.A1 = bwd; a.B = gate_w; a.bias = gate_b; a.C = gpre;
        a.N = DM; a.K = 2 * DM; a.KA0 = DM;
        gemm_t<1><<<dim3(DM / BN, MROWS / BM, 1), gblk>>>(a);
    }
    gate_fuse_kernel<<<MROWS, 256>>>(gpre, fwd, bwd, gln_g, gln_b, bstr, fused);

    // output projection + residual LN
    {
        GArgs a = {};
        a.A0 = fused; a.A1 = fused; a.B = out_w; a.bias = out_b; a.C = out2;
        a.N = DM; a.K = DM; a.KA0 = DM;
        gemm_t<1><<<dim3(DM / BN, MROWS / BM, 1), gblk>>>(a);
    }
    final_ln_kernel<<<MROWS, 256>>>(x, out2, ln_g, ln_b, (float*)d_out);
}

// round 8
// speedup vs baseline: 3.4930x; 1.1987x over previous
#include <cuda_runtime.h>
#include <cuda_bf16.h>
#include <math.h>

// Problem constants
#define SEQ   2048
#define NB    2
#define NH    16
#define HDIM  64
#define DM    1024
#define BHT   (NB*NH)        // 32 batch*heads
#define MROWS (NB*SEQ)       // 4096

// bf16 GEMM tile config: 128x128 block tile, 4 warps of 64x64, BK=32
#define BM 128
#define BN 128
#define BKH 32
#define LDAH 40              // bf16-element stride for 32-col tiles (80B rows)
#define LDBH 40

// Flash attention
#define FQ  72               // bf16 stride for 64-col Q/K tiles (144B rows, 16B-aligned, conflict-free)
#define FLD 68               // fp32 stride for Vs/Ps

typedef __nv_bfloat16 bf;
typedef __nv_bfloat162 bf2;

// ---------------- scratch (device globals: allocation-free) ----------------
__device__ unsigned short g_xb [(size_t)MROWS*DM];          // x in bf16
__device__ unsigned short g_wt7[7][DM*DM];                  // fq,fk,fv,bq,bk,bv,out  ([N][K] bf16)
__device__ unsigned short g_gwt[2*DM*DM];                   // gate_w transposed [1024][2048]
__device__ unsigned short g_hb16[6][BHT*SEQ*HDIM];          // bf16 proj outputs (head layout)
__device__ float g_q [BHT*SEQ*HDIM];
__device__ float g_k [BHT*SEQ*HDIM];
__device__ float g_v [BHT*SEQ*HDIM];
__device__ float g_qb[BHT*SEQ*HDIM];
__device__ float g_kb[BHT*SEQ*HDIM];
__device__ float g_vb[BHT*SEQ*HDIM];
__device__ float g_fwd [(size_t)MROWS*DM];                  // fp32 fwd (for fuse)
__device__ unsigned short g_fwdb  [(size_t)MROWS*DM];       // bf16 fwd (gemm A)
__device__ unsigned short g_bwdb  [(size_t)MROWS*DM];       // bf16 bwd
__device__ unsigned short g_fusedb[(size_t)MROWS*DM];       // bf16 fused
__device__ float g_gpre[(size_t)MROWS*DM];
__device__ float g_out2[(size_t)MROWS*DM];

// ---------------- helpers ----------------
__device__ __forceinline__ void cpa8(unsigned dst, const void* src) {
    asm volatile("cp.async.ca.shared.global [%0], [%1], 8;" :: "r"(dst), "l"(src));
}
__device__ __forceinline__ void cp_commit() { asm volatile("cp.async.commit_group;"); }
template<int N> __device__ __forceinline__ void cp_wait() {
    asm volatile("cp.async.wait_group %0;" :: "n"(N));
}

// bf16 m16n8k16, fp32 accumulate
__device__ __forceinline__ void mma16(float* c, const unsigned* a, unsigned b0, unsigned b1) {
    asm volatile(
        "mma.sync.aligned.m16n8k16.row.col.f32.bf16.bf16.f32 "
        "{%0,%1,%2,%3}, {%4,%5,%6,%7}, {%8,%9}, {%0,%1,%2,%3};"
        : "+f"(c[0]), "+f"(c[1]), "+f"(c[2]), "+f"(c[3])
        : "r"(a[0]), "r"(a[1]), "r"(a[2]), "r"(a[3]), "r"(b0), "r"(b1));
}
// tf32 m16n8k8 (flash PV)
__device__ __forceinline__ void mma8(float* c, const unsigned* a, unsigned b0, unsigned b1) {
    asm volatile(
        "mma.sync.aligned.m16n8k8.row.col.f32.tf32.tf32.f32 "
        "{%0,%1,%2,%3}, {%4,%5,%6,%7}, {%8,%9}, {%0,%1,%2,%3};"
        : "+f"(c[0]), "+f"(c[1]), "+f"(c[2]), "+f"(c[3])
        : "r"(a[0]), "r"(a[1]), "r"(a[2]), "r"(a[3]), "r"(b0), "r"(b1));
}

__device__ __forceinline__ float sigmoidf_(float x) { return 1.f / (1.f + __expf(-x)); }

// ---------------- conversion kernels ----------------
__global__ void cvt_x_kernel(const float4* __restrict__ x, bf2* __restrict__ xb) {
    int i = blockIdx.x * 256 + threadIdx.x;           // over 4M/4 float4s
    float4 t = x[i];
    xb[2 * i]     = __floats2bfloat162_rn(t.x, t.y);
    xb[2 * i + 1] = __floats2bfloat162_rn(t.z, t.w);
}

// W [K][N] fp32 -> Wt [N][K] bf16 (tiled transpose)
__global__ void transpose_w_kernel(const float* __restrict__ W, unsigned short* __restrict__ Wt,
                                   int K, int N) {
    __shared__ float t[32][33];
    const int n0 = blockIdx.x * 32, k0 = blockIdx.y * 32;
    const int tx = threadIdx.x, ty = threadIdx.y;
#pragma unroll
    for (int j = 0; j < 32; j += 8)
        t[ty + j][tx] = W[(size_t)(k0 + ty + j) * N + n0 + tx];
    __syncthreads();
    bf* out = (bf*)Wt;
#pragma unroll
    for (int j = 0; j < 32; j += 8)
        out[(size_t)(n0 + ty + j) * K + k0 + tx] = __float2bfloat16(t[tx][ty + j]);
}

// ---------------- bf16 GEMM ----------------
struct GB {
    const unsigned short *A0, *A1, *Bt;
    const float* bias;
    float* Cf;
    int N, K, KA0;
    const unsigned short* Bt6[6]; const float* b6[6];
    float* o6[6]; unsigned short* ob6[6];
};

// MODE 0: proj6  (A=xb, B=Wt6[z]) -> fp32 + bf16 head-layout outputs
// MODE 1: dense  (A=concat(A0|A1), B=Bt) -> fp32 C
template<int MODE>
__device__ __forceinline__ void issue_bf(
    const GB& g, const unsigned short* Ap, const unsigned short* Btp,
    unsigned short* As, unsigned short* Bs, int m0, int n0, int ks, int tid)
{
    unsigned aB = (unsigned)__cvta_generic_to_shared(As);
    unsigned bB = (unsigned)__cvta_generic_to_shared(Bs);
    // A tile: BM x BKH bf16 (8B = 4 elements per cp)
#pragma unroll
    for (int i = 0; i < 8; i++) {
        int e = i * 128 + tid, mm = e >> 3, c4 = (e & 7) * 4;
        const unsigned short* src;
        if (MODE == 0) src = Ap + (size_t)(m0 + mm) * g.K + ks + c4;
        else { int gk = ks + c4;
            src = (gk < g.KA0) ? g.A0 + (size_t)(m0 + mm) * g.KA0 + gk
                               : g.A1 + (size_t)(m0 + mm) * g.KA0 + (gk - g.KA0); }
        cpa8(aB + (unsigned)(mm * LDAH + c4) * 2u, src);
    }
    // B tile: BN rows of Wt[n][k] (k contiguous)
#pragma unroll
    for (int i = 0; i < 8; i++) {
        int e = i * 128 + tid, nn = e >> 3, c4 = (e & 7) * 4;
        cpa8(bB + (unsigned)(nn * LDBH + c4) * 2u, Btp + (size_t)(n0 + nn) * g.K + ks + c4);
    }
}

template<int MODE>
__global__ void __launch_bounds__(128, 2) gemm_bf(GB g)
{
    const int nb = blockIdx.x, mb = blockIdx.y, z = blockIdx.z;
    const int m0 = mb * BM, n0 = nb * BN;

    const unsigned short *Ap, *Btp; const float* bias; float* Cf; unsigned short* Cb;
    if (MODE == 0) { Ap = g.A0; Btp = g.Bt6[z]; bias = g.b6[z]; Cf = g.o6[z]; Cb = g.ob6[z]; }
    else           { Ap = g.A0; Btp = g.Bt; bias = g.bias; Cf = g.Cf; Cb = nullptr; }

    __shared__ unsigned short As[2][BM * LDAH];
    __shared__ unsigned short Bs[2][BN * LDBH];

    const int tid = threadIdx.x, lane = tid & 31, warp = tid >> 5;
    const int wm = (warp & 1) * 64, wn = (warp >> 1) * 64;
    const int qrow = lane >> 2, qcol = lane & 3;

    float acc[4][8][4] = {};
    const int nIter = g.K / BKH;

    issue_bf<MODE>(g, Ap, Btp, As[0], Bs[0], m0, n0, 0, tid);
    cp_commit();

    for (int it = 0; it < nIter; ++it) {
        if (it + 1 < nIter) {
            issue_bf<MODE>(g, Ap, Btp, As[(it + 1) & 1], Bs[(it + 1) & 1],
                           m0, n0, (it + 1) * BKH, tid);
            cp_commit();
            cp_wait<1>();
        } else cp_wait<0>();
        __syncthreads();

        const unsigned short* Ab = As[it & 1];
        const unsigned short* Bb = Bs[it & 1];
#pragma unroll
        for (int kk = 0; kk < BKH; kk += 16) {
            unsigned a[4][4];
#pragma unroll
            for (int mf = 0; mf < 4; mf++) {
                int r = wm + mf * 16 + qrow, c = kk + 2 * qcol;
                a[mf][0] = *(const unsigned*)(Ab + r * LDAH + c);
                a[mf][1] = *(const unsigned*)(Ab + (r + 8) * LDAH + c);
                a[mf][2] = *(const unsigned*)(Ab + r * LDAH + c + 8);
                a[mf][3] = *(const unsigned*)(Ab + (r + 8) * LDAH + c + 8);
            }
#pragma unroll
            for (int nf = 0; nf < 8; nf++) {
                int n = wn + nf * 8 + qrow;
                unsigned b0 = *(const unsigned*)(Bb + n * LDBH + kk + 2 * qcol);
                unsigned b1 = *(const unsigned*)(Bb + n * LDBH + kk + 2 * qcol + 8);
#pragma unroll
                for (int mf = 0; mf < 4; mf++)
                    mma16(acc[mf][nf], a[mf], b0, b1);
            }
        }
        __syncthreads();
    }

    // epilogue
#pragma unroll
    for (int mf = 0; mf < 4; mf++)
#pragma unroll
    for (int nf = 0; nf < 8; nf++)
#pragma unroll
    for (int t2 = 0; t2 < 2; t2++) {
        int r   = m0 + wm + mf * 16 + qrow + t2 * 8;
        int col = n0 + wn + nf * 8 + qcol * 2;
        float v0 = acc[mf][nf][t2 * 2] + bias[col];
        float v1 = acc[mf][nf][t2 * 2 + 1] + bias[col + 1];
        if (MODE == 0) {
            int b = r >> 11, s = r & (SEQ - 1), h = col >> 6, hd = col & 63;
            size_t off = ((size_t)(b * NH + h) * SEQ + s) * HDIM + hd;
            *reinterpret_cast<float2*>(&Cf[off]) = make_float2(v0, v1);
            *reinterpret_cast<bf2*>((bf*)Cb + off) = __floats2bfloat162_rn(v0, v1);
        } else {
            *reinterpret_cast<float2*>(&Cf[(size_t)r * g.N + col]) = make_float2(v0, v1);
        }
    }
}

// ---------------- fused causal flash attention (bf16 QK^T, tf32 PV) ----------------
__global__ void __launch_bounds__(256, 2) flash_fwd_kernel(
    const unsigned short* __restrict__ Qg, const unsigned short* __restrict__ Kg,
    const float* __restrict__ Vg, float* __restrict__ fwdf, unsigned short* __restrict__ fwdb)
{
    extern __shared__ char sm_[];
    bf*    Qs = (bf*)sm_;                  // 128 x FQ bf16 (18432 B)
    bf*    Ks = (bf*)(sm_ + 18432);        // 64 x FQ bf16  (9216 B)
    float* Vs = (float*)(sm_ + 27648);     // 64 x FLD fp32 (17408 B)
    float* Ps = (float*)(sm_ + 45056);     // 128 x FLD fp32 (34816 B)

    const int m0 = blockIdx.x * 128;
    const int bh = blockIdx.y;
    const bf* Qp = (const bf*)Qg + (size_t)bh * SEQ * HDIM;
    const bf* Kp = (const bf*)Kg + (size_t)bh * SEQ * HDIM;
    const float* Vp = Vg + (size_t)bh * SEQ * HDIM;

    const int tid = threadIdx.x, lane = tid & 31, warp = tid >> 5;
    const int wm = warp * 16;
    const int qrow = lane >> 2, qcol = lane & 3;

    // stage Q (bf16, 16B chunks), lift fragments
#pragma unroll
    for (int i = 0; i < 4; i++) {
        int e = i * 256 + tid, r = e >> 3, c8 = (e & 7) * 8;
        *reinterpret_cast<uint4*>(Qs + r * FQ + c8) =
            *reinterpret_cast<const uint4*>(Qp + (size_t)(m0 + r) * HDIM + c8);
    }
    __syncthreads();

    unsigned qf[4][4];
#pragma unroll
    for (int ks = 0; ks < 4; ks++) {
        int r = wm + qrow, c = 16 * ks + 2 * qcol;
        qf[ks][0] = *(const unsigned*)(Qs + r * FQ + c);
        qf[ks][1] = *(const unsigned*)(Qs + (r + 8) * FQ + c);
        qf[ks][2] = *(const unsigned*)(Qs + r * FQ + c + 8);
        qf[ks][3] = *(const unsigned*)(Qs + (r + 8) * FQ + c + 8);
    }

    float o[8][4] = {};
    float mrow[2] = {-1e30f, -1e30f};
    float lrow[2] = {0.f, 0.f};

    const int ntiles = m0 / 64 + 2;
    for (int kt = 0; kt < ntiles; kt++) {
        const int n0k = kt * 64;
        __syncthreads();
        // K tile (bf16) + V tile (fp32)
#pragma unroll
        for (int i = 0; i < 2; i++) {
            int e = i * 256 + tid, r = e >> 3, c8 = (e & 7) * 8;
            *reinterpret_cast<uint4*>(Ks + r * FQ + c8) =
                *reinterpret_cast<const uint4*>(Kp + (size_t)(n0k + r) * HDIM + c8);
        }
#pragma unroll
        for (int i = 0; i < 4; i++) {
            int e = i * 256 + tid, r = e >> 4, c4 = (e & 15) * 4;
            float4 tv = *reinterpret_cast<const float4*>(Vp + (size_t)(n0k + r) * HDIM + c4);
            float* dv = Vs + r * FLD + c4; dv[0]=tv.x; dv[1]=tv.y; dv[2]=tv.z; dv[3]=tv.w;
        }
        __syncthreads();

        // S = Q @ K^T (bf16)
        float s[8][4] = {};
#pragma unroll
        for (int ks = 0; ks < 4; ks++) {
#pragma unroll
            for (int nf = 0; nf < 8; nf++) {
                const bf* kb_ = Ks + (nf * 8 + qrow) * FQ + 16 * ks + 2 * qcol;
                unsigned b0 = *(const unsigned*)kb_;
                unsigned b1 = *(const unsigned*)(kb_ + 8);
                mma16(s[nf], qf[ks], b0, b1);
            }
        }

        // online softmax update
        const bool domask = (n0k + 63 > m0);
#pragma unroll
        for (int t2 = 0; t2 < 2; t2++) {
            const int row = m0 + wm + qrow + t2 * 8;
            float tmax = -1e30f;
#pragma unroll
            for (int nf = 0; nf < 8; nf++)
#pragma unroll
            for (int j = 0; j < 2; j++) {
                float v = s[nf][t2 * 2 + j] * 0.125f;
                if (domask) {
                    int key = n0k + nf * 8 + qcol * 2 + j;
                    if (key > row) v = -1e30f;
                }
                s[nf][t2 * 2 + j] = v;
                tmax = fmaxf(tmax, v);
            }
            tmax = fmaxf(tmax, __shfl_xor_sync(0xffffffffu, tmax, 1));
            tmax = fmaxf(tmax, __shfl_xor_sync(0xffffffffu, tmax, 2));
            float mnew = fmaxf(mrow[t2], tmax);
            float alpha = __expf(mrow[t2] - mnew);
            float psum = 0.f;
#pragma unroll
            for (int nf = 0; nf < 8; nf++)
#pragma unroll
            for (int j = 0; j < 2; j++) {
                float p = __expf(s[nf][t2 * 2 + j] - mnew);
                s[nf][t2 * 2 + j] = p;
                psum += p;
            }
            psum += __shfl_xor_sync(0xffffffffu, psum, 1);
            psum += __shfl_xor_sync(0xffffffffu, psum, 2);
            lrow[t2] = lrow[t2] * alpha + psum;
            mrow[t2] = mnew;
#pragma unroll
            for (int nf = 0; nf < 8; nf++) {
                o[nf][t2 * 2]     *= alpha;
                o[nf][t2 * 2 + 1] *= alpha;
            }
        }

        // write P (fp32) to smem
#pragma unroll
        for (int t2 = 0; t2 < 2; t2++) {
            int r = wm + qrow + t2 * 8;
#pragma unroll
            for (int nf = 0; nf < 8; nf++) {
                *reinterpret_cast<float2*>(&Ps[r * FLD + nf * 8 + qcol * 2]) =
                    make_float2(s[nf][t2 * 2], s[nf][t2 * 2 + 1]);
            }
        }
        __syncthreads();

        // O += P @ V (tf32)
#pragma unroll
        for (int ks = 0; ks < 8; ks++) {
            unsigned a[4];
            int r = wm + qrow, c = ks * 8 + qcol;
            a[0] = __float_as_uint(Ps[r * FLD + c]);
            a[1] = __float_as_uint(Ps[(r + 8) * FLD + c]);
            a[2] = __float_as_uint(Ps[r * FLD + c + 4]);
            a[3] = __float_as_uint(Ps[(r + 8) * FLD + c + 4]);
#pragma unroll
            for (int nf = 0; nf < 8; nf++) {
                unsigned b0 = __float_as_uint(Vs[(ks * 8 + qcol) * FLD + nf * 8 + qrow]);
                unsigned b1 = __float_as_uint(Vs[(ks * 8 + qcol + 4) * FLD + nf * 8 + qrow]);
                mma8(o[nf], a, b0, b1);
            }
        }
    }

    // epilogue: normalize, store fp32 + bf16 merged [B,S,D]
    const int b = bh >> 4, h = bh & 15;
#pragma unroll
    for (int t2 = 0; t2 < 2; t2++) {
        int srow = m0 + wm + qrow + t2 * 8;
        float inv = 1.f / lrow[t2];
        size_t base = ((size_t)(b * SEQ + srow)) * DM + h * HDIM;
#pragma unroll
        for (int nf = 0; nf < 8; nf++) {
            float v0 = o[nf][t2 * 2] * inv, v1 = o[nf][t2 * 2 + 1] * inv;
            *reinterpret_cast<float2*>(&fwdf[base + nf * 8 + qcol * 2]) = make_float2(v0, v1);
            *reinterpret_cast<bf2*>((bf*)fwdb + base + nf * 8 + qcol * 2) =
                __floats2bfloat162_rn(v0, v1);
        }
    }
}

// ---------------- window-32 backward attention ----------------
__global__ void bwd_attn_kernel(const float* __restrict__ Qb, const float* __restrict__ Kb,
                                const float* __restrict__ Vb, unsigned short* __restrict__ bwdb) {
    __shared__ float qsh[8][HDIM];
    const int tid = threadIdx.x;
    const int wid = tid >> 5, lane = tid & 31;
    const int idx = blockIdx.x * 8 + wid;
    const int bh = idx >> 11, m = idx & (SEQ - 1);
    const float* Qp = Qb + (size_t)bh * SEQ * HDIM;
    const float* Kp = Kb + (size_t)bh * SEQ * HDIM;
    const float* Vp = Vb + (size_t)bh * SEQ * HDIM;
    const int b = bh >> 4, h = bh & 15;
    bf* outp = (bf*)bwdb + ((size_t)(b * SEQ + m)) * DM + h * HDIM;

    int w = SEQ - 1 - m; if (w > 32) w = 32;
    float o0, o1;
    if (w == 0) {
        float s0 = 0.f, s1 = 0.f;
        for (int s = 0; s < SEQ; s++) {
            s0 += Vp[s * HDIM + lane];
            s1 += Vp[s * HDIM + lane + 32];
        }
        o0 = s0 * (1.f / SEQ); o1 = s1 * (1.f / SEQ);
    } else {
        qsh[wid][lane]      = Qp[m * HDIM + lane];
        qsh[wid][lane + 32] = Qp[m * HDIM + lane + 32];
        __syncwarp();
        float sc = -1e30f;
        if (lane < w) {
            const float* kr = Kp + (size_t)(m + 1 + lane) * HDIM;
            float a = 0.f;
#pragma unroll
            for (int d = 0; d < HDIM; d++) a += qsh[wid][d] * kr[d];
            sc = a * 0.125f;
        }
        float mx = sc;
#pragma unroll
        for (int o = 16; o > 0; o >>= 1) mx = fmaxf(mx, __shfl_xor_sync(0xffffffffu, mx, o));
        float e = __expf(sc - mx);
        float sum = e;
#pragma unroll
        for (int o = 16; o > 0; o >>= 1) sum += __shfl_xor_sync(0xffffffffu, sum, o);
        float p = e / sum;
        o0 = 0.f; o1 = 0.f;
        for (int kk = 0; kk < w; kk++) {
            float pk = __shfl_sync(0xffffffffu, p, kk);
            const float* vr = Vp + (size_t)(m + 1 + kk) * HDIM;
            o0 += pk * vr[lane];
            o1 += pk * vr[lane + 32];
        }
    }
    outp[lane] = __float2bfloat16(o0);
    outp[lane + 32] = __float2bfloat16(o1);
}

// ---------------- gate LN + sigmoid + fusion ----------------
__global__ void gate_fuse_kernel(const float* __restrict__ gpre, const float* __restrict__ fwdf,
                                 const unsigned short* __restrict__ bwdb,
                                 const float* __restrict__ gg, const float* __restrict__ gb,
                                 const float* __restrict__ bstr, unsigned short* __restrict__ fusedb) {
    const int r = blockIdx.x, tid = threadIdx.x;
    const float* rowp = gpre + (size_t)r * DM;
    __shared__ float red[256];
    float v[4]; float s = 0.f, ss = 0.f;
#pragma unroll
    for (int i = 0; i < 4; i++) { v[i] = rowp[tid + i * 256]; s += v[i]; ss += v[i] * v[i]; }
    red[tid] = s; __syncthreads();
    for (int o = 128; o > 0; o >>= 1) { if (tid < o) red[tid] += red[tid + o]; __syncthreads(); }
    float mean = red[0] * (1.f / DM); __syncthreads();
    red[tid] = ss; __syncthreads();
    for (int o = 128; o > 0; o >>= 1) { if (tid < o) red[tid] += red[tid + o]; __syncthreads(); }
    float var = red[0] * (1.f / DM) - mean * mean;
    float rstd = rsqrtf(var + 1e-5f);
    float strength = 0.3f * sigmoidf_(bstr[0]);
#pragma unroll
    for (int i = 0; i < 4; i++) {
        int j = tid + i * 256;
        float g = sigmoidf_((v[i] - mean) * rstd * gg[j] + gb[j]);
        size_t o = (size_t)r * DM + j;
        float bw = __bfloat162float(((const bf*)bwdb)[o]);
        ((bf*)fusedb)[o] = __float2bfloat16(fwdf[o] + strength * g * bw);
    }
}

// ---------------- final residual + LayerNorm ----------------
__global__ void final_ln_kernel(const float* __restrict__ x, const float* __restrict__ o2,
                                const float* __restrict__ lg, const float* __restrict__ lb,
                                float* __restrict__ out) {
    const int r = blockIdx.x, tid = threadIdx.x;
    __shared__ float red[256];
    float v[4]; float s = 0.f, ss = 0.f;
#pragma unroll
    for (int i = 0; i < 4; i++) {
        size_t o = (size_t)r * DM + tid + i * 256;
        v[i] = x[o] + o2[o];
        s += v[i]; ss += v[i] * v[i];
    }
    red[tid] = s; __syncthreads();
    for (int o = 128; o > 0; o >>= 1) { if (tid < o) red[tid] += red[tid + o]; __syncthreads(); }
    float mean = red[0] * (1.f / DM); __syncthreads();
    red[tid] = ss; __syncthreads();
    for (int o = 128; o > 0; o >>= 1) { if (tid < o) red[tid] += red[tid + o]; __syncthreads(); }
    float var = red[0] * (1.f / DM) - mean * mean;
    float rstd = rsqrtf(var + 1e-5f);
#pragma unroll
    for (int i = 0; i < 4; i++) {
        int j = tid + i * 256;
        size_t o = (size_t)r * DM + j;
        out[o] = (v[i] - mean) * rstd * lg[j] + lb[j];
    }
}

// ---------------- launch ----------------
extern "C" void kernel_launch(void* const* d_in, const int* in_sizes, int n_in,
                              void* d_out, int out_size) {
    const float* x      = (const float*)d_in[0];
    const float* fq_w   = (const float*)d_in[1];
    const float* fq_b   = (const float*)d_in[2];
    const float* fk_w   = (const float*)d_in[3];
    const float* fk_b   = (const float*)d_in[4];
    const float* fv_w   = (const float*)d_in[5];
    const float* fv_b   = (const float*)d_in[6];
    const float* bq_w   = (const float*)d_in[7];
    const float* bq_b   = (const float*)d_in[8];
    const float* bk_w   = (const float*)d_in[9];
    const float* bk_b   = (const float*)d_in[10];
    const float* bv_w   = (const float*)d_in[11];
    const float* bv_b   = (const float*)d_in[12];
    const float* gate_w = (const float*)d_in[13];
    const float* gate_b = (const float*)d_in[14];
    const float* gln_g  = (const float*)d_in[15];
    const float* gln_b  = (const float*)d_in[16];
    const float* bstr   = (const float*)d_in[17];
    const float* out_w  = (const float*)d_in[18];
    const float* out_b  = (const float*)d_in[19];
    const float* ln_g   = (const float*)d_in[20];
    const float* ln_b   = (const float*)d_in[21];

    unsigned short *xb, *gwt, *fwdb, *bwdb, *fusedb;
    unsigned short *wt7, *hb16;
    float *qf, *kf, *vf, *qbf, *kbf, *vbf, *fwdf, *gpre, *out2;
    cudaGetSymbolAddress((void**)&xb,     g_xb);
    cudaGetSymbolAddress((void**)&wt7,    g_wt7);
    cudaGetSymbolAddress((void**)&gwt,    g_gwt);
    cudaGetSymbolAddress((void**)&hb16,   g_hb16);
    cudaGetSymbolAddress((void**)&qf,     g_q);
    cudaGetSymbolAddress((void**)&kf,     g_k);
    cudaGetSymbolAddress((void**)&vf,     g_v);
    cudaGetSymbolAddress((void**)&qbf,    g_qb);
    cudaGetSymbolAddress((void**)&kbf,    g_kb);
    cudaGetSymbolAddress((void**)&vbf,    g_vb);
    cudaGetSymbolAddress((void**)&fwdf,   g_fwd);
    cudaGetSymbolAddress((void**)&fwdb,   g_fwdb);
    cudaGetSymbolAddress((void**)&bwdb,   g_bwdb);
    cudaGetSymbolAddress((void**)&fusedb, g_fusedb);
    cudaGetSymbolAddress((void**)&gpre,   g_gpre);
    cudaGetSymbolAddress((void**)&out2,   g_out2);

    const int flashSmem = 79872;   // Qs 18432 + Ks 9216 + Vs 17408 + Ps 34816
    cudaFuncSetAttribute(flash_fwd_kernel,
                         cudaFuncAttributeMaxDynamicSharedMemorySize, flashSmem);

    // conversions
    cvt_x_kernel<<<(MROWS * DM / 4) / 256, 256>>>((const float4*)x, (bf2*)xb);
    {
        const float* W[7] = {fq_w, fk_w, fv_w, bq_w, bk_w, bv_w, out_w};
        for (int i = 0; i < 7; i++)
            transpose_w_kernel<<<dim3(DM / 32, DM / 32), dim3(32, 8)>>>(
                W[i], wt7 + (size_t)i * DM * DM, DM, DM);
        transpose_w_kernel<<<dim3(DM / 32, 2 * DM / 32), dim3(32, 8)>>>(
            gate_w, gwt, 2 * DM, DM);
    }

    // 6 fused projections
    {
        GB a = {};
        a.A0 = xb; a.K = DM; a.N = DM; a.KA0 = DM;
        const float* Bb[6] = {fq_b, fk_b, fv_b, bq_b, bk_b, bv_b};
        float* Of[6] = {qf, kf, vf, qbf, kbf, vbf};
        for (int i = 0; i < 6; i++) {
            a.Bt6[i] = wt7 + (size_t)i * DM * DM;
            a.b6[i] = Bb[i];
            a.o6[i] = Of[i];
            a.ob6[i] = hb16 + (size_t)i * BHT * SEQ * HDIM;
        }
        gemm_bf<0><<<dim3(DM / BN, MROWS / BM, 6), 128>>>(a);
    }

    // flash attention (Q,K bf16; V fp32)
    flash_fwd_kernel<<<dim3(SEQ / 128, BHT), 256, flashSmem>>>(
        hb16, hb16 + (size_t)BHT * SEQ * HDIM, vf, fwdf, fwdb);

    // window backward attention (fp32 in, bf16 out)
    bwd_attn_kernel<<<(BHT * SEQ) / 8, 256>>>(qbf, kbf, vbf, bwdb);

    // gate gemm: gpre = concat(fwdb,bwdb) @ gate_w + gate_b
    {
        GB a = {};
        a.A0 = fwdb; a.A1 = bwdb; a.Bt = gwt; a.bias = gate_b; a.Cf = gpre;
        a.N = DM; a.K = 2 * DM; a.KA0 = DM;
        gemm_bf<1><<<dim3(DM / BN, MROWS / BM, 1), 128>>>(a);
    }
    gate_fuse_kernel<<<MROWS, 256>>>(gpre, fwdf, bwdb, gln_g, gln_b, bstr, fusedb);

    // output projection
    {
        GB a = {};
        a.A0 = fusedb; a.A1 = fusedb; a.Bt = wt7 + (size_t)6 * DM * DM;
        a.bias = out_b; a.Cf = out2;
        a.N = DM; a.K = DM; a.KA0 = DM;
        gemm_bf<1><<<dim3(DM / BN, MROWS / BM, 1), 128>>>(a);
    }
    final_ln_kernel<<<MROWS, 256>>>(x, out2, ln_g, ln_b, (float*)d_out);
}

// round 9
// speedup vs baseline: 5.8661x; 1.6794x over previous
#include <cuda_runtime.h>
#include <cuda_bf16.h>
#include <math.h>

// Problem constants
#define SEQ   2048
#define NB    2
#define NH    16
#define HDIM  64
#define DM    1024
#define BHT   (NB*NH)        // 32 batch*heads
#define MROWS (NB*SEQ)       // 4096

// bf16 GEMM tile config: 128x128 block tile, 4 warps of 64x64, BK=32, 3-stage
#define BM 128
#define BN 128
#define BKH 32
#define LDAH 40              // bf16-element stride for 32-col tiles (80B rows)
#define LDBH 40
#define GSTAGE_A (BM*LDAH)   // shorts per A stage
#define GSTAGE_B (BN*LDBH)

// Flash attention
#define FQ  72               // bf16 stride for 64-col Q/K tiles
#define FLD 68               // fp32 stride for Vs/Ps

typedef __nv_bfloat16 bf;
typedef __nv_bfloat162 bf2;

// ---------------- scratch (device globals: allocation-free) ----------------
__device__ unsigned short g_xb [(size_t)MROWS*DM];          // x in bf16
__device__ unsigned short g_wt7[7][DM*DM];                  // fq,fk,fv,bq,bk,bv,out  ([N][K] bf16)
__device__ unsigned short g_gwt[2*DM*DM];                   // gate_w transposed [1024][2048]
__device__ unsigned short g_hb16[6][BHT*SEQ*HDIM];          // bf16 proj outputs (head layout)
__device__ float g_v [BHT*SEQ*HDIM];
__device__ float g_qb[BHT*SEQ*HDIM];
__device__ float g_kb[BHT*SEQ*HDIM];
__device__ float g_vb[BHT*SEQ*HDIM];
__device__ float g_unused[3][BHT*SEQ*HDIM];                 // fp32 slots for q,k (unwritten)
__device__ float g_fwd [(size_t)MROWS*DM];                  // fp32 fwd (for fuse)
__device__ unsigned short g_fwdb  [(size_t)MROWS*DM];       // bf16 fwd (gemm A)
__device__ unsigned short g_bwdb  [(size_t)MROWS*DM];       // bf16 bwd
__device__ unsigned short g_fusedb[(size_t)MROWS*DM];       // bf16 fused
__device__ float g_gpre[(size_t)MROWS*DM];
__device__ float g_out2[(size_t)MROWS*DM];

// ---------------- helpers ----------------
__device__ __forceinline__ void cpa8(unsigned dst, const void* src) {
    asm volatile("cp.async.ca.shared.global [%0], [%1], 8;" :: "r"(dst), "l"(src));
}
__device__ __forceinline__ void cp_commit() { asm volatile("cp.async.commit_group;"); }
template<int N> __device__ __forceinline__ void cp_wait() {
    asm volatile("cp.async.wait_group %0;" :: "n"(N));
}

// bf16 m16n8k16, fp32 accumulate
__device__ __forceinline__ void mma16(float* c, const unsigned* a, unsigned b0, unsigned b1) {
    asm volatile(
        "mma.sync.aligned.m16n8k16.row.col.f32.bf16.bf16.f32 "
        "{%0,%1,%2,%3}, {%4,%5,%6,%7}, {%8,%9}, {%0,%1,%2,%3};"
        : "+f"(c[0]), "+f"(c[1]), "+f"(c[2]), "+f"(c[3])
        : "r"(a[0]), "r"(a[1]), "r"(a[2]), "r"(a[3]), "r"(b0), "r"(b1));
}
// tf32 m16n8k8 (flash PV)
__device__ __forceinline__ void mma8(float* c, const unsigned* a, unsigned b0, unsigned b1) {
    asm volatile(
        "mma.sync.aligned.m16n8k8.row.col.f32.tf32.tf32.f32 "
        "{%0,%1,%2,%3}, {%4,%5,%6,%7}, {%8,%9}, {%0,%1,%2,%3};"
        : "+f"(c[0]), "+f"(c[1]), "+f"(c[2]), "+f"(c[3])
        : "r"(a[0]), "r"(a[1]), "r"(a[2]), "r"(a[3]), "r"(b0), "r"(b1));
}

__device__ __forceinline__ float sigmoidf_(float x) { return 1.f / (1.f + __expf(-x)); }

// ---------------- conversion kernels ----------------
__global__ void cvt_x_kernel(const float4* __restrict__ x, bf2* __restrict__ xb) {
    int i = blockIdx.x * 256 + threadIdx.x;
    float4 t = x[i];
    xb[2 * i]     = __floats2bfloat162_rn(t.x, t.y);
    xb[2 * i + 1] = __floats2bfloat162_rn(t.z, t.w);
}

// W [K][N] fp32 -> Wt [N][K] bf16 (tiled transpose)
__global__ void transpose_w_kernel(const float* __restrict__ W, unsigned short* __restrict__ Wt,
                                   int K, int N) {
    __shared__ float t[32][33];
    const int n0 = blockIdx.x * 32, k0 = blockIdx.y * 32;
    const int tx = threadIdx.x, ty = threadIdx.y;
#pragma unroll
    for (int j = 0; j < 32; j += 8)
        t[ty + j][tx] = W[(size_t)(k0 + ty + j) * N + n0 + tx];
    __syncthreads();
    bf* out = (bf*)Wt;
#pragma unroll
    for (int j = 0; j < 32; j += 8)
        out[(size_t)(n0 + ty + j) * K + k0 + tx] = __float2bfloat16(t[tx][ty + j]);
}

// ---------------- bf16 GEMM (3-stage cp.async pipeline) ----------------
struct GB {
    const unsigned short *A0, *A1, *Bt;
    const float* bias;
    float* Cf;
    int N, K, KA0, maskF, maskB;
    const unsigned short* Bt6[6]; const float* b6[6];
    float* o6[6]; unsigned short* ob6[6];
};

template<int MODE>
__device__ __forceinline__ void issue_bf(
    const GB& g, const unsigned short* Ap, const unsigned short* Btp,
    unsigned short* As, unsigned short* Bs, int m0, int n0, int ks, int tid)
{
    unsigned aB = (unsigned)__cvta_generic_to_shared(As);
    unsigned bB = (unsigned)__cvta_generic_to_shared(Bs);
#pragma unroll
    for (int i = 0; i < 8; i++) {
        int e = i * 128 + tid, mm = e >> 3, c4 = (e & 7) * 4;
        const unsigned short* src;
        if (MODE == 0) src = Ap + (size_t)(m0 + mm) * g.K + ks + c4;
        else { int gk = ks + c4;
            src = (gk < g.KA0) ? g.A0 + (size_t)(m0 + mm) * g.KA0 + gk
                               : g.A1 + (size_t)(m0 + mm) * g.KA0 + (gk - g.KA0); }
        cpa8(aB + (unsigned)(mm * LDAH + c4) * 2u, src);
    }
#pragma unroll
    for (int i = 0; i < 8; i++) {
        int e = i * 128 + tid, nn = e >> 3, c4 = (e & 7) * 4;
        cpa8(bB + (unsigned)(nn * LDBH + c4) * 2u, Btp + (size_t)(n0 + nn) * g.K + ks + c4);
    }
}

template<int MODE>
__global__ void __launch_bounds__(128, 2) gemm_bf(GB g)
{
    extern __shared__ unsigned short gsm[];
    unsigned short* Asm = gsm;                       // 3 stages A
    unsigned short* Bsm = gsm + 3 * GSTAGE_A;        // 3 stages B

    const int nb = blockIdx.x, mb = blockIdx.y, z = blockIdx.z;
    const int m0 = mb * BM, n0 = nb * BN;

    const unsigned short *Ap, *Btp; const float* bias; float* Cf; unsigned short* Cb;
    if (MODE == 0) { Ap = g.A0; Btp = g.Bt6[z]; bias = g.b6[z]; Cf = g.o6[z]; Cb = g.ob6[z]; }
    else           { Ap = g.A0; Btp = g.Bt; bias = g.bias; Cf = g.Cf; Cb = nullptr; }

    const int tid = threadIdx.x, lane = tid & 31, warp = tid >> 5;
    const int wm = (warp & 1) * 64, wn = (warp >> 1) * 64;
    const int qrow = lane >> 2, qcol = lane & 3;

    float acc[4][8][4] = {};
    const int nIter = g.K / BKH;

    issue_bf<MODE>(g, Ap, Btp, Asm, Bsm, m0, n0, 0, tid);
    cp_commit();
    issue_bf<MODE>(g, Ap, Btp, Asm + GSTAGE_A, Bsm + GSTAGE_B, m0, n0, BKH, tid);
    cp_commit();

    int bi = 0;                      // buffer index = it % 3
    for (int it = 0; it < nIter; ++it) {
        if (it + 1 < nIter) cp_wait<1>(); else cp_wait<0>();
        __syncthreads();
        if (it + 2 < nIter) {
            int wb = bi + 2; if (wb >= 3) wb -= 3;
            issue_bf<MODE>(g, Ap, Btp, Asm + wb * GSTAGE_A, Bsm + wb * GSTAGE_B,
                           m0, n0, (it + 2) * BKH, tid);
            cp_commit();
        }
        const unsigned short* Ab = Asm + bi * GSTAGE_A;
        const unsigned short* Bb = Bsm + bi * GSTAGE_B;
#pragma unroll
        for (int kk = 0; kk < BKH; kk += 16) {
            unsigned a[4][4];
#pragma unroll
            for (int mf = 0; mf < 4; mf++) {
                int r = wm + mf * 16 + qrow, c = kk + 2 * qcol;
                a[mf][0] = *(const unsigned*)(Ab + r * LDAH + c);
                a[mf][1] = *(const unsigned*)(Ab + (r + 8) * LDAH + c);
                a[mf][2] = *(const unsigned*)(Ab + r * LDAH + c + 8);
                a[mf][3] = *(const unsigned*)(Ab + (r + 8) * LDAH + c + 8);
            }
#pragma unroll
            for (int nf = 0; nf < 8; nf++) {
                int n = wn + nf * 8 + qrow;
                unsigned b0 = *(const unsigned*)(Bb + n * LDBH + kk + 2 * qcol);
                unsigned b1 = *(const unsigned*)(Bb + n * LDBH + kk + 2 * qcol + 8);
#pragma unroll
                for (int mf = 0; mf < 4; mf++)
                    mma16(acc[mf][nf], a[mf], b0, b1);
            }
        }
        if (++bi == 3) bi = 0;
    }

    const bool doF = (MODE != 0) || ((g.maskF >> z) & 1);
    const bool doB = (MODE == 0) && ((g.maskB >> z) & 1);
#pragma unroll
    for (int mf = 0; mf < 4; mf++)
#pragma unroll
    for (int nf = 0; nf < 8; nf++)
#pragma unroll
    for (int t2 = 0; t2 < 2; t2++) {
        int r   = m0 + wm + mf * 16 + qrow + t2 * 8;
        int col = n0 + wn + nf * 8 + qcol * 2;
        float v0 = acc[mf][nf][t2 * 2] + bias[col];
        float v1 = acc[mf][nf][t2 * 2 + 1] + bias[col + 1];
        if (MODE == 0) {
            int b = r >> 11, s = r & (SEQ - 1), h = col >> 6, hd = col & 63;
            size_t off = ((size_t)(b * NH + h) * SEQ + s) * HDIM + hd;
            if (doF) *reinterpret_cast<float2*>(&Cf[off]) = make_float2(v0, v1);
            if (doB) *reinterpret_cast<bf2*>((bf*)Cb + off) = __floats2bfloat162_rn(v0, v1);
        } else {
            *reinterpret_cast<float2*>(&Cf[(size_t)r * g.N + col]) = make_float2(v0, v1);
        }
    }
}

// ---------------- fused causal flash attention (bf16 QK^T, tf32 PV) ----------------
__global__ void __launch_bounds__(256, 2) flash_fwd_kernel(
    const unsigned short* __restrict__ Qg, const unsigned short* __restrict__ Kg,
    const float* __restrict__ Vg, float* __restrict__ fwdf, unsigned short* __restrict__ fwdb)
{
    extern __shared__ char sm_[];
    bf*    Qs = (bf*)sm_;                  // 128 x FQ bf16 (18432 B)
    bf*    Ks = (bf*)(sm_ + 18432);        // 64 x FQ bf16  (9216 B)
    float* Vs = (float*)(sm_ + 27648);     // 64 x FLD fp32 (17408 B)
    float* Ps = (float*)(sm_ + 45056);     // 128 x FLD fp32 (34816 B)

    const int m0 = blockIdx.x * 128;
    const int bh = blockIdx.y;
    const bf* Qp = (const bf*)Qg + (size_t)bh * SEQ * HDIM;
    const bf* Kp = (const bf*)Kg + (size_t)bh * SEQ * HDIM;
    const float* Vp = Vg + (size_t)bh * SEQ * HDIM;

    const int tid = threadIdx.x, lane = tid & 31, warp = tid >> 5;
    const int wm = warp * 16;
    const int qrow = lane >> 2, qcol = lane & 3;

#pragma unroll
    for (int i = 0; i < 4; i++) {
        int e = i * 256 + tid, r = e >> 3, c8 = (e & 7) * 8;
        *reinterpret_cast<uint4*>(Qs + r * FQ + c8) =
            *reinterpret_cast<const uint4*>(Qp + (size_t)(m0 + r) * HDIM + c8);
    }
    __syncthreads();

    unsigned qf[4][4];
#pragma unroll
    for (int ks = 0; ks < 4; ks++) {
        int r = wm + qrow, c = 16 * ks + 2 * qcol;
        qf[ks][0] = *(const unsigned*)(Qs + r * FQ + c);
        qf[ks][1] = *(const unsigned*)(Qs + (r + 8) * FQ + c);
        qf[ks][2] = *(const unsigned*)(Qs + r * FQ + c + 8);
        qf[ks][3] = *(const unsigned*)(Qs + (r + 8) * FQ + c + 8);
    }

    float o[8][4] = {};
    float mrow[2] = {-1e30f, -1e30f};
    float lrow[2] = {0.f, 0.f};

    const int ntiles = m0 / 64 + 2;
    for (int kt = 0; kt < ntiles; kt++) {
        const int n0k = kt * 64;
        __syncthreads();
#pragma unroll
        for (int i = 0; i < 2; i++) {
            int e = i * 256 + tid, r = e >> 3, c8 = (e & 7) * 8;
            *reinterpret_cast<uint4*>(Ks + r * FQ + c8) =
                *reinterpret_cast<const uint4*>(Kp + (size_t)(n0k + r) * HDIM + c8);
        }
#pragma unroll
        for (int i = 0; i < 4; i++) {
            int e = i * 256 + tid, r = e >> 4, c4 = (e & 15) * 4;
            float4 tv = *reinterpret_cast<const float4*>(Vp + (size_t)(n0k + r) * HDIM + c4);
            float* dv = Vs + r * FLD + c4; dv[0]=tv.x; dv[1]=tv.y; dv[2]=tv.z; dv[3]=tv.w;
        }
        __syncthreads();

        float s[8][4] = {};
#pragma unroll
        for (int ks = 0; ks < 4; ks++) {
#pragma unroll
            for (int nf = 0; nf < 8; nf++) {
                const bf* kb_ = Ks + (nf * 8 + qrow) * FQ + 16 * ks + 2 * qcol;
                unsigned b0 = *(const unsigned*)kb_;
                unsigned b1 = *(const unsigned*)(kb_ + 8);
                mma16(s[nf], qf[ks], b0, b1);
            }
        }

        const bool domask = (n0k + 63 > m0);
#pragma unroll
        for (int t2 = 0; t2 < 2; t2++) {
            const int row = m0 + wm + qrow + t2 * 8;
            float tmax = -1e30f;
#pragma unroll
            for (int nf = 0; nf < 8; nf++)
#pragma unroll
            for (int j = 0; j < 2; j++) {
                float v = s[nf][t2 * 2 + j] * 0.125f;
                if (domask) {
                    int key = n0k + nf * 8 + qcol * 2 + j;
                    if (key > row) v = -1e30f;
                }
                s[nf][t2 * 2 + j] = v;
                tmax = fmaxf(tmax, v);
            }
            tmax = fmaxf(tmax, __shfl_xor_sync(0xffffffffu, tmax, 1));
            tmax = fmaxf(tmax, __shfl_xor_sync(0xffffffffu, tmax, 2));
            float mnew = fmaxf(mrow[t2], tmax);
            float alpha = __expf(mrow[t2] - mnew);
            float psum = 0.f;
#pragma unroll
            for (int nf = 0; nf < 8; nf++)
#pragma unroll
            for (int j = 0; j < 2; j++) {
                float p = __expf(s[nf][t2 * 2 + j] - mnew);
                s[nf][t2 * 2 + j] = p;
                psum += p;
            }
            psum += __shfl_xor_sync(0xffffffffu, psum, 1);
            psum += __shfl_xor_sync(0xffffffffu, psum, 2);
            lrow[t2] = lrow[t2] * alpha + psum;
            mrow[t2] = mnew;
#pragma unroll
            for (int nf = 0; nf < 8; nf++) {
                o[nf][t2 * 2]     *= alpha;
                o[nf][t2 * 2 + 1] *= alpha;
            }
        }

#pragma unroll
        for (int t2 = 0; t2 < 2; t2++) {
            int r = wm + qrow + t2 * 8;
#pragma unroll
            for (int nf = 0; nf < 8; nf++) {
                *reinterpret_cast<float2*>(&Ps[r * FLD + nf * 8 + qcol * 2]) =
                    make_float2(s[nf][t2 * 2], s[nf][t2 * 2 + 1]);
            }
        }
        __syncthreads();

#pragma unroll
        for (int ks = 0; ks < 8; ks++) {
            unsigned a[4];
            int r = wm + qrow, c = ks * 8 + qcol;
            a[0] = __float_as_uint(Ps[r * FLD + c]);
            a[1] = __float_as_uint(Ps[(r + 8) * FLD + c]);
            a[2] = __float_as_uint(Ps[r * FLD + c + 4]);
            a[3] = __float_as_uint(Ps[(r + 8) * FLD + c + 4]);
#pragma unroll
            for (int nf = 0; nf < 8; nf++) {
                unsigned b0 = __float_as_uint(Vs[(ks * 8 + qcol) * FLD + nf * 8 + qrow]);
                unsigned b1 = __float_as_uint(Vs[(ks * 8 + qcol + 4) * FLD + nf * 8 + qrow]);
                mma8(o[nf], a, b0, b1);
            }
        }
    }

    const int b = bh >> 4, h = bh & 15;
#pragma unroll
    for (int t2 = 0; t2 < 2; t2++) {
        int srow = m0 + wm + qrow + t2 * 8;
        float inv = 1.f / lrow[t2];
        size_t base = ((size_t)(b * SEQ + srow)) * DM + h * HDIM;
#pragma unroll
        for (int nf = 0; nf < 8; nf++) {
            float v0 = o[nf][t2 * 2] * inv, v1 = o[nf][t2 * 2 + 1] * inv;
            *reinterpret_cast<float2*>(&fwdf[base + nf * 8 + qcol * 2]) = make_float2(v0, v1);
            *reinterpret_cast<bf2*>((bf*)fwdb + base + nf * 8 + qcol * 2) =
                __floats2bfloat162_rn(v0, v1);
        }
    }
}

// ---------------- tiled window-32 backward attention ----------------
// Grid: (SEQ/64, BHT), block 256 (8 warps x 8 queries each).
// K/V rows [m0+1, m0+96) staged in smem (stride 65 -> conflict-free).
__global__ void __launch_bounds__(256) bwd_attn_kernel(
    const float* __restrict__ Qb, const float* __restrict__ Kb,
    const float* __restrict__ Vb, unsigned short* __restrict__ bwdb)
{
    extern __shared__ float bsm[];
    float* Ks = bsm;              // 96 x 65
    float* Vs = bsm + 96 * 65;    // 96 x 65
    __shared__ float qsh[8][66];

    const int m0 = blockIdx.x * 64;
    const int bh = blockIdx.y;
    const float* Qp = Qb + (size_t)bh * SEQ * HDIM;
    const float* Kp = Kb + (size_t)bh * SEQ * HDIM;
    const float* Vp = Vb + (size_t)bh * SEQ * HDIM;
    const int b = bh >> 4, h = bh & 15;

    const int tid = threadIdx.x, wid = tid >> 5, lane = tid & 31;
    const int nrows = min(96, SEQ - 1 - m0);

    for (int i = tid; i < nrows * 16; i += 256) {
        int row = i >> 4, c4 = (i & 15) * 4;
        float4 tk = *reinterpret_cast<const float4*>(Kp + (size_t)(m0 + 1 + row) * HDIM + c4);
        float4 tv = *reinterpret_cast<const float4*>(Vp + (size_t)(m0 + 1 + row) * HDIM + c4);
        float* dk = Ks + row * 65 + c4; dk[0]=tk.x; dk[1]=tk.y; dk[2]=tk.z; dk[3]=tk.w;
        float* dv = Vs + row * 65 + c4; dv[0]=tv.x; dv[1]=tv.y; dv[2]=tv.z; dv[3]=tv.w;
    }
    __syncthreads();

#pragma unroll
    for (int t = 0; t < 8; t++) {
        const int m = m0 + wid * 8 + t;
        int w = SEQ - 1 - m; if (w > 32) w = 32;
        if (w <= 0) continue;                      // last row handled by vb_mean_kernel

        __syncwarp();
        qsh[wid][lane]      = Qp[m * HDIM + lane];
        qsh[wid][lane + 32] = Qp[m * HDIM + lane + 32];
        __syncwarp();

        float sc = -1e30f;
        if (lane < w) {
            const float* kr = Ks + (m - m0 + lane) * 65;
            float a = 0.f;
#pragma unroll
            for (int d = 0; d < HDIM; d++) a += qsh[wid][d] * kr[d];
            sc = a * 0.125f;
        }
        float mx = sc;
#pragma unroll
        for (int o = 16; o > 0; o >>= 1) mx = fmaxf(mx, __shfl_xor_sync(0xffffffffu, mx, o));
        float e = __expf(sc - mx);
        float sum = e;
#pragma unroll
        for (int o = 16; o > 0; o >>= 1) sum += __shfl_xor_sync(0xffffffffu, sum, o);
        float p = e / sum;

        float o0 = 0.f, o1 = 0.f;
        for (int kk = 0; kk < w; kk++) {
            float pk = __shfl_sync(0xffffffffu, p, kk);
            const float* vr = Vs + (m - m0 + kk) * 65;
            o0 += pk * vr[lane];
            o1 += pk * vr[lane + 32];
        }
        bf* outp = (bf*)bwdb + ((size_t)(b * SEQ + m)) * DM + h * HDIM;
        outp[lane] = __float2bfloat16(o0);
        outp[lane + 32] = __float2bfloat16(o1);
    }
}

// mean of Vb over all S for the all-masked last row (ref: uniform softmax)
__global__ void vb_mean_kernel(const float* __restrict__ Vb, unsigned short* __restrict__ bwdb) {
    __shared__ float part[4][64];
    const int bh = blockIdx.x, tid = threadIdx.x;
    const int col = tid & 63, grp = tid >> 6;
    const float* Vp = Vb + (size_t)bh * SEQ * HDIM;
    float s = 0.f;
    for (int r = grp; r < SEQ; r += 4) s += Vp[(size_t)r * HDIM + col];
    part[grp][col] = s;
    __syncthreads();
    if (tid < 64) {
        float m = (part[0][tid] + part[1][tid] + part[2][tid] + part[3][tid]) * (1.f / SEQ);
        int b = bh >> 4, h = bh & 15;
        ((bf*)bwdb)[((size_t)(b * SEQ + SEQ - 1)) * DM + h * HDIM + tid] = __float2bfloat16(m);
    }
}

// ---------------- gate LN + sigmoid + fusion ----------------
__global__ void gate_fuse_kernel(const float* __restrict__ gpre, const float* __restrict__ fwdf,
                                 const unsigned short* __restrict__ bwdb,
                                 const float* __restrict__ gg, const float* __restrict__ gb,
                                 const float* __restrict__ bstr, unsigned short* __restrict__ fusedb) {
    const int r = blockIdx.x, tid = threadIdx.x;
    const float* rowp = gpre + (size_t)r * DM;
    __shared__ float red[256];
    float v[4]; float s = 0.f, ss = 0.f;
#pragma unroll
    for (int i = 0; i < 4; i++) { v[i] = rowp[tid + i * 256]; s += v[i]; ss += v[i] * v[i]; }
    red[tid] = s; __syncthreads();
    for (int o = 128; o > 0; o >>= 1) { if (tid < o) red[tid] += red[tid + o]; __syncthreads(); }
    float mean = red[0] * (1.f / DM); __syncthreads();
    red[tid] = ss; __syncthreads();
    for (int o = 128; o > 0; o >>= 1) { if (tid < o) red[tid] += red[tid + o]; __syncthreads(); }
    float var = red[0] * (1.f / DM) - mean * mean;
    float rstd = rsqrtf(var + 1e-5f);
    float strength = 0.3f * sigmoidf_(bstr[0]);
#pragma unroll
    for (int i = 0; i < 4; i++) {
        int j = tid + i * 256;
        float g = sigmoidf_((v[i] - mean) * rstd * gg[j] + gb[j]);
        size_t o = (size_t)r * DM + j;
        float bw = __bfloat162float(((const bf*)bwdb)[o]);
        ((bf*)fusedb)[o] = __float2bfloat16(fwdf[o] + strength * g * bw);
    }
}

// ---------------- final residual + LayerNorm ----------------
__global__ void final_ln_kernel(const float* __restrict__ x, const float* __restrict__ o2,
                                const float* __restrict__ lg, const float* __restrict__ lb,
                                float* __restrict__ out) {
    const int r = blockIdx.x, tid = threadIdx.x;
    __shared__ float red[256];
    float v[4]; float s = 0.f, ss = 0.f;
#pragma unroll
    for (int i = 0; i < 4; i++) {
        size_t o = (size_t)r * DM + tid + i * 256;
        v[i] = x[o] + o2[o];
        s += v[i]; ss += v[i] * v[i];
    }
    red[tid] = s; __syncthreads();
    for (int o = 128; o > 0; o >>= 1) { if (tid < o) red[tid] += red[tid + o]; __syncthreads(); }
    float mean = red[0] * (1.f / DM); __syncthreads();
    red[tid] = ss; __syncthreads();
    for (int o = 128; o > 0; o >>= 1) { if (tid < o) red[tid] += red[tid + o]; __syncthreads(); }
    float var = red[0] * (1.f / DM) - mean * mean;
    float rstd = rsqrtf(var + 1e-5f);
#pragma unroll
    for (int i = 0; i < 4; i++) {
        int j = tid + i * 256;
        size_t o = (size_t)r * DM + j;
        out[o] = (v[i] - mean) * rstd * lg[j] + lb[j];
    }
}

// ---------------- launch ----------------
extern "C" void kernel_launch(void* const* d_in, const int* in_sizes, int n_in,
                              void* d_out, int out_size) {
    const float* x      = (const float*)d_in[0];
    const float* fq_w   = (const float*)d_in[1];
    const float* fq_b   = (const float*)d_in[2];
    const float* fk_w   = (const float*)d_in[3];
    const float* fk_b   = (const float*)d_in[4];
    const float* fv_w   = (const float*)d_in[5];
    const float* fv_b   = (const float*)d_in[6];
    const float* bq_w   = (const float*)d_in[7];
    const float* bq_b   = (const float*)d_in[8];
    const float* bk_w   = (const float*)d_in[9];
    const float* bk_b   = (const float*)d_in[10];
    const float* bv_w   = (const float*)d_in[11];
    const float* bv_b   = (const float*)d_in[12];
    const float* gate_w = (const float*)d_in[13];
    const float* gate_b = (const float*)d_in[14];
    const float* gln_g  = (const float*)d_in[15];
    const float* gln_b  = (const float*)d_in[16];
    const float* bstr   = (const float*)d_in[17];
    const float* out_w  = (const float*)d_in[18];
    const float* out_b  = (const float*)d_in[19];
    const float* ln_g   = (const float*)d_in[20];
    const float* ln_b   = (const float*)d_in[21];

    unsigned short *xb, *gwt, *fwdb, *bwdb, *fusedb, *wt7, *hb16;
    float *vf, *qbf, *kbf, *vbf, *unused, *fwdf, *gpre, *out2;
    cudaGetSymbolAddress((void**)&xb,     g_xb);
    cudaGetSymbolAddress((void**)&wt7,    g_wt7);
    cudaGetSymbolAddress((void**)&gwt,    g_gwt);
    cudaGetSymbolAddress((void**)&hb16,   g_hb16);
    cudaGetSymbolAddress((void**)&vf,     g_v);
    cudaGetSymbolAddress((void**)&qbf,    g_qb);
    cudaGetSymbolAddress((void**)&kbf,    g_kb);
    cudaGetSymbolAddress((void**)&vbf,    g_vb);
    cudaGetSymbolAddress((void**)&unused, g_unused);
    cudaGetSymbolAddress((void**)&fwdf,   g_fwd);
    cudaGetSymbolAddress((void**)&fwdb,   g_fwdb);
    cudaGetSymbolAddress((void**)&bwdb,   g_bwdb);
    cudaGetSymbolAddress((void**)&fusedb, g_fusedb);
    cudaGetSymbolAddress((void**)&gpre,   g_gpre);
    cudaGetSymbolAddress((void**)&out2,   g_out2);

    const int flashSmem = 79872;
    const int gemmSmem  = 3 * (GSTAGE_A + GSTAGE_B) * 2;   // 61440
    const int bwdSmem   = 2 * 96 * 65 * 4;                 // 49920
    cudaFuncSetAttribute(flash_fwd_kernel,
                         cudaFuncAttributeMaxDynamicSharedMemorySize, flashSmem);
    cudaFuncSetAttribute(gemm_bf<0>,
                         cudaFuncAttributeMaxDynamicSharedMemorySize, gemmSmem);
    cudaFuncSetAttribute(gemm_bf<1>,
                         cudaFuncAttributeMaxDynamicSharedMemorySize, gemmSmem);
    cudaFuncSetAttribute(bwd_attn_kernel,
                         cudaFuncAttributeMaxDynamicSharedMemorySize, bwdSmem);

    // conversions
    cvt_x_kernel<<<(MROWS * DM / 4) / 256, 256>>>((const float4*)x, (bf2*)xb);
    {
        const float* W[7] = {fq_w, fk_w, fv_w, bq_w, bk_w, bv_w, out_w};
        for (int i = 0; i < 7; i++)
            transpose_w_kernel<<<dim3(DM / 32, DM / 32), dim3(32, 8)>>>(
                W[i], wt7 + (size_t)i * DM * DM, DM, DM);
        transpose_w_kernel<<<dim3(DM / 32, 2 * DM / 32), dim3(32, 8)>>>(
            gate_w, gwt, 2 * DM, DM);
    }

    // 6 fused projections (fp32 only where read: v,qb,kb,vb; bf16 only for q,k)
    {
        GB a = {};
        a.A0 = xb; a.K = DM; a.N = DM; a.KA0 = DM;
        a.maskF = 0b111100; a.maskB = 0b000011;
        const float* Bb[6] = {fq_b, fk_b, fv_b, bq_b, bk_b, bv_b};
        float* Of[6] = {unused, unused + (size_t)BHT*SEQ*HDIM, vf, qbf, kbf, vbf};
        for (int i = 0; i < 6; i++) {
            a.Bt6[i] = wt7 + (size_t)i * DM * DM;
            a.b6[i] = Bb[i];
            a.o6[i] = Of[i];
            a.ob6[i] = hb16 + (size_t)i * BHT * SEQ * HDIM;
        }
        gemm_bf<0><<<dim3(DM / BN, MROWS / BM, 6), 128, gemmSmem>>>(a);
    }

    // flash attention (Q,K bf16; V fp32)
    flash_fwd_kernel<<<dim3(SEQ / 128, BHT), 256, flashSmem>>>(
        hb16, hb16 + (size_t)BHT * SEQ * HDIM, vf, fwdf, fwdb);

    // window backward attention (tiled) + last-row mean
    bwd_attn_kernel<<<dim3(SEQ / 64, BHT), 256, bwdSmem>>>(qbf, kbf, vbf, bwdb);
    vb_mean_kernel<<<BHT, 256>>>(vbf, bwdb);

    // gate gemm: gpre = concat(fwdb,bwdb) @ gate_w + gate_b
    {
        GB a = {};
        a.A0 = fwdb; a.A1 = bwdb; a.Bt = gwt; a.bias = gate_b; a.Cf = gpre;
        a.N = DM; a.K = 2 * DM; a.KA0 = DM;
        gemm_bf<1><<<dim3(DM / BN, MROWS / BM, 1), 128, gemmSmem>>>(a);
    }
    gate_fuse_kernel<<<MROWS, 256>>>(gpre, fwdf, bwdb, gln_g, gln_b, bstr, fusedb);

    // output projection
    {
        GB a = {};
        a.A0 = fusedb; a.A1 = fusedb; a.Bt = wt7 + (size_t)6 * DM * DM;
        a.bias = out_b; a.Cf = out2;
        a.N = DM; a.K = DM; a.KA0 = DM;
        gemm_bf<1><<<dim3(DM / BN, MROWS / BM, 1), 128, gemmSmem>>>(a);
    }
    final_ln_kernel<<<MROWS, 256>>>(x, out2, ln_g, ln_b, (float*)d_out);
}

// round 12
// speedup vs baseline: 5.9178x; 1.0088x over previous
#include <cuda_runtime.h>
#include <cuda_bf16.h>
#include <math.h>

// Problem constants
#define SEQ   2048
#define NB    2
#define NH    16
#define HDIM  64
#define DM    1024
#define BHT   (NB*NH)        // 32 batch*heads
#define MROWS (NB*SEQ)       // 4096

// bf16 GEMM tile config: 128x128 block tile, 4 warps of 64x64, BK=32, 3-stage
#define BM 128
#define BN 128
#define BKH 32
#define LDAH 40              // bf16-element stride for 32-col tiles (80B rows)
#define LDBH 40
#define GSTAGE_A (BM*LDAH)   // shorts per A stage
#define GSTAGE_B (BN*LDBH)

// Flash attention
#define FQ  72               // bf16 stride for 64-col Q/K tiles (144B rows)
#define FLD 68               // fp32 stride for Vs/Ps (272B rows)

typedef __nv_bfloat16 bf;
typedef __nv_bfloat162 bf2;

// ---------------- scratch (device globals: allocation-free) ----------------
__device__ unsigned short g_xb [(size_t)MROWS*DM];          // x in bf16
__device__ unsigned short g_wt7[7][DM*DM];                  // fq,fk,fv,bq,bk,bv,out  ([N][K] bf16)
__device__ unsigned short g_gwt[2*DM*DM];                   // gate_w transposed [1024][2048]
__device__ unsigned short g_hb16[6][BHT*SEQ*HDIM];          // bf16 proj outputs (head layout)
__device__ float g_v [BHT*SEQ*HDIM];
__device__ float g_qb[BHT*SEQ*HDIM];
__device__ float g_kb[BHT*SEQ*HDIM];
__device__ float g_vb[BHT*SEQ*HDIM];
__device__ float g_unused[3][BHT*SEQ*HDIM];                 // fp32 slots for q,k (unwritten)
__device__ float g_fwd [(size_t)MROWS*DM];                  // fp32 fwd (for fuse)
__device__ unsigned short g_fwdb  [(size_t)MROWS*DM];       // bf16 fwd (gemm A)
__device__ unsigned short g_bwdb  [(size_t)MROWS*DM];       // bf16 bwd
__device__ unsigned short g_fusedb[(size_t)MROWS*DM];       // bf16 fused
__device__ float g_gpre[(size_t)MROWS*DM];
__device__ float g_out2[(size_t)MROWS*DM];

// ---------------- helpers ----------------
__device__ __forceinline__ void cpa8(unsigned dst, const void* src) {
    asm volatile("cp.async.ca.shared.global [%0], [%1], 8;" :: "r"(dst), "l"(src));
}
__device__ __forceinline__ void cp16(unsigned dst, const void* src) {
    asm volatile("cp.async.cg.shared.global [%0], [%1], 16;" :: "r"(dst), "l"(src));
}
__device__ __forceinline__ void cp_commit() { asm volatile("cp.async.commit_group;"); }
template<int N> __device__ __forceinline__ void cp_wait() {
    asm volatile("cp.async.wait_group %0;" :: "n"(N));
}

// bf16 m16n8k16, fp32 accumulate
__device__ __forceinline__ void mma16(float* c, const unsigned* a, unsigned b0, unsigned b1) {
    asm volatile(
        "mma.sync.aligned.m16n8k16.row.col.f32.bf16.bf16.f32 "
        "{%0,%1,%2,%3}, {%4,%5,%6,%7}, {%8,%9}, {%0,%1,%2,%3};"
        : "+f"(c[0]), "+f"(c[1]), "+f"(c[2]), "+f"(c[3])
        : "r"(a[0]), "r"(a[1]), "r"(a[2]), "r"(a[3]), "r"(b0), "r"(b1));
}
// tf32 m16n8k8 (flash PV)
__device__ __forceinline__ void mma8(float* c, const unsigned* a, unsigned b0, unsigned b1) {
    asm volatile(
        "mma.sync.aligned.m16n8k8.row.col.f32.tf32.tf32.f32 "
        "{%0,%1,%2,%3}, {%4,%5,%6,%7}, {%8,%9}, {%0,%1,%2,%3};"
        : "+f"(c[0]), "+f"(c[1]), "+f"(c[2]), "+f"(c[3])
        : "r"(a[0]), "r"(a[1]), "r"(a[2]), "r"(a[3]), "r"(b0), "r"(b1));
}

__device__ __forceinline__ float sigmoidf_(float x) { return 1.f / (1.f + __expf(-x)); }

// ---------------- conversion kernels ----------------
__global__ void cvt_x_kernel(const float4* __restrict__ x, bf2* __restrict__ xb) {
    int i = blockIdx.x * 256 + threadIdx.x;
    float4 t = x[i];
    xb[2 * i]     = __floats2bfloat162_rn(t.x, t.y);
    xb[2 * i + 1] = __floats2bfloat162_rn(t.z, t.w);
}

struct TW { const float* W[7]; unsigned short* Wt[7]; };

// batched: 7 square (1024x1024) fp32->bf16 transposes in one launch
__global__ void transpose_w7(TW t) {
    __shared__ float sm[32][33];
    const float* W = t.W[blockIdx.z];
    bf* out = (bf*)t.Wt[blockIdx.z];
    const int n0 = blockIdx.x * 32, k0 = blockIdx.y * 32;
    const int tx = threadIdx.x, ty = threadIdx.y;
#pragma unroll
    for (int j = 0; j < 32; j += 8)
        sm[ty + j][tx] = W[(size_t)(k0 + ty + j) * DM + n0 + tx];
    __syncthreads();
#pragma unroll
    for (int j = 0; j < 32; j += 8)
        out[(size_t)(n0 + ty + j) * DM + k0 + tx] = __float2bfloat16(sm[tx][ty + j]);
}

// generic K x N transpose (gate_w: 2048 x 1024)
__global__ void transpose_w_kernel(const float* __restrict__ W, unsigned short* __restrict__ Wt,
                                   int K, int N) {
    __shared__ float t[32][33];
    const int n0 = blockIdx.x * 32, k0 = blockIdx.y * 32;
    const int tx = threadIdx.x, ty = threadIdx.y;
#pragma unroll
    for (int j = 0; j < 32; j += 8)
        t[ty + j][tx] = W[(size_t)(k0 + ty + j) * N + n0 + tx];
    __syncthreads();
    bf* out = (bf*)Wt;
#pragma unroll
    for (int j = 0; j < 32; j += 8)
        out[(size_t)(n0 + ty + j) * K + k0 + tx] = __float2bfloat16(t[tx][ty + j]);
}

// ---------------- bf16 GEMM (3-stage cp.async pipeline, HMMA) ----------------
struct GB {
    const unsigned short *A0, *A1, *Bt;
    const float* bias;
    float* Cf;
    int N, K, KA0, maskF, maskB;
    const unsigned short* Bt6[6]; const float* b6[6];
    float* o6[6]; unsigned short* ob6[6];
};

template<int MODE>
__device__ __forceinline__ void issue_bf(
    const GB& g, const unsigned short* Ap, const unsigned short* Btp,
    unsigned short* As, unsigned short* Bs, int m0, int n0, int ks, int tid)
{
    unsigned aB = (unsigned)__cvta_generic_to_shared(As);
    unsigned bB = (unsigned)__cvta_generic_to_shared(Bs);
#pragma unroll
    for (int i = 0; i < 8; i++) {
        int e = i * 128 + tid, mm = e >> 3, c4 = (e & 7) * 4;
        const unsigned short* src;
        if (MODE == 0) src = Ap + (size_t)(m0 + mm) * g.K + ks + c4;
        else { int gk = ks + c4;
            src = (gk < g.KA0) ? g.A0 + (size_t)(m0 + mm) * g.KA0 + gk
                               : g.A1 + (size_t)(m0 + mm) * g.KA0 + (gk - g.KA0); }
        cpa8(aB + (unsigned)(mm * LDAH + c4) * 2u, src);
    }
#pragma unroll
    for (int i = 0; i < 8; i++) {
        int e = i * 128 + tid, nn = e >> 3, c4 = (e & 7) * 4;
        cpa8(bB + (unsigned)(nn * LDBH + c4) * 2u, Btp + (size_t)(n0 + nn) * g.K + ks + c4);
    }
}

template<int MODE>
__global__ void __launch_bounds__(128, 2) gemm_bf(GB g)
{
    extern __shared__ unsigned short gsm[];
    unsigned short* Asm = gsm;                       // 3 stages A
    unsigned short* Bsm = gsm + 3 * GSTAGE_A;        // 3 stages B

    const int nb = blockIdx.x, mb = blockIdx.y, z = blockIdx.z;
    const int m0 = mb * BM, n0 = nb * BN;

    const unsigned short *Ap, *Btp; const float* bias; float* Cf; unsigned short* Cb;
    if (MODE == 0) { Ap = g.A0; Btp = g.Bt6[z]; bias = g.b6[z]; Cf = g.o6[z]; Cb = g.ob6[z]; }
    else           { Ap = g.A0; Btp = g.Bt; bias = g.bias; Cf = g.Cf; Cb = nullptr; }

    const int tid = threadIdx.x, lane = tid & 31, warp = tid >> 5;
    const int wm = (warp & 1) * 64, wn = (warp >> 1) * 64;
    const int qrow = lane >> 2, qcol = lane & 3;

    float acc[4][8][4] = {};
    const int nIter = g.K / BKH;

    issue_bf<MODE>(g, Ap, Btp, Asm, Bsm, m0, n0, 0, tid);
    cp_commit();
    issue_bf<MODE>(g, Ap, Btp, Asm + GSTAGE_A, Bsm + GSTAGE_B, m0, n0, BKH, tid);
    cp_commit();

    int bi = 0;
    for (int it = 0; it < nIter; ++it) {
        if (it + 1 < nIter) cp_wait<1>(); else cp_wait<0>();
        __syncthreads();
        if (it + 2 < nIter) {
            int wb = bi + 2; if (wb >= 3) wb -= 3;
            issue_bf<MODE>(g, Ap, Btp, Asm + wb * GSTAGE_A, Bsm + wb * GSTAGE_B,
                           m0, n0, (it + 2) * BKH, tid);
            cp_commit();
        }
        const unsigned short* Ab = Asm + bi * GSTAGE_A;
        const unsigned short* Bb = Bsm + bi * GSTAGE_B;
#pragma unroll
        for (int kk = 0; kk < BKH; kk += 16) {
            unsigned a[4][4];
#pragma unroll
            for (int mf = 0; mf < 4; mf++) {
                int r = wm + mf * 16 + qrow, c = kk + 2 * qcol;
                a[mf][0] = *(const unsigned*)(Ab + r * LDAH + c);
                a[mf][1] = *(const unsigned*)(Ab + (r + 8) * LDAH + c);
                a[mf][2] = *(const unsigned*)(Ab + r * LDAH + c + 8);
                a[mf][3] = *(const unsigned*)(Ab + (r + 8) * LDAH + c + 8);
            }
#pragma unroll
            for (int nf = 0; nf < 8; nf++) {
                int n = wn + nf * 8 + qrow;
                unsigned b0 = *(const unsigned*)(Bb + n * LDBH + kk + 2 * qcol);
                unsigned b1 = *(const unsigned*)(Bb + n * LDBH + kk + 2 * qcol + 8);
#pragma unroll
                for (int mf = 0; mf < 4; mf++)
                    mma16(acc[mf][nf], a[mf], b0, b1);
            }
        }
        if (++bi == 3) bi = 0;
    }

    const bool doF = (MODE != 0) || ((g.maskF >> z) & 1);
    const bool doB = (MODE == 0) && ((g.maskB >> z) & 1);
#pragma unroll
    for (int mf = 0; mf < 4; mf++)
#pragma unroll
    for (int nf = 0; nf < 8; nf++)
#pragma unroll
    for (int t2 = 0; t2 < 2; t2++) {
        int r   = m0 + wm + mf * 16 + qrow + t2 * 8;
        int col = n0 + wn + nf * 8 + qcol * 2;
        float v0 = acc[mf][nf][t2 * 2] + bias[col];
        float v1 = acc[mf][nf][t2 * 2 + 1] + bias[col + 1];
        if (MODE == 0) {
            int b = r >> 11, s = r & (SEQ - 1), h = col >> 6, hd = col & 63;
            size_t off = ((size_t)(b * NH + h) * SEQ + s) * HDIM + hd;
            if (doF) *reinterpret_cast<float2*>(&Cf[off]) = make_float2(v0, v1);
            if (doB) *reinterpret_cast<bf2*>((bf*)Cb + off) = __floats2bfloat162_rn(v0, v1);
        } else {
            *reinterpret_cast<float2*>(&Cf[(size_t)r * g.N + col]) = make_float2(v0, v1);
        }
    }
}

// ---------------- fused causal flash attention ----------------
// bf16 QK^T, tf32 PV; double-buffered K/V tiles via cp.async.
// SMEM: Qs@0 (18432) | Ks[2]@18432 (2x9216) | Vs[2]@36864 (2x17408) | Ps@71680 (34816)
__global__ void __launch_bounds__(256, 2) flash_fwd_kernel(
    const unsigned short* __restrict__ Qg, const unsigned short* __restrict__ Kg,
    const float* __restrict__ Vg, float* __restrict__ fwdf, unsigned short* __restrict__ fwdb)
{
    extern __shared__ char sm_[];
    bf*    Qs = (bf*)sm_;
    float* Ps = (float*)(sm_ + 71680);
    const unsigned sbase = (unsigned)__cvta_generic_to_shared(sm_);

    const int m0 = blockIdx.x * 128;
    const int bh = blockIdx.y;
    const bf* Qp = (const bf*)Qg + (size_t)bh * SEQ * HDIM;
    const bf* Kp = (const bf*)Kg + (size_t)bh * SEQ * HDIM;
    const float* Vp = Vg + (size_t)bh * SEQ * HDIM;

    const int tid = threadIdx.x, lane = tid & 31, warp = tid >> 5;
    const int wm = warp * 16;
    const int qrow = lane >> 2, qcol = lane & 3;

    auto issue_kv = [&](int kt2, int buf) {
        unsigned kb = sbase + 18432u + (unsigned)buf * 9216u;
        unsigned vb = sbase + 36864u + (unsigned)buf * 17408u;
        const int nk = kt2 * 64;
#pragma unroll
        for (int i = 0; i < 2; i++) {
            int e = i * 256 + tid, r = e >> 3, c8 = (e & 7) * 8;
            cp16(kb + (unsigned)(r * FQ + c8) * 2u, Kp + (size_t)(nk + r) * HDIM + c8);
        }
#pragma unroll
        for (int i = 0; i < 4; i++) {
            int e = i * 256 + tid, r = e >> 4, c4 = (e & 15) * 4;
            cp16(vb + (unsigned)(r * FLD + c4) * 4u, Vp + (size_t)(nk + r) * HDIM + c4);
        }
    };

    // start tile-0 load immediately
    issue_kv(0, 0);
    cp_commit();

    // stage Q, lift fragments
#pragma unroll
    for (int i = 0; i < 4; i++) {
        int e = i * 256 + tid, r = e >> 3, c8 = (e & 7) * 8;
        *reinterpret_cast<uint4*>(Qs + r * FQ + c8) =
            *reinterpret_cast<const uint4*>(Qp + (size_t)(m0 + r) * HDIM + c8);
    }
    __syncthreads();

    unsigned qf[4][4];
#pragma unroll
    for (int ks = 0; ks < 4; ks++) {
        int r = wm + qrow, c = 16 * ks + 2 * qcol;
        qf[ks][0] = *(const unsigned*)(Qs + r * FQ + c);
        qf[ks][1] = *(const unsigned*)(Qs + (r + 8) * FQ + c);
        qf[ks][2] = *(const unsigned*)(Qs + r * FQ + c + 8);
        qf[ks][3] = *(const unsigned*)(Qs + (r + 8) * FQ + c + 8);
    }

    float o[8][4] = {};
    float mrow[2] = {-1e30f, -1e30f};
    float lrow[2] = {0.f, 0.f};

    const int ntiles = m0 / 64 + 2;
    for (int kt = 0; kt < ntiles; kt++) {
        const int n0k = kt * 64;
        const int buf = kt & 1;
        if (kt + 1 < ntiles) {
            issue_kv(kt + 1, buf ^ 1);
            cp_commit();
            cp_wait<1>();
        } else cp_wait<0>();
        __syncthreads();                    // tile kt data visible to all

        const bf*    Ks = (const bf*)(sm_ + 18432 + buf * 9216);
        const float* Vs = (const float*)(sm_ + 36864 + buf * 17408);

        // S = Q @ K^T (bf16)
        float s[8][4] = {};
#pragma unroll
        for (int ks = 0; ks < 4; ks++) {
#pragma unroll
            for (int nf = 0; nf < 8; nf++) {
                const bf* kb_ = Ks + (nf * 8 + qrow) * FQ + 16 * ks + 2 * qcol;
                unsigned b0 = *(const unsigned*)kb_;
                unsigned b1 = *(const unsigned*)(kb_ + 8);
                mma16(s[nf], qf[ks], b0, b1);
            }
        }

        // online softmax
        const bool domask = (n0k + 63 > m0);
#pragma unroll
        for (int t2 = 0; t2 < 2; t2++) {
            const int row = m0 + wm + qrow + t2 * 8;
            float tmax = -1e30f;
#pragma unroll
            for (int nf = 0; nf < 8; nf++)
#pragma unroll
            for (int j = 0; j < 2; j++) {
                float v = s[nf][t2 * 2 + j] * 0.125f;
                if (domask) {
                    int key = n0k + nf * 8 + qcol * 2 + j;
                    if (key > row) v = -1e30f;
                }
                s[nf][t2 * 2 + j] = v;
                tmax = fmaxf(tmax, v);
            }
            tmax = fmaxf(tmax, __shfl_xor_sync(0xffffffffu, tmax, 1));
            tmax = fmaxf(tmax, __shfl_xor_sync(0xffffffffu, tmax, 2));
            float mnew = fmaxf(mrow[t2], tmax);
            float alpha = __expf(mrow[t2] - mnew);
            float psum = 0.f;
#pragma unroll
            for (int nf = 0; nf < 8; nf++)
#pragma unroll
            for (int j = 0; j < 2; j++) {
                float p = __expf(s[nf][t2 * 2 + j] - mnew);
                s[nf][t2 * 2 + j] = p;
                psum += p;
            }
            psum += __shfl_xor_sync(0xffffffffu, psum, 1);
            psum += __shfl_xor_sync(0xffffffffu, psum, 2);
            lrow[t2] = lrow[t2] * alpha + psum;
            mrow[t2] = mnew;
#pragma unroll
            for (int nf = 0; nf < 8; nf++) {
                o[nf][t2 * 2]     *= alpha;
                o[nf][t2 * 2 + 1] *= alpha;
            }
        }

        // write P to smem
#pragma unroll
        for (int t2 = 0; t2 < 2; t2++) {
            int r = wm + qrow + t2 * 8;
#pragma unroll
            for (int nf = 0; nf < 8; nf++) {
                *reinterpret_cast<float2*>(&Ps[r * FLD + nf * 8 + qcol * 2]) =
                    make_float2(s[nf][t2 * 2], s[nf][t2 * 2 + 1]);
            }
        }
        __syncthreads();

        // O += P @ V (tf32)
#pragma unroll
        for (int ks = 0; ks < 8; ks++) {
            unsigned a[4];
            int r = wm + qrow, c = ks * 8 + qcol;
            a[0] = __float_as_uint(Ps[r * FLD + c]);
            a[1] = __float_as_uint(Ps[(r + 8) * FLD + c]);
            a[2] = __float_as_uint(Ps[r * FLD + c + 4]);
            a[3] = __float_as_uint(Ps[(r + 8) * FLD + c + 4]);
#pragma unroll
            for (int nf = 0; nf < 8; nf++) {
                unsigned b0 = __float_as_uint(Vs[(ks * 8 + qcol) * FLD + nf * 8 + qrow]);
                unsigned b1 = __float_as_uint(Vs[(ks * 8 + qcol + 4) * FLD + nf * 8 + qrow]);
                mma8(o[nf], a, b0, b1);
            }
        }
        __syncthreads();                    // protect buf reuse by kt+2's issue
    }

    const int b = bh >> 4, h = bh & 15;
#pragma unroll
    for (int t2 = 0; t2 < 2; t2++) {
        int srow = m0 + wm + qrow + t2 * 8;
        float inv = 1.f / lrow[t2];
        size_t base = ((size_t)(b * SEQ + srow)) * DM + h * HDIM;
#pragma unroll
        for (int nf = 0; nf < 8; nf++) {
            float v0 = o[nf][t2 * 2] * inv, v1 = o[nf][t2 * 2 + 1] * inv;
            *reinterpret_cast<float2*>(&fwdf[base + nf * 8 + qcol * 2]) = make_float2(v0, v1);
            *reinterpret_cast<bf2*>((bf*)fwdb + base + nf * 8 + qcol * 2) =
                __floats2bfloat162_rn(v0, v1);
        }
    }
}

// ---------------- tiled window-32 backward attention ----------------
__global__ void __launch_bounds__(256) bwd_attn_kernel(
    const float* __restrict__ Qb, const float* __restrict__ Kb,
    const float* __restrict__ Vb, unsigned short* __restrict__ bwdb)
{
    extern __shared__ float bsm[];
    float* Ks = bsm;              // 96 x 65
    float* Vs = bsm + 96 * 65;    // 96 x 65
    __shared__ float qsh[8][66];

    const int m0 = blockIdx.x * 64;
    const int bh = blockIdx.y;
    const float* Qp = Qb + (size_t)bh * SEQ * HDIM;
    const float* Kp = Kb + (size_t)bh * SEQ * HDIM;
    const float* Vp = Vb + (size_t)bh * SEQ * HDIM;
    const int b = bh >> 4, h = bh & 15;

    const int tid = threadIdx.x, wid = tid >> 5, lane = tid & 31;
    const int nrows = min(96, SEQ - 1 - m0);

    for (int i = tid; i < nrows * 16; i += 256) {
        int row = i >> 4, c4 = (i & 15) * 4;
        float4 tk = *reinterpret_cast<const float4*>(Kp + (size_t)(m0 + 1 + row) * HDIM + c4);
        float4 tv = *reinterpret_cast<const float4*>(Vp + (size_t)(m0 + 1 + row) * HDIM + c4);
        float* dk = Ks + row * 65 + c4; dk[0]=tk.x; dk[1]=tk.y; dk[2]=tk.z; dk[3]=tk.w;
        float* dv = Vs + row * 65 + c4; dv[0]=tv.x; dv[1]=tv.y; dv[2]=tv.z; dv[3]=tv.w;
    }
    __syncthreads();

#pragma unroll
    for (int t = 0; t < 8; t++) {
        const int m = m0 + wid * 8 + t;
        int w = SEQ - 1 - m; if (w > 32) w = 32;
        if (w <= 0) continue;

        __syncwarp();
        qsh[wid][lane]      = Qp[m * HDIM + lane];
        qsh[wid][lane + 32] = Qp[m * HDIM + lane + 32];
        __syncwarp();

        float sc = -1e30f;
        if (lane < w) {
            const float* kr = Ks + (m - m0 + lane) * 65;
            float a = 0.f;
#pragma unroll
            for (int d = 0; d < HDIM; d++) a += qsh[wid][d] * kr[d];
            sc = a * 0.125f;
        }
        float mx = sc;
#pragma unroll
        for (int o = 16; o > 0; o >>= 1) mx = fmaxf(mx, __shfl_xor_sync(0xffffffffu, mx, o));
        float e = __expf(sc - mx);
        float sum = e;
#pragma unroll
        for (int o = 16; o > 0; o >>= 1) sum += __shfl_xor_sync(0xffffffffu, sum, o);
        float p = e / sum;

        float o0 = 0.f, o1 = 0.f;
        for (int kk = 0; kk < w; kk++) {
            float pk = __shfl_sync(0xffffffffu, p, kk);
            const float* vr = Vs + (m - m0 + kk) * 65;
            o0 += pk * vr[lane];
            o1 += pk * vr[lane + 32];
        }
        bf* outp = (bf*)bwdb + ((size_t)(b * SEQ + m)) * DM + h * HDIM;
        outp[lane] = __float2bfloat16(o0);
        outp[lane + 32] = __float2bfloat16(o1);
    }
}

// mean of Vb over all S for the all-masked last row
__global__ void vb_mean_kernel(const float* __restrict__ Vb, unsigned short* __restrict__ bwdb) {
    __shared__ float part[4][64];
    const int bh = blockIdx.x, tid = threadIdx.x;
    const int col = tid & 63, grp = tid >> 6;
    const float* Vp = Vb + (size_t)bh * SEQ * HDIM;
    float s = 0.f;
    for (int r = grp; r < SEQ; r += 4) s += Vp[(size_t)r * HDIM + col];
    part[grp][col] = s;
    __syncthreads();
    if (tid < 64) {
        float m = (part[0][tid] + part[1][tid] + part[2][tid] + part[3][tid]) * (1.f / SEQ);
        int b = bh >> 4, h = bh & 15;
        ((bf*)bwdb)[((size_t)(b * SEQ + SEQ - 1)) * DM + h * HDIM + tid] = __float2bfloat16(m);
    }
}

// ---------------- gate LN + sigmoid + fusion ----------------
__global__ void gate_fuse_kernel(const float* __restrict__ gpre, const float* __restrict__ fwdf,
                                 const unsigned short* __restrict__ bwdb,
                                 const float* __restrict__ gg, const float* __restrict__ gb,
                                 const float* __restrict__ bstr, unsigned short* __restrict__ fusedb) {
    const int r = blockIdx.x, tid = threadIdx.x;
    const float* rowp = gpre + (size_t)r * DM;
    __shared__ float red[256];
    float v[4]; float s = 0.f, ss = 0.f;
#pragma unroll
    for (int i = 0; i < 4; i++) { v[i] = rowp[tid + i * 256]; s += v[i]; ss += v[i] * v[i]; }
    red[tid] = s; __syncthreads();
    for (int o = 128; o > 0; o >>= 1) { if (tid < o) red[tid] += red[tid + o]; __syncthreads(); }
    float mean = red[0] * (1.f / DM); __syncthreads();
    red[tid] = ss; __syncthreads();
    for (int o = 128; o > 0; o >>= 1) { if (tid < o) red[tid] += red[tid + o]; __syncthreads(); }
    float var = red[0] * (1.f / DM) - mean * mean;
    float rstd = rsqrtf(var + 1e-5f);
    float strength = 0.3f * sigmoidf_(bstr[0]);
#pragma unroll
    for (int i = 0; i < 4; i++) {
        int j = tid + i * 256;
        float g = sigmoidf_((v[i] - mean) * rstd * gg[j] + gb[j]);
        size_t o = (size_t)r * DM + j;
        float bw = __bfloat162float(((const bf*)bwdb)[o]);
        ((bf*)fusedb)[o] = __float2bfloat16(fwdf[o] + strength * g * bw);
    }
}

// ---------------- final residual + LayerNorm ----------------
__global__ void final_ln_kernel(const float* __restrict__ x, const float* __restrict__ o2,
                                const float* __restrict__ lg, const float* __restrict__ lb,
                                float* __restrict__ out) {
    const int r = blockIdx.x, tid = threadIdx.x;
    __shared__ float red[256];
    float v[4]; float s = 0.f, ss = 0.f;
#pragma unroll
    for (int i = 0; i < 4; i++) {
        size_t o = (size_t)r * DM + tid + i * 256;
        v[i] = x[o] + o2[o];
        s += v[i]; ss += v[i] * v[i];
    }
    red[tid] = s; __syncthreads();
    for (int o = 128; o > 0; o >>= 1) { if (tid < o) red[tid] += red[tid + o]; __syncthreads(); }
    float mean = red[0] * (1.f / DM); __syncthreads();
    red[tid] = ss; __syncthreads();
    for (int o = 128; o > 0; o >>= 1) { if (tid < o) red[tid] += red[tid + o]; __syncthreads(); }
    float var = red[0] * (1.f / DM) - mean * mean;
    float rstd = rsqrtf(var + 1e-5f);
#pragma unroll
    for (int i = 0; i < 4; i++) {
        int j = tid + i * 256;
        size_t o = (size_t)r * DM + j;
        out[o] = (v[i] - mean) * rstd * lg[j] + lb[j];
    }
}

// ---------------- launch ----------------
extern "C" void kernel_launch(void* const* d_in, const int* in_sizes, int n_in,
                              void* d_out, int out_size) {
    const float* x      = (const float*)d_in[0];
    const float* fq_w   = (const float*)d_in[1];
    const float* fq_b   = (const float*)d_in[2];
    const float* fk_w   = (const float*)d_in[3];
    const float* fk_b   = (const float*)d_in[4];
    const float* fv_w   = (const float*)d_in[5];
    const float* fv_b   = (const float*)d_in[6];
    const float* bq_w   = (const float*)d_in[7];
    const float* bq_b   = (const float*)d_in[8];
    const float* bk_w   = (const float*)d_in[9];
    const float* bk_b   = (const float*)d_in[10];
    const float* bv_w   = (const float*)d_in[11];
    const float* bv_b   = (const float*)d_in[12];
    const float* gate_w = (const float*)d_in[13];
    const float* gate_b = (const float*)d_in[14];
    const float* gln_g  = (const float*)d_in[15];
    const float* gln_b  = (const float*)d_in[16];
    const float* bstr   = (const float*)d_in[17];
    const float* out_w  = (const float*)d_in[18];
    const float* out_b  = (const float*)d_in[19];
    const float* ln_g   = (const float*)d_in[20];
    const float* ln_b   = (const float*)d_in[21];

    unsigned short *xb, *gwt, *fwdb, *bwdb, *fusedb, *wt7, *hb16;
    float *vf, *qbf, *kbf, *vbf, *unused, *fwdf, *gpre, *out2;
    cudaGetSymbolAddress((void**)&xb,     g_xb);
    cudaGetSymbolAddress((void**)&wt7,    g_wt7);
    cudaGetSymbolAddress((void**)&gwt,    g_gwt);
    cudaGetSymbolAddress((void**)&hb16,   g_hb16);
    cudaGetSymbolAddress((void**)&vf,     g_v);
    cudaGetSymbolAddress((void**)&qbf,    g_qb);
    cudaGetSymbolAddress((void**)&kbf,    g_kb);
    cudaGetSymbolAddress((void**)&vbf,    g_vb);
    cudaGetSymbolAddress((void**)&unused, g_unused);
    cudaGetSymbolAddress((void**)&fwdf,   g_fwd);
    cudaGetSymbolAddress((void**)&fwdb,   g_fwdb);
    cudaGetSymbolAddress((void**)&bwdb,   g_bwdb);
    cudaGetSymbolAddress((void**)&fusedb, g_fusedb);
    cudaGetSymbolAddress((void**)&gpre,   g_gpre);
    cudaGetSymbolAddress((void**)&out2,   g_out2);

    const int flashSmem = 106496;   // Qs 18432 + 2xKs 18432 + 2xVs 34816 + Ps 34816
    const int gemmSmem  = 3 * (GSTAGE_A + GSTAGE_B) * 2;   // 61440
    const int bwdSmem   = 2 * 96 * 65 * 4;                 // 49920
    cudaFuncSetAttribute(flash_fwd_kernel,
                         cudaFuncAttributeMaxDynamicSharedMemorySize, flashSmem);
    cudaFuncSetAttribute(gemm_bf<0>,
                         cudaFuncAttributeMaxDynamicSharedMemorySize, gemmSmem);
    cudaFuncSetAttribute(gemm_bf<1>,
                         cudaFuncAttributeMaxDynamicSharedMemorySize, gemmSmem);
    cudaFuncSetAttribute(bwd_attn_kernel,
                         cudaFuncAttributeMaxDynamicSharedMemorySize, bwdSmem);

    // conversions
    cvt_x_kernel<<<(MROWS * DM / 4) / 256, 256>>>((const float4*)x, (bf2*)xb);
    {
        TW t;
        const float* W[7] = {fq_w, fk_w, fv_w, bq_w, bk_w, bv_w, out_w};
        for (int i = 0; i < 7; i++) { t.W[i] = W[i]; t.Wt[i] = wt7 + (size_t)i * DM * DM; }
        transpose_w7<<<dim3(DM / 32, DM / 32, 7), dim3(32, 8)>>>(t);
        transpose_w_kernel<<<dim3(DM / 32, 2 * DM / 32), dim3(32, 8)>>>(gate_w, gwt, 2 * DM, DM);
    }

    // 6 fused projections (fp32 only where read: v,qb,kb,vb; bf16 only for q,k)
    {
        GB a = {};
        a.A0 = xb; a.K = DM; a.N = DM; a.KA0 = DM;
        a.maskF = 0b111100; a.maskB = 0b000011;
        const float* Bb[6] = {fq_b, fk_b, fv_b, bq_b, bk_b, bv_b};
        float* Of[6] = {unused, unused + (size_t)BHT*SEQ*HDIM, vf, qbf, kbf, vbf};
        for (int i = 0; i < 6; i++) {
            a.Bt6[i] = wt7 + (size_t)i * DM * DM;
            a.b6[i] = Bb[i];
            a.o6[i] = Of[i];
            a.ob6[i] = hb16 + (size_t)i * BHT * SEQ * HDIM;
        }
        gemm_bf<0><<<dim3(DM / BN, MROWS / BM, 6), 128, gemmSmem>>>(a);
    }

    // flash attention (Q,K bf16; V fp32)
    flash_fwd_kernel<<<dim3(SEQ / 128, BHT), 256, flashSmem>>>(
        hb16, hb16 + (size_t)BHT * SEQ * HDIM, vf, fwdf, fwdb);

    // window backward attention (tiled) + last-row mean
    bwd_attn_kernel<<<dim3(SEQ / 64, BHT), 256, bwdSmem>>>(qbf, kbf, vbf, bwdb);
    vb_mean_kernel<<<BHT, 256>>>(vbf, bwdb);

    // gate gemm: gpre = concat(fwdb,bwdb) @ gate_w + gate_b
    {
        GB a = {};
        a.A0 = fwdb; a.A1 = bwdb; a.Bt = gwt; a.bias = gate_b; a.Cf = gpre;
        a.N = DM; a.K = 2 * DM; a.KA0 = DM;
        gemm_bf<1><<<dim3(DM / BN, MROWS / BM, 1), 128, gemmSmem>>>(a);
    }
    gate_fuse_kernel<<<MROWS, 256>>>(gpre, fwdf, bwdb, gln_g, gln_b, bstr, fusedb);

    // output projection
    {
        GB a = {};
        a.A0 = fusedb; a.A1 = fusedb; a.Bt = wt7 + (size_t)6 * DM * DM;
        a.bias = out_b; a.Cf = out2;
        a.N = DM; a.K = DM; a.KA0 = DM;
        gemm_bf<1><<<dim3(DM / BN, MROWS / BM, 1), 128, gemmSmem>>>(a);
    }
    final_ln_kernel<<<MROWS, 256>>>(x, out2, ln_g, ln_b, (float*)d_out);
}

// round 13
// speedup vs baseline: 6.3869x; 1.0793x over previous
#include <cuda_runtime.h>
#include <cuda_bf16.h>
#include <math.h>

// Problem constants
#define SEQ   2048
#define NB    2
#define NH    16
#define HDIM  64
#define DM    1024
#define BHT   (NB*NH)        // 32 batch*heads
#define MROWS (NB*SEQ)       // 4096

// bf16 GEMM tile config: 128x128 block tile, 4 warps of 64x64, BK=32, 3-stage
#define BM 128
#define BN 128
#define BKH 32
#define LDAH 40              // bf16-element stride (80B rows; ldmatrix conflict-free)
#define LDBH 40
#define GSTAGE_A (BM*LDAH)
#define GSTAGE_B (BN*LDBH)

// Flash attention
#define FQ  72               // bf16 stride (144B rows; ldmatrix conflict-free)
#define FLD 68               // fp32 stride for Vs/Ps

typedef __nv_bfloat16 bf;
typedef __nv_bfloat162 bf2;

// ---------------- scratch (device globals: allocation-free) ----------------
__device__ unsigned short g_xb [(size_t)MROWS*DM];
__device__ unsigned short g_wt7[7][DM*DM];                  // [N][K] bf16
__device__ unsigned short g_gwt[2*DM*DM];                   // gate_w transposed
__device__ unsigned short g_hb16[6][BHT*SEQ*HDIM];          // bf16 proj outputs
__device__ float g_v [BHT*SEQ*HDIM];
__device__ float g_qb[BHT*SEQ*HDIM];
__device__ float g_kb[BHT*SEQ*HDIM];
__device__ float g_vb[BHT*SEQ*HDIM];
__device__ float g_unused[3][BHT*SEQ*HDIM];
__device__ float g_fwd [(size_t)MROWS*DM];
__device__ unsigned short g_fwdb  [(size_t)MROWS*DM];
__device__ unsigned short g_bwdb  [(size_t)MROWS*DM];
__device__ unsigned short g_fusedb[(size_t)MROWS*DM];
__device__ float g_gpre[(size_t)MROWS*DM];
__device__ float g_out2[(size_t)MROWS*DM];

// ---------------- helpers ----------------
__device__ __forceinline__ void cpa8(unsigned dst, const void* src) {
    asm volatile("cp.async.ca.shared.global [%0], [%1], 8;" :: "r"(dst), "l"(src));
}
__device__ __forceinline__ void cp16(unsigned dst, const void* src) {
    asm volatile("cp.async.cg.shared.global [%0], [%1], 16;" :: "r"(dst), "l"(src));
}
__device__ __forceinline__ void cp_commit() { asm volatile("cp.async.commit_group;"); }
template<int N> __device__ __forceinline__ void cp_wait() {
    asm volatile("cp.async.wait_group %0;" :: "n"(N));
}
__device__ __forceinline__ void ldm_x4(unsigned* r, unsigned addr) {
    asm volatile("ldmatrix.sync.aligned.m8n8.x4.shared.b16 {%0,%1,%2,%3}, [%4];"
        : "=r"(r[0]), "=r"(r[1]), "=r"(r[2]), "=r"(r[3]) : "r"(addr));
}

// bf16 m16n8k16, fp32 accumulate
__device__ __forceinline__ void mma16(float* c, const unsigned* a, unsigned b0, unsigned b1) {
    asm volatile(
        "mma.sync.aligned.m16n8k16.row.col.f32.bf16.bf16.f32 "
        "{%0,%1,%2,%3}, {%4,%5,%6,%7}, {%8,%9}, {%0,%1,%2,%3};"
        : "+f"(c[0]), "+f"(c[1]), "+f"(c[2]), "+f"(c[3])
        : "r"(a[0]), "r"(a[1]), "r"(a[2]), "r"(a[3]), "r"(b0), "r"(b1));
}
// tf32 m16n8k8 (flash PV)
__device__ __forceinline__ void mma8(float* c, const unsigned* a, unsigned b0, unsigned b1) {
    asm volatile(
        "mma.sync.aligned.m16n8k8.row.col.f32.tf32.tf32.f32 "
        "{%0,%1,%2,%3}, {%4,%5,%6,%7}, {%8,%9}, {%0,%1,%2,%3};"
        : "+f"(c[0]), "+f"(c[1]), "+f"(c[2]), "+f"(c[3])
        : "r"(a[0]), "r"(a[1]), "r"(a[2]), "r"(a[3]), "r"(b0), "r"(b1));
}

__device__ __forceinline__ float sigmoidf_(float x) { return 1.f / (1.f + __expf(-x)); }

// ---------------- conversion kernels ----------------
__global__ void cvt_x_kernel(const float4* __restrict__ x, bf2* __restrict__ xb) {
    int i = blockIdx.x * 256 + threadIdx.x;
    float4 t = x[i];
    xb[2 * i]     = __floats2bfloat162_rn(t.x, t.y);
    xb[2 * i + 1] = __floats2bfloat162_rn(t.z, t.w);
}

struct TW { const float* W[7]; unsigned short* Wt[7]; };

__global__ void transpose_w7(TW t) {
    __shared__ float sm[32][33];
    const float* W = t.W[blockIdx.z];
    bf* out = (bf*)t.Wt[blockIdx.z];
    const int n0 = blockIdx.x * 32, k0 = blockIdx.y * 32;
    const int tx = threadIdx.x, ty = threadIdx.y;
#pragma unroll
    for (int j = 0; j < 32; j += 8)
        sm[ty + j][tx] = W[(size_t)(k0 + ty + j) * DM + n0 + tx];
    __syncthreads();
#pragma unroll
    for (int j = 0; j < 32; j += 8)
        out[(size_t)(n0 + ty + j) * DM + k0 + tx] = __float2bfloat16(sm[tx][ty + j]);
}

__global__ void transpose_w_kernel(const float* __restrict__ W, unsigned short* __restrict__ Wt,
                                   int K, int N) {
    __shared__ float t[32][33];
    const int n0 = blockIdx.x * 32, k0 = blockIdx.y * 32;
    const int tx = threadIdx.x, ty = threadIdx.y;
#pragma unroll
    for (int j = 0; j < 32; j += 8)
        t[ty + j][tx] = W[(size_t)(k0 + ty + j) * N + n0 + tx];
    __syncthreads();
    bf* out = (bf*)Wt;
#pragma unroll
    for (int j = 0; j < 32; j += 8)
        out[(size_t)(n0 + ty + j) * K + k0 + tx] = __float2bfloat16(t[tx][ty + j]);
}

// ---------------- bf16 GEMM (3-stage cp.async, ldmatrix feeding) ----------------
struct GB {
    const unsigned short *A0, *A1, *Bt;
    const float* bias;
    float* Cf;
    int N, K, KA0, maskF, maskB;
    const unsigned short* Bt6[6]; const float* b6[6];
    float* o6[6]; unsigned short* ob6[6];
};

template<int MODE>
__device__ __forceinline__ void issue_bf(
    const GB& g, const unsigned short* Ap, const unsigned short* Btp,
    unsigned short* As, unsigned short* Bs, int m0, int n0, int ks, int tid)
{
    unsigned aB = (unsigned)__cvta_generic_to_shared(As);
    unsigned bB = (unsigned)__cvta_generic_to_shared(Bs);
#pragma unroll
    for (int i = 0; i < 8; i++) {
        int e = i * 128 + tid, mm = e >> 3, c4 = (e & 7) * 4;
        const unsigned short* src;
        if (MODE == 0) src = Ap + (size_t)(m0 + mm) * g.K + ks + c4;
        else { int gk = ks + c4;
            src = (gk < g.KA0) ? g.A0 + (size_t)(m0 + mm) * g.KA0 + gk
                               : g.A1 + (size_t)(m0 + mm) * g.KA0 + (gk - g.KA0); }
        cpa8(aB + (unsigned)(mm * LDAH + c4) * 2u, src);
    }
#pragma unroll
    for (int i = 0; i < 8; i++) {
        int e = i * 128 + tid, nn = e >> 3, c4 = (e & 7) * 4;
        cpa8(bB + (unsigned)(nn * LDBH + c4) * 2u, Btp + (size_t)(n0 + nn) * g.K + ks + c4);
    }
}

template<int MODE>
__global__ void __launch_bounds__(128, 2) gemm_bf(GB g)
{
    extern __shared__ unsigned short gsm[];
    const unsigned gsmU = (unsigned)__cvta_generic_to_shared(gsm);

    const int nb = blockIdx.x, mb = blockIdx.y, z = blockIdx.z;
    const int m0 = mb * BM, n0 = nb * BN;

    const unsigned short *Ap, *Btp; const float* bias; float* Cf; unsigned short* Cb;
    if (MODE == 0) { Ap = g.A0; Btp = g.Bt6[z]; bias = g.b6[z]; Cf = g.o6[z]; Cb = g.ob6[z]; }
    else           { Ap = g.A0; Btp = g.Bt; bias = g.bias; Cf = g.Cf; Cb = nullptr; }

    const int tid = threadIdx.x, lane = tid & 31, warp = tid >> 5;
    const int wm = (warp & 1) * 64, wn = (warp >> 1) * 64;
    const int qrow = lane >> 2, qcol = lane & 3;
    const int la15 = lane & 15, la16 = lane >> 4;       // A ldmatrix addressing
    const int bg = lane >> 3, br = lane & 7;            // B ldmatrix addressing

    // loop-invariant ldmatrix element offsets (x2 bytes applied at use)
    const unsigned aOff = (unsigned)((wm + la15) * LDAH + la16 * 8);
    const unsigned bOff = (unsigned)((wn + ((bg >> 1) * 8) + br) * LDBH + (bg & 1) * 8);

    float acc[4][8][4] = {};
    const int nIter = g.K / BKH;

    issue_bf<MODE>(g, Ap, Btp, gsm, gsm + 3 * GSTAGE_A, m0, n0, 0, tid);
    cp_commit();
    issue_bf<MODE>(g, Ap, Btp, gsm + GSTAGE_A, gsm + 3 * GSTAGE_A + GSTAGE_B, m0, n0, BKH, tid);
    cp_commit();

    int bi = 0;
    for (int it = 0; it < nIter; ++it) {
        if (it + 1 < nIter) cp_wait<1>(); else cp_wait<0>();
        __syncthreads();
        if (it + 2 < nIter) {
            int wb = bi + 2; if (wb >= 3) wb -= 3;
            issue_bf<MODE>(g, Ap, Btp, gsm + wb * GSTAGE_A,
                           gsm + 3 * GSTAGE_A + wb * GSTAGE_B, m0, n0, (it + 2) * BKH, tid);
            cp_commit();
        }
        const unsigned aSt = gsmU + (unsigned)(bi * GSTAGE_A) * 2u;
        const unsigned bSt = gsmU + (unsigned)(3 * GSTAGE_A + bi * GSTAGE_B) * 2u;
#pragma unroll
        for (int kk = 0; kk < BKH; kk += 16) {
            unsigned a[4][4];
#pragma unroll
            for (int mf = 0; mf < 4; mf++)
                ldm_x4(a[mf], aSt + (aOff + (unsigned)(mf * 16 * LDAH + kk)) * 2u);
            unsigned bfr[4][4];
#pragma unroll
            for (int nfp = 0; nfp < 4; nfp++)
                ldm_x4(bfr[nfp], bSt + (bOff + (unsigned)(nfp * 16 * LDBH + kk)) * 2u);
#pragma unroll
            for (int nf = 0; nf < 8; nf++) {
                unsigned b0 = bfr[nf >> 1][(nf & 1) * 2];
                unsigned b1 = bfr[nf >> 1][(nf & 1) * 2 + 1];
#pragma unroll
                for (int mf = 0; mf < 4; mf++)
                    mma16(acc[mf][nf], a[mf], b0, b1);
            }
        }
        if (++bi == 3) bi = 0;
    }

    const bool doF = (MODE != 0) || ((g.maskF >> z) & 1);
    const bool doB = (MODE == 0) && ((g.maskB >> z) & 1);
#pragma unroll
    for (int mf = 0; mf < 4; mf++)
#pragma unroll
    for (int nf = 0; nf < 8; nf++)
#pragma unroll
    for (int t2 = 0; t2 < 2; t2++) {
        int r   = m0 + wm + mf * 16 + qrow + t2 * 8;
        int col = n0 + wn + nf * 8 + qcol * 2;
        float v0 = acc[mf][nf][t2 * 2] + bias[col];
        float v1 = acc[mf][nf][t2 * 2 + 1] + bias[col + 1];
        if (MODE == 0) {
            int b = r >> 11, s = r & (SEQ - 1), h = col >> 6, hd = col & 63;
            size_t off = ((size_t)(b * NH + h) * SEQ + s) * HDIM + hd;
            if (doF) *reinterpret_cast<float2*>(&Cf[off]) = make_float2(v0, v1);
            if (doB) *reinterpret_cast<bf2*>((bf*)Cb + off) = __floats2bfloat162_rn(v0, v1);
        } else {
            *reinterpret_cast<float2*>(&Cf[(size_t)r * g.N + col]) = make_float2(v0, v1);
        }
    }
}

// ---------------- fused causal flash attention ----------------
// bf16 QK^T (ldmatrix-fed), tf32 PV; double-buffered K/V via cp.async.
// SMEM: Qs@0 (18432) | Ks[2]@18432 (2x9216) | Vs[2]@36864 (2x17408) | Ps@71680 (34816)
__global__ void __launch_bounds__(256, 2) flash_fwd_kernel(
    const unsigned short* __restrict__ Qg, const unsigned short* __restrict__ Kg,
    const float* __restrict__ Vg, float* __restrict__ fwdf, unsigned short* __restrict__ fwdb)
{
    extern __shared__ char sm_[];
    bf*    Qs = (bf*)sm_;
    float* Ps = (float*)(sm_ + 71680);
    const unsigned sbase = (unsigned)__cvta_generic_to_shared(sm_);

    const int m0 = blockIdx.x * 128;
    const int bh = blockIdx.y;
    const bf* Qp = (const bf*)Qg + (size_t)bh * SEQ * HDIM;
    const bf* Kp = (const bf*)Kg + (size_t)bh * SEQ * HDIM;
    const float* Vp = Vg + (size_t)bh * SEQ * HDIM;

    const int tid = threadIdx.x, lane = tid & 31, warp = tid >> 5;
    const int wm = warp * 16;
    const int qrow = lane >> 2, qcol = lane & 3;
    const int bg = lane >> 3, br = lane & 7;
    const unsigned kOff = (unsigned)((((bg >> 1) * 8) + br) * FQ + (bg & 1) * 8);

    auto issue_kv = [&](int kt2, int buf) {
        unsigned kb = sbase + 18432u + (unsigned)buf * 9216u;
        unsigned vb = sbase + 36864u + (unsigned)buf * 17408u;
        const int nk = kt2 * 64;
#pragma unroll
        for (int i = 0; i < 2; i++) {
            int e = i * 256 + tid, r = e >> 3, c8 = (e & 7) * 8;
            cp16(kb + (unsigned)(r * FQ + c8) * 2u, Kp + (size_t)(nk + r) * HDIM + c8);
        }
#pragma unroll
        for (int i = 0; i < 4; i++) {
            int e = i * 256 + tid, r = e >> 4, c4 = (e & 15) * 4;
            cp16(vb + (unsigned)(r * FLD + c4) * 4u, Vp + (size_t)(nk + r) * HDIM + c4);
        }
    };

    issue_kv(0, 0);
    cp_commit();

#pragma unroll
    for (int i = 0; i < 4; i++) {
        int e = i * 256 + tid, r = e >> 3, c8 = (e & 7) * 8;
        *reinterpret_cast<uint4*>(Qs + r * FQ + c8) =
            *reinterpret_cast<const uint4*>(Qp + (size_t)(m0 + r) * HDIM + c8);
    }
    __syncthreads();

    unsigned qf[4][4];
#pragma unroll
    for (int ks = 0; ks < 4; ks++) {
        int r = wm + qrow, c = 16 * ks + 2 * qcol;
        qf[ks][0] = *(const unsigned*)(Qs + r * FQ + c);
        qf[ks][1] = *(const unsigned*)(Qs + (r + 8) * FQ + c);
        qf[ks][2] = *(const unsigned*)(Qs + r * FQ + c + 8);
        qf[ks][3] = *(const unsigned*)(Qs + (r + 8) * FQ + c + 8);
    }

    float o[8][4] = {};
    float mrow[2] = {-1e30f, -1e30f};
    float lrow[2] = {0.f, 0.f};

    const int ntiles = m0 / 64 + 2;
    for (int kt = 0; kt < ntiles; kt++) {
        const int n0k = kt * 64;
        const int buf = kt & 1;
        if (kt + 1 < ntiles) {
            issue_kv(kt + 1, buf ^ 1);
            cp_commit();
            cp_wait<1>();
        } else cp_wait<0>();
        __syncthreads();

        const unsigned kSt = sbase + 18432u + (unsigned)buf * 9216u;
        const float* Vs = (const float*)(sm_ + 36864 + buf * 17408);

        // S = Q @ K^T (bf16, ldmatrix-fed B fragments)
        float s[8][4] = {};
#pragma unroll
        for (int ks = 0; ks < 4; ks++) {
            unsigned bfr[4][4];
#pragma unroll
            for (int nfp = 0; nfp < 4; nfp++)
                ldm_x4(bfr[nfp], kSt + (kOff + (unsigned)(nfp * 16 * FQ + 16 * ks)) * 2u);
#pragma unroll
            for (int nf = 0; nf < 8; nf++) {
                unsigned b0 = bfr[nf >> 1][(nf & 1) * 2];
                unsigned b1 = bfr[nf >> 1][(nf & 1) * 2 + 1];
                mma16(s[nf], qf[ks], b0, b1);
            }
        }

        // online softmax
        const bool domask = (n0k + 63 > m0);
#pragma unroll
        for (int t2 = 0; t2 < 2; t2++) {
            const int row = m0 + wm + qrow + t2 * 8;
            float tmax = -1e30f;
#pragma unroll
            for (int nf = 0; nf < 8; nf++)
#pragma unroll
            for (int j = 0; j < 2; j++) {
                float v = s[nf][t2 * 2 + j] * 0.125f;
                if (domask) {
                    int key = n0k + nf * 8 + qcol * 2 + j;
                    if (key > row) v = -1e30f;
                }
                s[nf][t2 * 2 + j] = v;
                tmax = fmaxf(tmax, v);
            }
            tmax = fmaxf(tmax, __shfl_xor_sync(0xffffffffu, tmax, 1));
            tmax = fmaxf(tmax, __shfl_xor_sync(0xffffffffu, tmax, 2));
            float mnew = fmaxf(mrow[t2], tmax);
            float alpha = __expf(mrow[t2] - mnew);
            float psum = 0.f;
#pragma unroll
            for (int nf = 0; nf < 8; nf++)
#pragma unroll
            for (int j = 0; j < 2; j++) {
                float p = __expf(s[nf][t2 * 2 + j] - mnew);
                s[nf][t2 * 2 + j] = p;
                psum += p;
            }
            psum += __shfl_xor_sync(0xffffffffu, psum, 1);
            psum += __shfl_xor_sync(0xffffffffu, psum, 2);
            lrow[t2] = lrow[t2] * alpha + psum;
            mrow[t2] = mnew;
#pragma unroll
            for (int nf = 0; nf < 8; nf++) {
                o[nf][t2 * 2]     *= alpha;
                o[nf][t2 * 2 + 1] *= alpha;
            }
        }

        // write P to smem
#pragma unroll
        for (int t2 = 0; t2 < 2; t2++) {
            int r = wm + qrow + t2 * 8;
#pragma unroll
            for (int nf = 0; nf < 8; nf++) {
                *reinterpret_cast<float2*>(&Ps[r * FLD + nf * 8 + qcol * 2]) =
                    make_float2(s[nf][t2 * 2], s[nf][t2 * 2 + 1]);
            }
        }
        __syncthreads();

        // O += P @ V (tf32)
#pragma unroll
        for (int ks = 0; ks < 8; ks++) {
            unsigned a[4];
            int r = wm + qrow, c = ks * 8 + qcol;
            a[0] = __float_as_uint(Ps[r * FLD + c]);
            a[1] = __float_as_uint(Ps[(r + 8) * FLD + c]);
            a[2] = __float_as_uint(Ps[r * FLD + c + 4]);
            a[3] = __float_as_uint(Ps[(r + 8) * FLD + c + 4]);
#pragma unroll
            for (int nf = 0; nf < 8; nf++) {
                unsigned b0 = __float_as_uint(Vs[(ks * 8 + qcol) * FLD + nf * 8 + qrow]);
                unsigned b1 = __float_as_uint(Vs[(ks * 8 + qcol + 4) * FLD + nf * 8 + qrow]);
                mma8(o[nf], a, b0, b1);
            }
        }
        __syncthreads();
    }

    const int b = bh >> 4, h = bh & 15;
#pragma unroll
    for (int t2 = 0; t2 < 2; t2++) {
        int srow = m0 + wm + qrow + t2 * 8;
        float inv = 1.f / lrow[t2];
        size_t base = ((size_t)(b * SEQ + srow)) * DM + h * HDIM;
#pragma unroll
        for (int nf = 0; nf < 8; nf++) {
            float v0 = o[nf][t2 * 2] * inv, v1 = o[nf][t2 * 2 + 1] * inv;
            *reinterpret_cast<float2*>(&fwdf[base + nf * 8 + qcol * 2]) = make_float2(v0, v1);
            *reinterpret_cast<bf2*>((bf*)fwdb + base + nf * 8 + qcol * 2) =
                __floats2bfloat162_rn(v0, v1);
        }
    }
}

// ---------------- tiled window-32 backward attention ----------------
__global__ void __launch_bounds__(256) bwd_attn_kernel(
    const float* __restrict__ Qb, const float* __restrict__ Kb,
    const float* __restrict__ Vb, unsigned short* __restrict__ bwdb)
{
    extern __shared__ float bsm[];
    float* Ks = bsm;              // 96 x 65
    float* Vs = bsm + 96 * 65;    // 96 x 65
    __shared__ float qsh[8][66];

    const int m0 = blockIdx.x * 64;
    const int bh = blockIdx.y;
    const float* Qp = Qb + (size_t)bh * SEQ * HDIM;
    const float* Kp = Kb + (size_t)bh * SEQ * HDIM;
    const float* Vp = Vb + (size_t)bh * SEQ * HDIM;
    const int b = bh >> 4, h = bh & 15;

    const int tid = threadIdx.x, wid = tid >> 5, lane = tid & 31;
    const int nrows = min(96, SEQ - 1 - m0);

    for (int i = tid; i < nrows * 16; i += 256) {
        int row = i >> 4, c4 = (i & 15) * 4;
        float4 tk = *reinterpret_cast<const float4*>(Kp + (size_t)(m0 + 1 + row) * HDIM + c4);
        float4 tv = *reinterpret_cast<const float4*>(Vp + (size_t)(m0 + 1 + row) * HDIM + c4);
        float* dk = Ks + row * 65 + c4; dk[0]=tk.x; dk[1]=tk.y; dk[2]=tk.z; dk[3]=tk.w;
        float* dv = Vs + row * 65 + c4; dv[0]=tv.x; dv[1]=tv.y; dv[2]=tv.z; dv[3]=tv.w;
    }
    __syncthreads();

#pragma unroll
    for (int t = 0; t < 8; t++) {
        const int m = m0 + wid * 8 + t;
        int w = SEQ - 1 - m; if (w > 32) w = 32;
        if (w <= 0) continue;

        __syncwarp();
        qsh[wid][lane]      = Qp[m * HDIM + lane];
        qsh[wid][lane + 32] = Qp[m * HDIM + lane + 32];
        __syncwarp();

        float sc = -1e30f;
        if (lane < w) {
            const float* kr = Ks + (m - m0 + lane) * 65;
            float a = 0.f;
#pragma unroll
            for (int d = 0; d < HDIM; d++) a += qsh[wid][d] * kr[d];
            sc = a * 0.125f;
        }
        float mx = sc;
#pragma unroll
        for (int o = 16; o > 0; o >>= 1) mx = fmaxf(mx, __shfl_xor_sync(0xffffffffu, mx, o));
        float e = __expf(sc - mx);
        float sum = e;
#pragma unroll
        for (int o = 16; o > 0; o >>= 1) sum += __shfl_xor_sync(0xffffffffu, sum, o);
        float p = e / sum;

        float o0 = 0.f, o1 = 0.f;
        for (int kk = 0; kk < w; kk++) {
            float pk = __shfl_sync(0xffffffffu, p, kk);
            const float* vr = Vs + (m - m0 + kk) * 65;
            o0 += pk * vr[lane];
            o1 += pk * vr[lane + 32];
        }
        bf* outp = (bf*)bwdb + ((size_t)(b * SEQ + m)) * DM + h * HDIM;
        outp[lane] = __float2bfloat16(o0);
        outp[lane + 32] = __float2bfloat16(o1);
    }
}

// mean of Vb over all S for the all-masked last row
__global__ void vb_mean_kernel(const float* __restrict__ Vb, unsigned short* __restrict__ bwdb) {
    __shared__ float part[4][64];
    const int bh = blockIdx.x, tid = threadIdx.x;
    const int col = tid & 63, grp = tid >> 6;
    const float* Vp = Vb + (size_t)bh * SEQ * HDIM;
    float s = 0.f;
    for (int r = grp; r < SEQ; r += 4) s += Vp[(size_t)r * HDIM + col];
    part[grp][col] = s;
    __syncthreads();
    if (tid < 64) {
        float m = (part[0][tid] + part[1][tid] + part[2][tid] + part[3][tid]) * (1.f / SEQ);
        int b = bh >> 4, h = bh & 15;
        ((bf*)bwdb)[((size_t)(b * SEQ + SEQ - 1)) * DM + h * HDIM + tid] = __float2bfloat16(m);
    }
}

// ---------------- gate LN + sigmoid + fusion ----------------
__global__ void gate_fuse_kernel(const float* __restrict__ gpre, const float* __restrict__ fwdf,
                                 const unsigned short* __restrict__ bwdb,
                                 const float* __restrict__ gg, const float* __restrict__ gb,
                                 const float* __restrict__ bstr, unsigned short* __restrict__ fusedb) {
    const int r = blockIdx.x, tid = threadIdx.x;
    const float* rowp = gpre + (size_t)r * DM;
    __shared__ float red[256];
    float v[4]; float s = 0.f, ss = 0.f;
#pragma unroll
    for (int i = 0; i < 4; i++) { v[i] = rowp[tid + i * 256]; s += v[i]; ss += v[i] * v[i]; }
    red[tid] = s; __syncthreads();
    for (int o = 128; o > 0; o >>= 1) { if (tid < o) red[tid] += red[tid + o]; __syncthreads(); }
    float mean = red[0] * (1.f / DM); __syncthreads();
    red[tid] = ss; __syncthreads();
    for (int o = 128; o > 0; o >>= 1) { if (tid < o) red[tid] += red[tid + o]; __syncthreads(); }
    float var = red[0] * (1.f / DM) - mean * mean;
    float rstd = rsqrtf(var + 1e-5f);
    float strength = 0.3f * sigmoidf_(bstr[0]);
#pragma unroll
    for (int i = 0; i < 4; i++) {
        int j = tid + i * 256;
        float g = sigmoidf_((v[i] - mean) * rstd * gg[j] + gb[j]);
        size_t o = (size_t)r * DM + j;
        float bw = __bfloat162float(((const bf*)bwdb)[o]);
        ((bf*)fusedb)[o] = __float2bfloat16(fwdf[o] + strength * g * bw);
    }
}

// ---------------- final residual + LayerNorm ----------------
__global__ void final_ln_kernel(const float* __restrict__ x, const float* __restrict__ o2,
                                const float* __restrict__ lg, const float* __restrict__ lb,
                                float* __restrict__ out) {
    const int r = blockIdx.x, tid = threadIdx.x;
    __shared__ float red[256];
    float v[4]; float s = 0.f, ss = 0.f;
#pragma unroll
    for (int i = 0; i < 4; i++) {
        size_t o = (size_t)r * DM + tid + i * 256;
        v[i] = x[o] + o2[o];
        s += v[i]; ss += v[i] * v[i];
    }
    red[tid] = s; __syncthreads();
    for (int o = 128; o > 0; o >>= 1) { if (tid < o) red[tid] += red[tid + o]; __syncthreads(); }
    float mean = red[0] * (1.f / DM); __syncthreads();
    red[tid] = ss; __syncthreads();
    for (int o = 128; o > 0; o >>= 1) { if (tid < o) red[tid] += red[tid + o]; __syncthreads(); }
    float var = red[0] * (1.f / DM) - mean * mean;
    float rstd = rsqrtf(var + 1e-5f);
#pragma unroll
    for (int i = 0; i < 4; i++) {
        int j = tid + i * 256;
        size_t o = (size_t)r * DM + j;
        out[o] = (v[i] - mean) * rstd * lg[j] + lb[j];
    }
}

// ---------------- launch ----------------
extern "C" void kernel_launch(void* const* d_in, const int* in_sizes, int n_in,
                              void* d_out, int out_size) {
    const float* x      = (const float*)d_in[0];
    const float* fq_w   = (const float*)d_in[1];
    const float* fq_b   = (const float*)d_in[2];
    const float* fk_w   = (const float*)d_in[3];
    const float* fk_b   = (const float*)d_in[4];
    const float* fv_w   = (const float*)d_in[5];
    const float* fv_b   = (const float*)d_in[6];
    const float* bq_w   = (const float*)d_in[7];
    const float* bq_b   = (const float*)d_in[8];
    const float* bk_w   = (const float*)d_in[9];
    const float* bk_b   = (const float*)d_in[10];
    const float* bv_w   = (const float*)d_in[11];
    const float* bv_b   = (const float*)d_in[12];
    const float* gate_w = (const float*)d_in[13];
    const float* gate_b = (const float*)d_in[14];
    const float* gln_g  = (const float*)d_in[15];
    const float* gln_b  = (const float*)d_in[16];
    const float* bstr   = (const float*)d_in[17];
    const float* out_w  = (const float*)d_in[18];
    const float* out_b  = (const float*)d_in[19];
    const float* ln_g   = (const float*)d_in[20];
    const float* ln_b   = (const float*)d_in[21];

    unsigned short *xb, *gwt, *fwdb, *bwdb, *fusedb, *wt7, *hb16;
    float *vf, *qbf, *kbf, *vbf, *unused, *fwdf, *gpre, *out2;
    cudaGetSymbolAddress((void**)&xb,     g_xb);
    cudaGetSymbolAddress((void**)&wt7,    g_wt7);
    cudaGetSymbolAddress((void**)&gwt,    g_gwt);
    cudaGetSymbolAddress((void**)&hb16,   g_hb16);
    cudaGetSymbolAddress((void**)&vf,     g_v);
    cudaGetSymbolAddress((void**)&qbf,    g_qb);
    cudaGetSymbolAddress((void**)&kbf,    g_kb);
    cudaGetSymbolAddress((void**)&vbf,    g_vb);
    cudaGetSymbolAddress((void**)&unused, g_unused);
    cudaGetSymbolAddress((void**)&fwdf,   g_fwd);
    cudaGetSymbolAddress((void**)&fwdb,   g_fwdb);
    cudaGetSymbolAddress((void**)&bwdb,   g_bwdb);
    cudaGetSymbolAddress((void**)&fusedb, g_fusedb);
    cudaGetSymbolAddress((void**)&gpre,   g_gpre);
    cudaGetSymbolAddress((void**)&out2,   g_out2);

    const int flashSmem = 106496;
    const int gemmSmem  = 3 * (GSTAGE_A + GSTAGE_B) * 2;   // 61440
    const int bwdSmem   = 2 * 96 * 65 * 4;                 // 49920
    cudaFuncSetAttribute(flash_fwd_kernel,
                         cudaFuncAttributeMaxDynamicSharedMemorySize, flashSmem);
    cudaFuncSetAttribute(gemm_bf<0>,
                         cudaFuncAttributeMaxDynamicSharedMemorySize, gemmSmem);
    cudaFuncSetAttribute(gemm_bf<1>,
                         cudaFuncAttributeMaxDynamicSharedMemorySize, gemmSmem);
    cudaFuncSetAttribute(bwd_attn_kernel,
                         cudaFuncAttributeMaxDynamicSharedMemorySize, bwdSmem);

    // conversions
    cvt_x_kernel<<<(MROWS * DM / 4) / 256, 256>>>((const float4*)x, (bf2*)xb);
    {
        TW t;
        const float* W[7] = {fq_w, fk_w, fv_w, bq_w, bk_w, bv_w, out_w};
        for (int i = 0; i < 7; i++) { t.W[i] = W[i]; t.Wt[i] = wt7 + (size_t)i * DM * DM; }
        transpose_w7<<<dim3(DM / 32, DM / 32, 7), dim3(32, 8)>>>(t);
        transpose_w_kernel<<<dim3(DM / 32, 2 * DM / 32), dim3(32, 8)>>>(gate_w, gwt, 2 * DM, DM);
    }

    // 6 fused projections
    {
        GB a = {};
        a.A0 = xb; a.K = DM; a.N = DM; a.KA0 = DM;
        a.maskF = 0b111100; a.maskB = 0b000011;
        const float* Bb[6] = {fq_b, fk_b, fv_b, bq_b, bk_b, bv_b};
        float* Of[6] = {unused, unused + (size_t)BHT*SEQ*HDIM, vf, qbf, kbf, vbf};
        for (int i = 0; i < 6; i++) {
            a.Bt6[i] = wt7 + (size_t)i * DM * DM;
            a.b6[i] = Bb[i];
            a.o6[i] = Of[i];
            a.ob6[i] = hb16 + (size_t)i * BHT * SEQ * HDIM;
        }
        gemm_bf<0><<<dim3(DM / BN, MROWS / BM, 6), 128, gemmSmem>>>(a);
    }

    // flash attention
    flash_fwd_kernel<<<dim3(SEQ / 128, BHT), 256, flashSmem>>>(
        hb16, hb16 + (size_t)BHT * SEQ * HDIM, vf, fwdf, fwdb);

    // window backward attention + last-row mean
    bwd_attn_kernel<<<dim3(SEQ / 64, BHT), 256, bwdSmem>>>(qbf, kbf, vbf, bwdb);
    vb_mean_kernel<<<BHT, 256>>>(vbf, bwdb);

    // gate gemm
    {
        GB a = {};
        a.A0 = fwdb; a.A1 = bwdb; a.Bt = gwt; a.bias = gate_b; a.Cf = gpre;
        a.N = DM; a.K = 2 * DM; a.KA0 = DM;
        gemm_bf<1><<<dim3(DM / BN, MROWS / BM, 1), 128, gemmSmem>>>(a);
    }
    gate_fuse_kernel<<<MROWS, 256>>>(gpre, fwdf, bwdb, gln_g, gln_b, bstr, fusedb);

    // output projection
    {
        GB a = {};
        a.A0 = fusedb; a.A1 = fusedb; a.Bt = wt7 + (size_t)6 * DM * DM;
        a.bias = out_b; a.Cf = out2;
        a.N = DM; a.K = DM; a.KA0 = DM;
        gemm_bf<1><<<dim3(DM / BN, MROWS / BM, 1), 128, gemmSmem>>>(a);
    }
    final_ln_kernel<<<MROWS, 256>>>(x, out2, ln_g, ln_b, (float*)d_out);
}

// round 14
// speedup vs baseline: 7.4242x; 1.1624x over previous
#include <cuda_runtime.h>
#include <cuda_bf16.h>
#include <math.h>

// Problem constants
#define SEQ   2048
#define NB    2
#define NH    16
#define HDIM  64
#define DM    1024
#define BHT   (NB*NH)        // 32 batch*heads
#define MROWS (NB*SEQ)       // 4096

// bf16 GEMM tile config: 128x128 block tile, 4 warps of 64x64, BK=32, 3-stage
#define BM 128
#define BN 128
#define BKH 32
#define LDAH 40              // bf16-element stride (80B rows; ldmatrix conflict-free)
#define LDBH 40
#define GSTAGE_A (BM*LDAH)
#define GSTAGE_B (BN*LDBH)

// Flash attention (all-bf16 tiles, stride 72 elements = 144B rows)
#define FQ  72

typedef __nv_bfloat16 bf;
typedef __nv_bfloat162 bf2;

// ---------------- scratch (device globals: allocation-free) ----------------
__device__ unsigned short g_xb [(size_t)MROWS*DM];
__device__ unsigned short g_wt7[7][DM*DM];                  // [N][K] bf16
__device__ unsigned short g_gwt[2*DM*DM];                   // gate_w transposed
__device__ unsigned short g_hb16[6][BHT*SEQ*HDIM];          // bf16 proj outputs
__device__ float g_qb[BHT*SEQ*HDIM];
__device__ float g_kb[BHT*SEQ*HDIM];
__device__ float g_vb[BHT*SEQ*HDIM];
__device__ float g_unused[3][BHT*SEQ*HDIM];                 // fp32 slots for q,k,v (unwritten)
__device__ float g_fwd [(size_t)MROWS*DM];
__device__ unsigned short g_fwdb  [(size_t)MROWS*DM];
__device__ unsigned short g_bwdb  [(size_t)MROWS*DM];
__device__ unsigned short g_fusedb[(size_t)MROWS*DM];
__device__ float g_gpre[(size_t)MROWS*DM];
__device__ float g_out2[(size_t)MROWS*DM];

// ---------------- helpers ----------------
__device__ __forceinline__ void cpa8(unsigned dst, const void* src) {
    asm volatile("cp.async.ca.shared.global [%0], [%1], 8;" :: "r"(dst), "l"(src));
}
__device__ __forceinline__ void cp16(unsigned dst, const void* src) {
    asm volatile("cp.async.cg.shared.global [%0], [%1], 16;" :: "r"(dst), "l"(src));
}
__device__ __forceinline__ void cp_commit() { asm volatile("cp.async.commit_group;"); }
template<int N> __device__ __forceinline__ void cp_wait() {
    asm volatile("cp.async.wait_group %0;" :: "n"(N));
}
__device__ __forceinline__ void ldm_x4(unsigned* r, unsigned addr) {
    asm volatile("ldmatrix.sync.aligned.m8n8.x4.shared.b16 {%0,%1,%2,%3}, [%4];"
        : "=r"(r[0]), "=r"(r[1]), "=r"(r[2]), "=r"(r[3]) : "r"(addr));
}
__device__ __forceinline__ void ldm_x4t(unsigned* r, unsigned addr) {
    asm volatile("ldmatrix.sync.aligned.m8n8.x4.trans.shared.b16 {%0,%1,%2,%3}, [%4];"
        : "=r"(r[0]), "=r"(r[1]), "=r"(r[2]), "=r"(r[3]) : "r"(addr));
}

// bf16 m16n8k16, fp32 accumulate
__device__ __forceinline__ void mma16(float* c, const unsigned* a, unsigned b0, unsigned b1) {
    asm volatile(
        "mma.sync.aligned.m16n8k16.row.col.f32.bf16.bf16.f32 "
        "{%0,%1,%2,%3}, {%4,%5,%6,%7}, {%8,%9}, {%0,%1,%2,%3};"
        : "+f"(c[0]), "+f"(c[1]), "+f"(c[2]), "+f"(c[3])
        : "r"(a[0]), "r"(a[1]), "r"(a[2]), "r"(a[3]), "r"(b0), "r"(b1));
}

__device__ __forceinline__ float sigmoidf_(float x) { return 1.f / (1.f + __expf(-x)); }

// ---------------- conversion kernels ----------------
__global__ void cvt_x_kernel(const float4* __restrict__ x, bf2* __restrict__ xb) {
    int i = blockIdx.x * 256 + threadIdx.x;
    float4 t = x[i];
    xb[2 * i]     = __floats2bfloat162_rn(t.x, t.y);
    xb[2 * i + 1] = __floats2bfloat162_rn(t.z, t.w);
}

struct TW { const float* W[7]; unsigned short* Wt[7]; };

__global__ void transpose_w7(TW t) {
    __shared__ float sm[32][33];
    const float* W = t.W[blockIdx.z];
    bf* out = (bf*)t.Wt[blockIdx.z];
    const int n0 = blockIdx.x * 32, k0 = blockIdx.y * 32;
    const int tx = threadIdx.x, ty = threadIdx.y;
#pragma unroll
    for (int j = 0; j < 32; j += 8)
        sm[ty + j][tx] = W[(size_t)(k0 + ty + j) * DM + n0 + tx];
    __syncthreads();
#pragma unroll
    for (int j = 0; j < 32; j += 8)
        out[(size_t)(n0 + ty + j) * DM + k0 + tx] = __float2bfloat16(sm[tx][ty + j]);
}

__global__ void transpose_w_kernel(const float* __restrict__ W, unsigned short* __restrict__ Wt,
                                   int K, int N) {
    __shared__ float t[32][33];
    const int n0 = blockIdx.x * 32, k0 = blockIdx.y * 32;
    const int tx = threadIdx.x, ty = threadIdx.y;
#pragma unroll
    for (int j = 0; j < 32; j += 8)
        t[ty + j][tx] = W[(size_t)(k0 + ty + j) * N + n0 + tx];
    __syncthreads();
    bf* out = (bf*)Wt;
#pragma unroll
    for (int j = 0; j < 32; j += 8)
        out[(size_t)(n0 + ty + j) * K + k0 + tx] = __float2bfloat16(t[tx][ty + j]);
}

// ---------------- bf16 GEMM (3-stage cp.async, ldmatrix feeding) ----------------
struct GB {
    const unsigned short *A0, *A1, *Bt;
    const float* bias;
    float* Cf;
    int N, K, KA0, maskF, maskB;
    const unsigned short* Bt6[6]; const float* b6[6];
    float* o6[6]; unsigned short* ob6[6];
};

template<int MODE>
__device__ __forceinline__ void issue_bf(
    const GB& g, const unsigned short* Ap, const unsigned short* Btp,
    unsigned short* As, unsigned short* Bs, int m0, int n0, int ks, int tid)
{
    unsigned aB = (unsigned)__cvta_generic_to_shared(As);
    unsigned bB = (unsigned)__cvta_generic_to_shared(Bs);
#pragma unroll
    for (int i = 0; i < 8; i++) {
        int e = i * 128 + tid, mm = e >> 3, c4 = (e & 7) * 4;
        const unsigned short* src;
        if (MODE == 0) src = Ap + (size_t)(m0 + mm) * g.K + ks + c4;
        else { int gk = ks + c4;
            src = (gk < g.KA0) ? g.A0 + (size_t)(m0 + mm) * g.KA0 + gk
                               : g.A1 + (size_t)(m0 + mm) * g.KA0 + (gk - g.KA0); }
        cpa8(aB + (unsigned)(mm * LDAH + c4) * 2u, src);
    }
#pragma unroll
    for (int i = 0; i < 8; i++) {
        int e = i * 128 + tid, nn = e >> 3, c4 = (e & 7) * 4;
        cpa8(bB + (unsigned)(nn * LDBH + c4) * 2u, Btp + (size_t)(n0 + nn) * g.K + ks + c4);
    }
}

template<int MODE>
__global__ void __launch_bounds__(128, 2) gemm_bf(GB g)
{
    extern __shared__ unsigned short gsm[];
    const unsigned gsmU = (unsigned)__cvta_generic_to_shared(gsm);

    const int nb = blockIdx.x, mb = blockIdx.y, z = blockIdx.z;
    const int m0 = mb * BM, n0 = nb * BN;

    const unsigned short *Ap, *Btp; const float* bias; float* Cf; unsigned short* Cb;
    if (MODE == 0) { Ap = g.A0; Btp = g.Bt6[z]; bias = g.b6[z]; Cf = g.o6[z]; Cb = g.ob6[z]; }
    else           { Ap = g.A0; Btp = g.Bt; bias = g.bias; Cf = g.Cf; Cb = nullptr; }

    const int tid = threadIdx.x, lane = tid & 31, warp = tid >> 5;
    const int wm = (warp & 1) * 64, wn = (warp >> 1) * 64;
    const int qrow = lane >> 2, qcol = lane & 3;
    const int la15 = lane & 15, la16 = lane >> 4;
    const int bg = lane >> 3, br = lane & 7;

    const unsigned aOff = (unsigned)((wm + la15) * LDAH + la16 * 8);
    const unsigned bOff = (unsigned)((wn + ((bg >> 1) * 8) + br) * LDBH + (bg & 1) * 8);

    float acc[4][8][4] = {};
    const int nIter = g.K / BKH;

    issue_bf<MODE>(g, Ap, Btp, gsm, gsm + 3 * GSTAGE_A, m0, n0, 0, tid);
    cp_commit();
    issue_bf<MODE>(g, Ap, Btp, gsm + GSTAGE_A, gsm + 3 * GSTAGE_A + GSTAGE_B, m0, n0, BKH, tid);
    cp_commit();

    int bi = 0;
    for (int it = 0; it < nIter; ++it) {
        if (it + 1 < nIter) cp_wait<1>(); else cp_wait<0>();
        __syncthreads();
        if (it + 2 < nIter) {
            int wb = bi + 2; if (wb >= 3) wb -= 3;
            issue_bf<MODE>(g, Ap, Btp, gsm + wb * GSTAGE_A,
                           gsm + 3 * GSTAGE_A + wb * GSTAGE_B, m0, n0, (it + 2) * BKH, tid);
            cp_commit();
        }
        const unsigned aSt = gsmU + (unsigned)(bi * GSTAGE_A) * 2u;
        const unsigned bSt = gsmU + (unsigned)(3 * GSTAGE_A + bi * GSTAGE_B) * 2u;
#pragma unroll
        for (int kk = 0; kk < BKH; kk += 16) {
            unsigned a[4][4];
#pragma unroll
            for (int mf = 0; mf < 4; mf++)
                ldm_x4(a[mf], aSt + (aOff + (unsigned)(mf * 16 * LDAH + kk)) * 2u);
            unsigned bfr[4][4];
#pragma unroll
            for (int nfp = 0; nfp < 4; nfp++)
                ldm_x4(bfr[nfp], bSt + (bOff + (unsigned)(nfp * 16 * LDBH + kk)) * 2u);
#pragma unroll
            for (int nf = 0; nf < 8; nf++) {
                unsigned b0 = bfr[nf >> 1][(nf & 1) * 2];
                unsigned b1 = bfr[nf >> 1][(nf & 1) * 2 + 1];
#pragma unroll
                for (int mf = 0; mf < 4; mf++)
                    mma16(acc[mf][nf], a[mf], b0, b1);
            }
        }
        if (++bi == 3) bi = 0;
    }

    const bool doF = (MODE != 0) || ((g.maskF >> z) & 1);
    const bool doB = (MODE == 0) && ((g.maskB >> z) & 1);
#pragma unroll
    for (int mf = 0; mf < 4; mf++)
#pragma unroll
    for (int nf = 0; nf < 8; nf++)
#pragma unroll
    for (int t2 = 0; t2 < 2; t2++) {
        int r   = m0 + wm + mf * 16 + qrow + t2 * 8;
        int col = n0 + wn + nf * 8 + qcol * 2;
        float v0 = acc[mf][nf][t2 * 2] + bias[col];
        float v1 = acc[mf][nf][t2 * 2 + 1] + bias[col + 1];
        if (MODE == 0) {
            int b = r >> 11, s = r & (SEQ - 1), h = col >> 6, hd = col & 63;
            size_t off = ((size_t)(b * NH + h) * SEQ + s) * HDIM + hd;
            if (doF) *reinterpret_cast<float2*>(&Cf[off]) = make_float2(v0, v1);
            if (doB) *reinterpret_cast<bf2*>((bf*)Cb + off) = __floats2bfloat162_rn(v0, v1);
        } else {
            *reinterpret_cast<float2*>(&Cf[(size_t)r * g.N + col]) = make_float2(v0, v1);
        }
    }
}

// ---------------- fused causal flash attention (all-bf16 MMA) ----------------
// SMEM: Qs@0 (18432) | Ks[2]@18432 (2x9216) | Vs[2]@36864 (2x9216, bf16) | Ps@55296 (18432, bf16)
__global__ void __launch_bounds__(256, 2) flash_fwd_kernel(
    const unsigned short* __restrict__ Qg, const unsigned short* __restrict__ Kg,
    const unsigned short* __restrict__ Vg, float* __restrict__ fwdf,
    unsigned short* __restrict__ fwdb)
{
    extern __shared__ char sm_[];
    bf* Qs  = (bf*)sm_;
    bf* Psb = (bf*)(sm_ + 55296);
    const unsigned sbase = (unsigned)__cvta_generic_to_shared(sm_);

    const int m0 = blockIdx.x * 128;
    const int bh = blockIdx.y;
    const bf* Qp = (const bf*)Qg + (size_t)bh * SEQ * HDIM;
    const bf* Kp = (const bf*)Kg + (size_t)bh * SEQ * HDIM;
    const bf* Vp = (const bf*)Vg + (size_t)bh * SEQ * HDIM;

    const int tid = threadIdx.x, lane = tid & 31, warp = tid >> 5;
    const int wm = warp * 16;
    const int qrow = lane >> 2, qcol = lane & 3;
    const int bg = lane >> 3, br = lane & 7;
    const int la15 = lane & 15, la16 = lane >> 4;
    // QK B-frag (non-trans): rows = key, contiguous = hd
    const unsigned kOff = (unsigned)((((bg >> 1) * 8) + br) * FQ + (bg & 1) * 8);
    // PV A-frag (non-trans): rows = q, contiguous = key
    const unsigned pOff = (unsigned)((wm + la15) * FQ + la16 * 8);
    // PV B-frag (trans): rows = key, contiguous = hd, transposed by ldmatrix
    const unsigned vLane = (unsigned)((((lane >> 3) & 1) * 8 + (lane & 7)) * FQ + (lane >> 4) * 8);

    auto issue_kv = [&](int kt2, int buf) {
        unsigned kb = sbase + 18432u + (unsigned)buf * 9216u;
        unsigned vb = sbase + 36864u + (unsigned)buf * 9216u;
        const int nk = kt2 * 64;
#pragma unroll
        for (int i = 0; i < 2; i++) {
            int e = i * 256 + tid, r = e >> 3, c8 = (e & 7) * 8;
            cp16(kb + (unsigned)(r * FQ + c8) * 2u, Kp + (size_t)(nk + r) * HDIM + c8);
            cp16(vb + (unsigned)(r * FQ + c8) * 2u, Vp + (size_t)(nk + r) * HDIM + c8);
        }
    };

    issue_kv(0, 0);
    cp_commit();

#pragma unroll
    for (int i = 0; i < 4; i++) {
        int e = i * 256 + tid, r = e >> 3, c8 = (e & 7) * 8;
        *reinterpret_cast<uint4*>(Qs + r * FQ + c8) =
            *reinterpret_cast<const uint4*>(Qp + (size_t)(m0 + r) * HDIM + c8);
    }
    __syncthreads();

    unsigned qf[4][4];
#pragma unroll
    for (int ks = 0; ks < 4; ks++) {
        int r = wm + qrow, c = 16 * ks + 2 * qcol;
        qf[ks][0] = *(const unsigned*)(Qs + r * FQ + c);
        qf[ks][1] = *(const unsigned*)(Qs + (r + 8) * FQ + c);
        qf[ks][2] = *(const unsigned*)(Qs + r * FQ + c + 8);
        qf[ks][3] = *(const unsigned*)(Qs + (r + 8) * FQ + c + 8);
    }

    float o[8][4] = {};
    float mrow[2] = {-1e30f, -1e30f};
    float lrow[2] = {0.f, 0.f};

    const int ntiles = m0 / 64 + 2;
    for (int kt = 0; kt < ntiles; kt++) {
        const int n0k = kt * 64;
        const int buf = kt & 1;
        if (kt + 1 < ntiles) {
            issue_kv(kt + 1, buf ^ 1);
            cp_commit();
            cp_wait<1>();
        } else cp_wait<0>();
        __syncthreads();

        const unsigned kSt = sbase + 18432u + (unsigned)buf * 9216u;
        const unsigned vSt = sbase + 36864u + (unsigned)buf * 9216u;

        // S = Q @ K^T (bf16, ldmatrix-fed)
        float s[8][4] = {};
#pragma unroll
        for (int ks = 0; ks < 4; ks++) {
            unsigned bfr[4][4];
#pragma unroll
            for (int nfp = 0; nfp < 4; nfp++)
                ldm_x4(bfr[nfp], kSt + (kOff + (unsigned)(nfp * 16 * FQ + 16 * ks)) * 2u);
#pragma unroll
            for (int nf = 0; nf < 8; nf++) {
                unsigned b0 = bfr[nf >> 1][(nf & 1) * 2];
                unsigned b1 = bfr[nf >> 1][(nf & 1) * 2 + 1];
                mma16(s[nf], qf[ks], b0, b1);
            }
        }

        // online softmax
        const bool domask = (n0k + 63 > m0);
#pragma unroll
        for (int t2 = 0; t2 < 2; t2++) {
            const int row = m0 + wm + qrow + t2 * 8;
            float tmax = -1e30f;
#pragma unroll
            for (int nf = 0; nf < 8; nf++)
#pragma unroll
            for (int j = 0; j < 2; j++) {
                float v = s[nf][t2 * 2 + j] * 0.125f;
                if (domask) {
                    int key = n0k + nf * 8 + qcol * 2 + j;
                    if (key > row) v = -1e30f;
                }
                s[nf][t2 * 2 + j] = v;
                tmax = fmaxf(tmax, v);
            }
            tmax = fmaxf(tmax, __shfl_xor_sync(0xffffffffu, tmax, 1));
            tmax = fmaxf(tmax, __shfl_xor_sync(0xffffffffu, tmax, 2));
            float mnew = fmaxf(mrow[t2], tmax);
            float alpha = __expf(mrow[t2] - mnew);
            float psum = 0.f;
#pragma unroll
            for (int nf = 0; nf < 8; nf++)
#pragma unroll
            for (int j = 0; j < 2; j++) {
                float p = __expf(s[nf][t2 * 2 + j] - mnew);
                s[nf][t2 * 2 + j] = p;
                psum += p;
            }
            psum += __shfl_xor_sync(0xffffffffu, psum, 1);
            psum += __shfl_xor_sync(0xffffffffu, psum, 2);
            lrow[t2] = lrow[t2] * alpha + psum;
            mrow[t2] = mnew;
#pragma unroll
            for (int nf = 0; nf < 8; nf++) {
                o[nf][t2 * 2]     *= alpha;
                o[nf][t2 * 2 + 1] *= alpha;
            }
        }

        // write P (bf16) to smem
#pragma unroll
        for (int t2 = 0; t2 < 2; t2++) {
            int r = wm + qrow + t2 * 8;
#pragma unroll
            for (int nf = 0; nf < 8; nf++) {
                *reinterpret_cast<bf2*>(Psb + r * FQ + nf * 8 + qcol * 2) =
                    __floats2bfloat162_rn(s[nf][t2 * 2], s[nf][t2 * 2 + 1]);
            }
        }
        __syncthreads();

        // O += P @ V (bf16: ldmatrix A + ldmatrix.trans B)
        const unsigned pSt = sbase + 55296u;
#pragma unroll
        for (int ks4 = 0; ks4 < 4; ks4++) {
            unsigned a[4];
            ldm_x4(a, pSt + (pOff + (unsigned)(ks4 * 16)) * 2u);
#pragma unroll
            for (int np = 0; np < 4; np++) {
                unsigned v4[4];
                ldm_x4t(v4, vSt + (vLane + (unsigned)(ks4 * 16 * FQ + np * 16)) * 2u);
                mma16(o[np * 2],     a, v4[0], v4[1]);
                mma16(o[np * 2 + 1], a, v4[2], v4[3]);
            }
        }
        __syncthreads();
    }

    const int b = bh >> 4, h = bh & 15;
#pragma unroll
    for (int t2 = 0; t2 < 2; t2++) {
        int srow = m0 + wm + qrow + t2 * 8;
        float inv = 1.f / lrow[t2];
        size_t base = ((size_t)(b * SEQ + srow)) * DM + h * HDIM;
#pragma unroll
        for (int nf = 0; nf < 8; nf++) {
            float v0 = o[nf][t2 * 2] * inv, v1 = o[nf][t2 * 2 + 1] * inv;
            *reinterpret_cast<float2*>(&fwdf[base + nf * 8 + qcol * 2]) = make_float2(v0, v1);
            *reinterpret_cast<bf2*>((bf*)fwdb + base + nf * 8 + qcol * 2) =
                __floats2bfloat162_rn(v0, v1);
        }
    }
}

// ---------------- tiled window-32 backward attention ----------------
__global__ void __launch_bounds__(256) bwd_attn_kernel(
    const float* __restrict__ Qb, const float* __restrict__ Kb,
    const float* __restrict__ Vb, unsigned short* __restrict__ bwdb)
{
    extern __shared__ float bsm[];
    float* Ks = bsm;              // 96 x 65
    float* Vs = bsm + 96 * 65;    // 96 x 65
    __shared__ float qsh[8][66];

    const int m0 = blockIdx.x * 64;
    const int bh = blockIdx.y;
    const float* Qp = Qb + (size_t)bh * SEQ * HDIM;
    const float* Kp = Kb + (size_t)bh * SEQ * HDIM;
    const float* Vp = Vb + (size_t)bh * SEQ * HDIM;
    const int b = bh >> 4, h = bh & 15;

    const int tid = threadIdx.x, wid = tid >> 5, lane = tid & 31;
    const int nrows = min(96, SEQ - 1 - m0);

    for (int i = tid; i < nrows * 16; i += 256) {
        int row = i >> 4, c4 = (i & 15) * 4;
        float4 tk = *reinterpret_cast<const float4*>(Kp + (size_t)(m0 + 1 + row) * HDIM + c4);
        float4 tv = *reinterpret_cast<const float4*>(Vp + (size_t)(m0 + 1 + row) * HDIM + c4);
        float* dk = Ks + row * 65 + c4; dk[0]=tk.x; dk[1]=tk.y; dk[2]=tk.z; dk[3]=tk.w;
        float* dv = Vs + row * 65 + c4; dv[0]=tv.x; dv[1]=tv.y; dv[2]=tv.z; dv[3]=tv.w;
    }
    __syncthreads();

#pragma unroll
    for (int t = 0; t < 8; t++) {
        const int m = m0 + wid * 8 + t;
        int w = SEQ - 1 - m; if (w > 32) w = 32;
        if (w <= 0) continue;

        __syncwarp();
        qsh[wid][lane]      = Qp[m * HDIM + lane];
        qsh[wid][lane + 32] = Qp[m * HDIM + lane + 32];
        __syncwarp();

        float sc = -1e30f;
        if (lane < w) {
            const float* kr = Ks + (m - m0 + lane) * 65;
            float a = 0.f;
#pragma unroll
            for (int d = 0; d < HDIM; d++) a += qsh[wid][d] * kr[d];
            sc = a * 0.125f;
        }
        float mx = sc;
#pragma unroll
        for (int o = 16; o > 0; o >>= 1) mx = fmaxf(mx, __shfl_xor_sync(0xffffffffu, mx, o));
        float e = __expf(sc - mx);
        float sum = e;
#pragma unroll
        for (int o = 16; o > 0; o >>= 1) sum += __shfl_xor_sync(0xffffffffu, sum, o);
        float p = e / sum;

        float o0 = 0.f, o1 = 0.f;
        for (int kk = 0; kk < w; kk++) {
            float pk = __shfl_sync(0xffffffffu, p, kk);
            const float* vr = Vs + (m - m0 + kk) * 65;
            o0 += pk * vr[lane];
            o1 += pk * vr[lane + 32];
        }
        bf* outp = (bf*)bwdb + ((size_t)(b * SEQ + m)) * DM + h * HDIM;
        outp[lane] = __float2bfloat16(o0);
        outp[lane + 32] = __float2bfloat16(o1);
    }
}

// mean of Vb over all S for the all-masked last row
__global__ void vb_mean_kernel(const float* __restrict__ Vb, unsigned short* __restrict__ bwdb) {
    __shared__ float part[4][64];
    const int bh = blockIdx.x, tid = threadIdx.x;
    const int col = tid & 63, grp = tid >> 6;
    const float* Vp = Vb + (size_t)bh * SEQ * HDIM;
    float s = 0.f;
    for (int r = grp; r < SEQ; r += 4) s += Vp[(size_t)r * HDIM + col];
    part[grp][col] = s;
    __syncthreads();
    if (tid < 64) {
        float m = (part[0][tid] + part[1][tid] + part[2][tid] + part[3][tid]) * (1.f / SEQ);
        int b = bh >> 4, h = bh & 15;
        ((bf*)bwdb)[((size_t)(b * SEQ + SEQ - 1)) * DM + h * HDIM + tid] = __float2bfloat16(m);
    }
}

// ---------------- gate LN + sigmoid + fusion ----------------
__global__ void gate_fuse_kernel(const float* __restrict__ gpre, const float* __restrict__ fwdf,
                                 const unsigned short* __restrict__ bwdb,
                                 const float* __restrict__ gg, const float* __restrict__ gb,
                                 const float* __restrict__ bstr, unsigned short* __restrict__ fusedb) {
    const int r = blockIdx.x, tid = threadIdx.x;
    const float* rowp = gpre + (size_t)r * DM;
    __shared__ float red[256];
    float v[4]; float s = 0.f, ss = 0.f;
#pragma unroll
    for (int i = 0; i < 4; i++) { v[i] = rowp[tid + i * 256]; s += v[i]; ss += v[i] * v[i]; }
    red[tid] = s; __syncthreads();
    for (int o = 128; o > 0; o >>= 1) { if (tid < o) red[tid] += red[tid + o]; __syncthreads(); }
    float mean = red[0] * (1.f / DM); __syncthreads();
    red[tid] = ss; __syncthreads();
    for (int o = 128; o > 0; o >>= 1) { if (tid < o) red[tid] += red[tid + o]; __syncthreads(); }
    float var = red[0] * (1.f / DM) - mean * mean;
    float rstd = rsqrtf(var + 1e-5f);
    float strength = 0.3f * sigmoidf_(bstr[0]);
#pragma unroll
    for (int i = 0; i < 4; i++) {
        int j = tid + i * 256;
        float g = sigmoidf_((v[i] - mean) * rstd * gg[j] + gb[j]);
        size_t o = (size_t)r * DM + j;
        float bw = __bfloat162float(((const bf*)bwdb)[o]);
        ((bf*)fusedb)[o] = __float2bfloat16(fwdf[o] + strength * g * bw);
    }
}

// ---------------- final residual + LayerNorm ----------------
__global__ void final_ln_kernel(const float* __restrict__ x, const float* __restrict__ o2,
                                const float* __restrict__ lg, const float* __restrict__ lb,
                                float* __restrict__ out) {
    const int r = blockIdx.x, tid = threadIdx.x;
    __shared__ float red[256];
    float v[4]; float s = 0.f, ss = 0.f;
#pragma unroll
    for (int i = 0; i < 4; i++) {
        size_t o = (size_t)r * DM + tid + i * 256;
        v[i] = x[o] + o2[o];
        s += v[i]; ss += v[i] * v[i];
    }
    red[tid] = s; __syncthreads();
    for (int o = 128; o > 0; o >>= 1) { if (tid < o) red[tid] += red[tid + o]; __syncthreads(); }
    float mean = red[0] * (1.f / DM); __syncthreads();
    red[tid] = ss; __syncthreads();
    for (int o = 128; o > 0; o >>= 1) { if (tid < o) red[tid] += red[tid + o]; __syncthreads(); }
    float var = red[0] * (1.f / DM) - mean * mean;
    float rstd = rsqrtf(var + 1e-5f);
#pragma unroll
    for (int i = 0; i < 4; i++) {
        int j = tid + i * 256;
        size_t o = (size_t)r * DM + j;
        out[o] = (v[i] - mean) * rstd * lg[j] + lb[j];
    }
}

// ---------------- launch ----------------
extern "C" void kernel_launch(void* const* d_in, const int* in_sizes, int n_in,
                              void* d_out, int out_size) {
    const float* x      = (const float*)d_in[0];
    const float* fq_w   = (const float*)d_in[1];
    const float* fq_b   = (const float*)d_in[2];
    const float* fk_w   = (const float*)d_in[3];
    const float* fk_b   = (const float*)d_in[4];
    const float* fv_w   = (const float*)d_in[5];
    const float* fv_b   = (const float*)d_in[6];
    const float* bq_w   = (const float*)d_in[7];
    const float* bq_b   = (const float*)d_in[8];
    const float* bk_w   = (const float*)d_in[9];
    const float* bk_b   = (const float*)d_in[10];
    const float* bv_w   = (const float*)d_in[11];
    const float* bv_b   = (const float*)d_in[12];
    const float* gate_w = (const float*)d_in[13];
    const float* gate_b = (const float*)d_in[14];
    const float* gln_g  = (const float*)d_in[15];
    const float* gln_b  = (const float*)d_in[16];
    const float* bstr   = (const float*)d_in[17];
    const float* out_w  = (const float*)d_in[18];
    const float* out_b  = (const float*)d_in[19];
    const float* ln_g   = (const float*)d_in[20];
    const float* ln_b   = (const float*)d_in[21];

    unsigned short *xb, *gwt, *fwdb, *bwdb, *fusedb, *wt7, *hb16;
    float *qbf, *kbf, *vbf, *unused, *fwdf, *gpre, *out2;
    cudaGetSymbolAddress((void**)&xb,     g_xb);
    cudaGetSymbolAddress((void**)&wt7,    g_wt7);
    cudaGetSymbolAddress((void**)&gwt,    g_gwt);
    cudaGetSymbolAddress((void**)&hb16,   g_hb16);
    cudaGetSymbolAddress((void**)&qbf,    g_qb);
    cudaGetSymbolAddress((void**)&kbf,    g_kb);
    cudaGetSymbolAddress((void**)&vbf,    g_vb);
    cudaGetSymbolAddress((void**)&unused, g_unused);
    cudaGetSymbolAddress((void**)&fwdf,   g_fwd);
    cudaGetSymbolAddress((void**)&fwdb,   g_fwdb);
    cudaGetSymbolAddress((void**)&bwdb,   g_bwdb);
    cudaGetSymbolAddress((void**)&fusedb, g_fusedb);
    cudaGetSymbolAddress((void**)&gpre,   g_gpre);
    cudaGetSymbolAddress((void**)&out2,   g_out2);

    const int flashSmem = 73728;   // Qs 18432 + 2xKs 18432 + 2xVs 18432 + Ps 18432
    const int gemmSmem  = 3 * (GSTAGE_A + GSTAGE_B) * 2;   // 61440
    const int bwdSmem   = 2 * 96 * 65 * 4;                 // 49920
    cudaFuncSetAttribute(flash_fwd_kernel,
                         cudaFuncAttributeMaxDynamicSharedMemorySize, flashSmem);
    cudaFuncSetAttribute(gemm_bf<0>,
                         cudaFuncAttributeMaxDynamicSharedMemorySize, gemmSmem);
    cudaFuncSetAttribute(gemm_bf<1>,
                         cudaFuncAttributeMaxDynamicSharedMemorySize, gemmSmem);
    cudaFuncSetAttribute(bwd_attn_kernel,
                         cudaFuncAttributeMaxDynamicSharedMemorySize, bwdSmem);

    // conversions
    cvt_x_kernel<<<(MROWS * DM / 4) / 256, 256>>>((const float4*)x, (bf2*)xb);
    {
        TW t;
        const float* W[7] = {fq_w, fk_w, fv_w, bq_w, bk_w, bv_w, out_w};
        for (int i = 0; i < 7; i++) { t.W[i] = W[i]; t.Wt[i] = wt7 + (size_t)i * DM * DM; }
        transpose_w7<<<dim3(DM / 32, DM / 32, 7), dim3(32, 8)>>>(t);
        transpose_w_kernel<<<dim3(DM / 32, 2 * DM / 32), dim3(32, 8)>>>(gate_w, gwt, 2 * DM, DM);
    }

    // 6 fused projections: fp32 for qb,kb,vb (bits 3,4,5); bf16 for q,k,v (bits 0,1,2)
    {
        GB a = {};
        a.A0 = xb; a.K = DM; a.N = DM; a.KA0 = DM;
        a.maskF = 0b111000; a.maskB = 0b000111;
        const float* Bb[6] = {fq_b, fk_b, fv_b, bq_b, bk_b, bv_b};
        float* Of[6] = {unused, unused + (size_t)BHT*SEQ*HDIM,
                        unused + (size_t)2*BHT*SEQ*HDIM, qbf, kbf, vbf};
        for (int i = 0; i < 6; i++) {
            a.Bt6[i] = wt7 + (size_t)i * DM * DM;
            a.b6[i] = Bb[i];
            a.o6[i] = Of[i];
            a.ob6[i] = hb16 + (size_t)i * BHT * SEQ * HDIM;
        }
        gemm_bf<0><<<dim3(DM / BN, MROWS / BM, 6), 128, gemmSmem>>>(a);
    }

    // flash attention (Q,K,V all bf16)
    flash_fwd_kernel<<<dim3(SEQ / 128, BHT), 256, flashSmem>>>(
        hb16, hb16 + (size_t)BHT * SEQ * HDIM, hb16 + (size_t)2 * BHT * SEQ * HDIM,
        fwdf, fwdb);

    // window backward attention + last-row mean
    bwd_attn_kernel<<<dim3(SEQ / 64, BHT), 256, bwdSmem>>>(qbf, kbf, vbf, bwdb);
    vb_mean_kernel<<<BHT, 256>>>(vbf, bwdb);

    // gate gemm
    {
        GB a = {};
        a.A0 = fwdb; a.A1 = bwdb; a.Bt = gwt; a.bias = gate_b; a.Cf = gpre;
        a.N = DM; a.K = 2 * DM; a.KA0 = DM;
        gemm_bf<1><<<dim3(DM / BN, MROWS / BM, 1), 128, gemmSmem>>>(a);
    }
    gate_fuse_kernel<<<MROWS, 256>>>(gpre, fwdf, bwdb, gln_g, gln_b, bstr, fusedb);

    // output projection
    {
        GB a = {};
        a.A0 = fusedb; a.A1 = fusedb; a.Bt = wt7 + (size_t)6 * DM * DM;
        a.bias = out_b; a.Cf = out2;
        a.N = DM; a.K = DM; a.KA0 = DM;
        gemm_bf<1><<<dim3(DM / BN, MROWS / BM, 1), 128, gemmSmem>>>(a);
    }
    final_ln_kernel<<<MROWS, 256>>>(x, out2, ln_g, ln_b, (float*)d_out);
}

// round 16
// speedup vs baseline: 7.7178x; 1.0396x over previous
#include <cuda_runtime.h>
#include <cuda_bf16.h>
#include <math.h>

// Problem constants
#define SEQ   2048
#define NB    2
#define NH    16
#define HDIM  64
#define DM    1024
#define BHT   (NB*NH)        // 32 batch*heads
#define MROWS (NB*SEQ)       // 4096

// bf16 GEMM tile config: 128x128 block tile, 4 warps of 64x64, BK=32, 3-stage
#define BM 128
#define BN 128
#define BKH 32
#define LDAH 40
#define LDBH 40
#define GSTAGE_A (BM*LDAH)
#define GSTAGE_B (BN*LDBH)

// Flash attention (all-bf16 tiles, stride 72 elements = 144B rows)
#define FQ  72

typedef __nv_bfloat16 bf;
typedef __nv_bfloat162 bf2;

// ---------------- scratch (device globals: allocation-free) ----------------
__device__ unsigned short g_xb [(size_t)MROWS*DM];
__device__ unsigned short g_wt7[7][DM*DM];                  // [N][K] bf16
__device__ unsigned short g_gwt[2*DM*DM];                   // gate_w transposed
__device__ unsigned short g_hb16[6][BHT*SEQ*HDIM];          // bf16 proj outputs
__device__ float g_unused[BHT*SEQ*HDIM];                    // dummy fp32 sink (unwritten)
__device__ unsigned short g_fwdb  [(size_t)MROWS*DM];
__device__ unsigned short g_bwdb  [(size_t)MROWS*DM];
__device__ unsigned short g_fusedb[(size_t)MROWS*DM];
__device__ float g_gpre[(size_t)MROWS*DM];
__device__ float g_out2[(size_t)MROWS*DM];

// ---------------- helpers ----------------
__device__ __forceinline__ void cpa8(unsigned dst, const void* src) {
    asm volatile("cp.async.ca.shared.global [%0], [%1], 8;" :: "r"(dst), "l"(src));
}
__device__ __forceinline__ void cp16(unsigned dst, const void* src) {
    asm volatile("cp.async.cg.shared.global [%0], [%1], 16;" :: "r"(dst), "l"(src));
}
__device__ __forceinline__ void cp_commit() { asm volatile("cp.async.commit_group;"); }
template<int N> __device__ __forceinline__ void cp_wait() {
    asm volatile("cp.async.wait_group %0;" :: "n"(N));
}
__device__ __forceinline__ void ldm_x4(unsigned* r, unsigned addr) {
    asm volatile("ldmatrix.sync.aligned.m8n8.x4.shared.b16 {%0,%1,%2,%3}, [%4];"
        : "=r"(r[0]), "=r"(r[1]), "=r"(r[2]), "=r"(r[3]) : "r"(addr));
}
__device__ __forceinline__ void ldm_x4t(unsigned* r, unsigned addr) {
    asm volatile("ldmatrix.sync.aligned.m8n8.x4.trans.shared.b16 {%0,%1,%2,%3}, [%4];"
        : "=r"(r[0]), "=r"(r[1]), "=r"(r[2]), "=r"(r[3]) : "r"(addr));
}
__device__ __forceinline__ float ex2_(float x) {
    float y; asm("ex2.approx.f32 %0, %1;" : "=f"(y) : "f"(x)); return y;
}

// bf16 m16n8k16, fp32 accumulate
__device__ __forceinline__ void mma16(float* c, const unsigned* a, unsigned b0, unsigned b1) {
    asm volatile(
        "mma.sync.aligned.m16n8k16.row.col.f32.bf16.bf16.f32 "
        "{%0,%1,%2,%3}, {%4,%5,%6,%7}, {%8,%9}, {%0,%1,%2,%3};"
        : "+f"(c[0]), "+f"(c[1]), "+f"(c[2]), "+f"(c[3])
        : "r"(a[0]), "r"(a[1]), "r"(a[2]), "r"(a[3]), "r"(b0), "r"(b1));
}

__device__ __forceinline__ float sigmoidf_(float x) { return 1.f / (1.f + __expf(-x)); }

// ---------------- conversion kernels ----------------
__global__ void cvt_x_kernel(const float4* __restrict__ x, bf2* __restrict__ xb) {
    int i = blockIdx.x * 256 + threadIdx.x;
    float4 t = x[i];
    xb[2 * i]     = __floats2bfloat162_rn(t.x, t.y);
    xb[2 * i + 1] = __floats2bfloat162_rn(t.z, t.w);
}

struct TW { const float* W[7]; unsigned short* Wt[7]; };

__global__ void transpose_w7(TW t) {
    __shared__ float sm[32][33];
    const float* W = t.W[blockIdx.z];
    bf* out = (bf*)t.Wt[blockIdx.z];
    const int n0 = blockIdx.x * 32, k0 = blockIdx.y * 32;
    const int tx = threadIdx.x, ty = threadIdx.y;
#pragma unroll
    for (int j = 0; j < 32; j += 8)
        sm[ty + j][tx] = W[(size_t)(k0 + ty + j) * DM + n0 + tx];
    __syncthreads();
#pragma unroll
    for (int j = 0; j < 32; j += 8)
        out[(size_t)(n0 + ty + j) * DM + k0 + tx] = __float2bfloat16(sm[tx][ty + j]);
}

__global__ void transpose_w_kernel(const float* __restrict__ W, unsigned short* __restrict__ Wt,
                                   int K, int N) {
    __shared__ float t[32][33];
    const int n0 = blockIdx.x * 32, k0 = blockIdx.y * 32;
    const int tx = threadIdx.x, ty = threadIdx.y;
#pragma unroll
    for (int j = 0; j < 32; j += 8)
        t[ty + j][tx] = W[(size_t)(k0 + ty + j) * N + n0 + tx];
    __syncthreads();
    bf* out = (bf*)Wt;
#pragma unroll
    for (int j = 0; j < 32; j += 8)
        out[(size_t)(n0 + ty + j) * K + k0 + tx] = __float2bfloat16(t[tx][ty + j]);
}

// ---------------- bf16 GEMM (3-stage cp.async, ldmatrix feeding) ----------------
struct GB {
    const unsigned short *A0, *A1, *Bt;
    const float* bias;
    float* Cf;
    int N, K, KA0, maskF, maskB;
    const unsigned short* Bt6[6]; const float* b6[6];
    float* o6[6]; unsigned short* ob6[6];
};

template<int MODE>
__device__ __forceinline__ void issue_bf(
    const GB& g, const unsigned short* Ap, const unsigned short* Btp,
    unsigned short* As, unsigned short* Bs, int m0, int n0, int ks, int tid)
{
    unsigned aB = (unsigned)__cvta_generic_to_shared(As);
    unsigned bB = (unsigned)__cvta_generic_to_shared(Bs);
#pragma unroll
    for (int i = 0; i < 8; i++) {
        int e = i * 128 + tid, mm = e >> 3, c4 = (e & 7) * 4;
        const unsigned short* src;
        if (MODE == 0) src = Ap + (size_t)(m0 + mm) * g.K + ks + c4;
        else { int gk = ks + c4;
            src = (gk < g.KA0) ? g.A0 + (size_t)(m0 + mm) * g.KA0 + gk
                               : g.A1 + (size_t)(m0 + mm) * g.KA0 + (gk - g.KA0); }
        cpa8(aB + (unsigned)(mm * LDAH + c4) * 2u, src);
    }
#pragma unroll
    for (int i = 0; i < 8; i++) {
        int e = i * 128 + tid, nn = e >> 3, c4 = (e & 7) * 4;
        cpa8(bB + (unsigned)(nn * LDBH + c4) * 2u, Btp + (size_t)(n0 + nn) * g.K + ks + c4);
    }
}

template<int MODE>
__global__ void __launch_bounds__(128, 2) gemm_bf(GB g)
{
    extern __shared__ unsigned short gsm[];
    const unsigned gsmU = (unsigned)__cvta_generic_to_shared(gsm);

    const int nb = blockIdx.x, mb = blockIdx.y, z = blockIdx.z;
    const int m0 = mb * BM, n0 = nb * BN;

    const unsigned short *Ap, *Btp; const float* bias; float* Cf; unsigned short* Cb;
    if (MODE == 0) { Ap = g.A0; Btp = g.Bt6[z]; bias = g.b6[z]; Cf = g.o6[z]; Cb = g.ob6[z]; }
    else           { Ap = g.A0; Btp = g.Bt; bias = g.bias; Cf = g.Cf; Cb = nullptr; }

    const int tid = threadIdx.x, lane = tid & 31, warp = tid >> 5;
    const int wm = (warp & 1) * 64, wn = (warp >> 1) * 64;
    const int qrow = lane >> 2, qcol = lane & 3;
    const int la15 = lane & 15, la16 = lane >> 4;
    const int bg = lane >> 3, br = lane & 7;

    const unsigned aOff = (unsigned)((wm + la15) * LDAH + la16 * 8);
    const unsigned bOff = (unsigned)((wn + ((bg >> 1) * 8) + br) * LDBH + (bg & 1) * 8);

    float acc[4][8][4] = {};
    const int nIter = g.K / BKH;

    issue_bf<MODE>(g, Ap, Btp, gsm, gsm + 3 * GSTAGE_A, m0, n0, 0, tid);
    cp_commit();
    issue_bf<MODE>(g, Ap, Btp, gsm + GSTAGE_A, gsm + 3 * GSTAGE_A + GSTAGE_B, m0, n0, BKH, tid);
    cp_commit();

    int bi = 0;
    for (int it = 0; it < nIter; ++it) {
        if (it + 1 < nIter) cp_wait<1>(); else cp_wait<0>();
        __syncthreads();
        if (it + 2 < nIter) {
            int wb = bi + 2; if (wb >= 3) wb -= 3;
            issue_bf<MODE>(g, Ap, Btp, gsm + wb * GSTAGE_A,
                           gsm + 3 * GSTAGE_A + wb * GSTAGE_B, m0, n0, (it + 2) * BKH, tid);
            cp_commit();
        }
        const unsigned aSt = gsmU + (unsigned)(bi * GSTAGE_A) * 2u;
        const unsigned bSt = gsmU + (unsigned)(3 * GSTAGE_A + bi * GSTAGE_B) * 2u;
#pragma unroll
        for (int kk = 0; kk < BKH; kk += 16) {
            unsigned a[4][4];
#pragma unroll
            for (int mf = 0; mf < 4; mf++)
                ldm_x4(a[mf], aSt + (aOff + (unsigned)(mf * 16 * LDAH + kk)) * 2u);
            unsigned bfr[4][4];
#pragma unroll
            for (int nfp = 0; nfp < 4; nfp++)
                ldm_x4(bfr[nfp], bSt + (bOff + (unsigned)(nfp * 16 * LDBH + kk)) * 2u);
#pragma unroll
            for (int nf = 0; nf < 8; nf++) {
                unsigned b0 = bfr[nf >> 1][(nf & 1) * 2];
                unsigned b1 = bfr[nf >> 1][(nf & 1) * 2 + 1];
#pragma unroll
                for (int mf = 0; mf < 4; mf++)
                    mma16(acc[mf][nf], a[mf], b0, b1);
            }
        }
        if (++bi == 3) bi = 0;
    }

    const bool doF = (MODE != 0) || ((g.maskF >> z) & 1);
    const bool doB = (MODE == 0) && ((g.maskB >> z) & 1);
#pragma unroll
    for (int mf = 0; mf < 4; mf++)
#pragma unroll
    for (int nf = 0; nf < 8; nf++)
#pragma unroll
    for (int t2 = 0; t2 < 2; t2++) {
        int r   = m0 + wm + mf * 16 + qrow + t2 * 8;
        int col = n0 + wn + nf * 8 + qcol * 2;
        float v0 = acc[mf][nf][t2 * 2] + bias[col];
        float v1 = acc[mf][nf][t2 * 2 + 1] + bias[col + 1];
        if (MODE == 0) {
            int b = r >> 11, s = r & (SEQ - 1), h = col >> 6, hd = col & 63;
            size_t off = ((size_t)(b * NH + h) * SEQ + s) * HDIM + hd;
            if (doF) *reinterpret_cast<float2*>(&Cf[off]) = make_float2(v0, v1);
            if (doB) *reinterpret_cast<bf2*>((bf*)Cb + off) = __floats2bfloat162_rn(v0, v1);
        } else {
            *reinterpret_cast<float2*>(&Cf[(size_t)r * g.N + col]) = make_float2(v0, v1);
        }
    }
}

// ---------------- fused causal flash attention (all-bf16 MMA, log2-domain softmax) ----
// SMEM: Qs@0 (18432) | Ks[2]@18432 (2x9216) | Vs[2]@36864 (2x9216) | Ps@55296 (18432)
__global__ void __launch_bounds__(256, 2) flash_fwd_kernel(
    const unsigned short* __restrict__ Qg, const unsigned short* __restrict__ Kg,
    const unsigned short* __restrict__ Vg, unsigned short* __restrict__ fwdb)
{
    extern __shared__ char sm_[];
    bf* Qs  = (bf*)sm_;
    bf* Psb = (bf*)(sm_ + 55296);
    const unsigned sbase = (unsigned)__cvta_generic_to_shared(sm_);

    const int m0 = blockIdx.x * 128;
    const int bh = blockIdx.y;
    const bf* Qp = (const bf*)Qg + (size_t)bh * SEQ * HDIM;
    const bf* Kp = (const bf*)Kg + (size_t)bh * SEQ * HDIM;
    const bf* Vp = (const bf*)Vg + (size_t)bh * SEQ * HDIM;

    const int tid = threadIdx.x, lane = tid & 31, warp = tid >> 5;
    const int wm = warp * 16;
    const int qrow = lane >> 2, qcol = lane & 3;
    const int bg = lane >> 3, br = lane & 7;
    const int la15 = lane & 15, la16 = lane >> 4;
    const unsigned kOff = (unsigned)((((bg >> 1) * 8) + br) * FQ + (bg & 1) * 8);
    const unsigned pOff = (unsigned)((wm + la15) * FQ + la16 * 8);
    const unsigned vLane = (unsigned)((((lane >> 3) & 1) * 8 + (lane & 7)) * FQ + (lane >> 4) * 8);

    auto issue_kv = [&](int kt2, int buf) {
        unsigned kb = sbase + 18432u + (unsigned)buf * 9216u;
        unsigned vb = sbase + 36864u + (unsigned)buf * 9216u;
        const int nk = kt2 * 64;
#pragma unroll
        for (int i = 0; i < 2; i++) {
            int e = i * 256 + tid, r = e >> 3, c8 = (e & 7) * 8;
            cp16(kb + (unsigned)(r * FQ + c8) * 2u, Kp + (size_t)(nk + r) * HDIM + c8);
            cp16(vb + (unsigned)(r * FQ + c8) * 2u, Vp + (size_t)(nk + r) * HDIM + c8);
        }
    };

    issue_kv(0, 0);
    cp_commit();

#pragma unroll
    for (int i = 0; i < 4; i++) {
        int e = i * 256 + tid, r = e >> 3, c8 = (e & 7) * 8;
        *reinterpret_cast<uint4*>(Qs + r * FQ + c8) =
            *reinterpret_cast<const uint4*>(Qp + (size_t)(m0 + r) * HDIM + c8);
    }
    __syncthreads();

    // lift Q fragments, fold scale 0.125*log2(e) into Q (log2-domain scores)
    const bf qsc = __float2bfloat16(0.180336881f);
    const bf2 qsc2 = __halves2bfloat162(qsc, qsc);
    unsigned qf[4][4];
#pragma unroll
    for (int ks = 0; ks < 4; ks++) {
        int r = wm + qrow, c = 16 * ks + 2 * qcol;
        qf[ks][0] = *(const unsigned*)(Qs + r * FQ + c);
        qf[ks][1] = *(const unsigned*)(Qs + (r + 8) * FQ + c);
        qf[ks][2] = *(const unsigned*)(Qs + r * FQ + c + 8);
        qf[ks][3] = *(const unsigned*)(Qs + (r + 8) * FQ + c + 8);
#pragma unroll
        for (int j = 0; j < 4; j++) {
            bf2 v = *reinterpret_cast<bf2*>(&qf[ks][j]);
            v = __hmul2(v, qsc2);
            qf[ks][j] = *reinterpret_cast<unsigned*>(&v);
        }
    }

    float o[8][4] = {};
    float mrow[2] = {-1e30f, -1e30f};
    float lrow[2] = {0.f, 0.f};

    const int ntiles = m0 / 64 + 2;
    for (int kt = 0; kt < ntiles; kt++) {
        const int n0k = kt * 64;
        const int buf = kt & 1;
        if (kt + 1 < ntiles) {
            issue_kv(kt + 1, buf ^ 1);
            cp_commit();
            cp_wait<1>();
        } else cp_wait<0>();
        __syncthreads();

        const unsigned kSt = sbase + 18432u + (unsigned)buf * 9216u;
        const unsigned vSt = sbase + 36864u + (unsigned)buf * 9216u;

        // S = Q @ K^T (log2-domain)
        float s[8][4] = {};
#pragma unroll
        for (int ks = 0; ks < 4; ks++) {
            unsigned bfr[4][4];
#pragma unroll
            for (int nfp = 0; nfp < 4; nfp++)
                ldm_x4(bfr[nfp], kSt + (kOff + (unsigned)(nfp * 16 * FQ + 16 * ks)) * 2u);
#pragma unroll
            for (int nf = 0; nf < 8; nf++) {
                unsigned b0 = bfr[nf >> 1][(nf & 1) * 2];
                unsigned b1 = bfr[nf >> 1][(nf & 1) * 2 + 1];
                mma16(s[nf], qf[ks], b0, b1);
            }
        }

        // online softmax (base-2)
        const bool domask = (n0k + 63 > m0);
#pragma unroll
        for (int t2 = 0; t2 < 2; t2++) {
            const int row = m0 + wm + qrow + t2 * 8;
            float tmax = -1e30f;
            if (domask) {
#pragma unroll
                for (int nf = 0; nf < 8; nf++)
#pragma unroll
                for (int j = 0; j < 2; j++) {
                    int key = n0k + nf * 8 + qcol * 2 + j;
                    if (key > row) s[nf][t2 * 2 + j] = -1e30f;
                    tmax = fmaxf(tmax, s[nf][t2 * 2 + j]);
                }
            } else {
#pragma unroll
                for (int nf = 0; nf < 8; nf++)
#pragma unroll
                for (int j = 0; j < 2; j++)
                    tmax = fmaxf(tmax, s[nf][t2 * 2 + j]);
            }
            tmax = fmaxf(tmax, __shfl_xor_sync(0xffffffffu, tmax, 1));
            tmax = fmaxf(tmax, __shfl_xor_sync(0xffffffffu, tmax, 2));
            float mnew = fmaxf(mrow[t2], tmax);
            float alpha = ex2_(mrow[t2] - mnew);
            float psum = 0.f;
#pragma unroll
            for (int nf = 0; nf < 8; nf++)
#pragma unroll
            for (int j = 0; j < 2; j++) {
                float p = ex2_(s[nf][t2 * 2 + j] - mnew);
                s[nf][t2 * 2 + j] = p;
                psum += p;
            }
            psum += __shfl_xor_sync(0xffffffffu, psum, 1);
            psum += __shfl_xor_sync(0xffffffffu, psum, 2);
            lrow[t2] = lrow[t2] * alpha + psum;
            mrow[t2] = mnew;
#pragma unroll
            for (int nf = 0; nf < 8; nf++) {
                o[nf][t2 * 2]     *= alpha;
                o[nf][t2 * 2 + 1] *= alpha;
            }
        }

        // write P (bf16) to smem
#pragma unroll
        for (int t2 = 0; t2 < 2; t2++) {
            int r = wm + qrow + t2 * 8;
#pragma unroll
            for (int nf = 0; nf < 8; nf++) {
                *reinterpret_cast<bf2*>(Psb + r * FQ + nf * 8 + qcol * 2) =
                    __floats2bfloat162_rn(s[nf][t2 * 2], s[nf][t2 * 2 + 1]);
            }
        }
        __syncthreads();

        // O += P @ V (bf16: ldmatrix A + ldmatrix.trans B)
        const unsigned pSt = sbase + 55296u;
#pragma unroll
        for (int ks4 = 0; ks4 < 4; ks4++) {
            unsigned a[4];
            ldm_x4(a, pSt + (pOff + (unsigned)(ks4 * 16)) * 2u);
#pragma unroll
            for (int np = 0; np < 4; np++) {
                unsigned v4[4];
                ldm_x4t(v4, vSt + (vLane + (unsigned)(ks4 * 16 * FQ + np * 16)) * 2u);
                mma16(o[np * 2],     a, v4[0], v4[1]);
                mma16(o[np * 2 + 1], a, v4[2], v4[3]);
            }
        }
        __syncthreads();
    }

    const int b = bh >> 4, h = bh & 15;
#pragma unroll
    for (int t2 = 0; t2 < 2; t2++) {
        int srow = m0 + wm + qrow + t2 * 8;
        float inv = 1.f / lrow[t2];
        size_t base = ((size_t)(b * SEQ + srow)) * DM + h * HDIM;
#pragma unroll
        for (int nf = 0; nf < 8; nf++) {
            *reinterpret_cast<bf2*>((bf*)fwdb + base + nf * 8 + qcol * 2) =
                __floats2bfloat162_rn(o[nf][t2 * 2] * inv, o[nf][t2 * 2 + 1] * inv);
        }
    }
}

// ---------------- tiled window-32 backward attention (bf16 inputs) ----------------
__global__ void __launch_bounds__(256) bwd_attn_kernel(
    const unsigned short* __restrict__ Qb, const unsigned short* __restrict__ Kb,
    const unsigned short* __restrict__ Vb, unsigned short* __restrict__ bwdb)
{
    extern __shared__ float bsm[];
    float* Ks = bsm;              // 96 x 65
    float* Vs = bsm + 96 * 65;    // 96 x 65
    __shared__ float qsh[8][66];

    const int m0 = blockIdx.x * 64;
    const int bh = blockIdx.y;
    const bf* Qp = (const bf*)Qb + (size_t)bh * SEQ * HDIM;
    const bf* Kp = (const bf*)Kb + (size_t)bh * SEQ * HDIM;
    const bf* Vp = (const bf*)Vb + (size_t)bh * SEQ * HDIM;
    const int b = bh >> 4, h = bh & 15;

    const int tid = threadIdx.x, wid = tid >> 5, lane = tid & 31;
    const int nrows = min(96, SEQ - 1 - m0);

    for (int i = tid; i < nrows * 8; i += 256) {
        int row = i >> 3, c8 = (i & 7) * 8;
        uint4 tk = *reinterpret_cast<const uint4*>(Kp + (size_t)(m0 + 1 + row) * HDIM + c8);
        uint4 tv = *reinterpret_cast<const uint4*>(Vp + (size_t)(m0 + 1 + row) * HDIM + c8);
        const bf2* pk = reinterpret_cast<const bf2*>(&tk);
        const bf2* pv = reinterpret_cast<const bf2*>(&tv);
        float* dk = Ks + row * 65 + c8;
        float* dv = Vs + row * 65 + c8;
#pragma unroll
        for (int j = 0; j < 4; j++) {
            float2 fk = __bfloat1622float2(pk[j]);
            float2 fv = __bfloat1622float2(pv[j]);
            dk[2 * j] = fk.x; dk[2 * j + 1] = fk.y;
            dv[2 * j] = fv.x; dv[2 * j + 1] = fv.y;
        }
    }
    __syncthreads();

#pragma unroll
    for (int t = 0; t < 8; t++) {
        const int m = m0 + wid * 8 + t;
        int w = SEQ - 1 - m; if (w > 32) w = 32;
        if (w <= 0) continue;

        __syncwarp();
        qsh[wid][lane]      = __bfloat162float(Qp[m * HDIM + lane]);
        qsh[wid][lane + 32] = __bfloat162float(Qp[m * HDIM + lane + 32]);
        __syncwarp();

        float sc = -1e30f;
        if (lane < w) {
            const float* kr = Ks + (m - m0 + lane) * 65;
            float a = 0.f;
#pragma unroll
            for (int d = 0; d < HDIM; d++) a += qsh[wid][d] * kr[d];
            sc = a * 0.125f;
        }
        float mx = sc;
#pragma unroll
        for (int o = 16; o > 0; o >>= 1) mx = fmaxf(mx, __shfl_xor_sync(0xffffffffu, mx, o));
        float e = __expf(sc - mx);
        float sum = e;
#pragma unroll
        for (int o = 16; o > 0; o >>= 1) sum += __shfl_xor_sync(0xffffffffu, sum, o);
        float p = e / sum;

        float o0 = 0.f, o1 = 0.f;
        for (int kk = 0; kk < w; kk++) {
            float pk = __shfl_sync(0xffffffffu, p, kk);
            const float* vr = Vs + (m - m0 + kk) * 65;
            o0 += pk * vr[lane];
            o1 += pk * vr[lane + 32];
        }
        bf* outp = (bf*)bwdb + ((size_t)(b * SEQ + m)) * DM + h * HDIM;
        outp[lane] = __float2bfloat16(o0);
        outp[lane + 32] = __float2bfloat16(o1);
    }
}

// mean of Vb over all S for the all-masked last row (bf16 input)
__global__ void vb_mean_kernel(const unsigned short* __restrict__ Vb,
                               unsigned short* __restrict__ bwdb) {
    __shared__ float part[4][64];
    const int bh = blockIdx.x, tid = threadIdx.x;
    const int col = tid & 63, grp = tid >> 6;
    const bf* Vp = (const bf*)Vb + (size_t)bh * SEQ * HDIM;
    float s = 0.f;
    for (int r = grp; r < SEQ; r += 4) s += __bfloat162float(Vp[(size_t)r * HDIM + col]);
    part[grp][col] = s;
    __syncthreads();
    if (tid < 64) {
        float m = (part[0][tid] + part[1][tid] + part[2][tid] + part[3][tid]) * (1.f / SEQ);
        int b = bh >> 4, h = bh & 15;
        ((bf*)bwdb)[((size_t)(b * SEQ + SEQ - 1)) * DM + h * HDIM + tid] = __float2bfloat16(m);
    }
}

// ---------------- gate LN + sigmoid + fusion (bf16 fwd/bwd) ----------------
__global__ void gate_fuse_kernel(const float* __restrict__ gpre,
                                 const unsigned short* __restrict__ fwdb,
                                 const unsigned short* __restrict__ bwdb,
                                 const float* __restrict__ gg, const float* __restrict__ gb,
                                 const float* __restrict__ bstr, unsigned short* __restrict__ fusedb) {
    const int r = blockIdx.x, tid = threadIdx.x;
    const float* rowp = gpre + (size_t)r * DM;
    __shared__ float red[256];
    float v[4]; float s = 0.f, ss = 0.f;
#pragma unroll
    for (int i = 0; i < 4; i++) { v[i] = rowp[tid + i * 256]; s += v[i]; ss += v[i] * v[i]; }
    red[tid] = s; __syncthreads();
    for (int o = 128; o > 0; o >>= 1) { if (tid < o) red[tid] += red[tid + o]; __syncthreads(); }
    float mean = red[0] * (1.f / DM); __syncthreads();
    red[tid] = ss; __syncthreads();
    for (int o = 128; o > 0; o >>= 1) { if (tid < o) red[tid] += red[tid + o]; __syncthreads(); }
    float var = red[0] * (1.f / DM) - mean * mean;
    float rstd = rsqrtf(var + 1e-5f);
    float strength = 0.3f * sigmoidf_(bstr[0]);
#pragma unroll
    for (int i = 0; i < 4; i++) {
        int j = tid + i * 256;
        float g = sigmoidf_((v[i] - mean) * rstd * gg[j] + gb[j]);
        size_t o = (size_t)r * DM + j;
        float fw = __bfloat162float(((const bf*)fwdb)[o]);
        float bw = __bfloat162float(((const bf*)bwdb)[o]);
        ((bf*)fusedb)[o] = __float2bfloat16(fw + strength * g * bw);
    }
}

// ---------------- final residual + LayerNorm ----------------
__global__ void final_ln_kernel(const float* __restrict__ x, const float* __restrict__ o2,
                                const float* __restrict__ lg, const float* __restrict__ lb,
                                float* __restrict__ out) {
    const int r = blockIdx.x, tid = threadIdx.x;
    __shared__ float red[256];
    float v[4]; float s = 0.f, ss = 0.f;
#pragma unroll
    for (int i = 0; i < 4; i++) {
        size_t o = (size_t)r * DM + tid + i * 256;
        v[i] = x[o] + o2[o];
        s += v[i]; ss += v[i] * v[i];
    }
    red[tid] = s; __syncthreads();
    for (int o = 128; o > 0; o >>= 1) { if (tid < o) red[tid] += red[tid + o]; __syncthreads(); }
    float mean = red[0] * (1.f / DM); __syncthreads();
    red[tid] = ss; __syncthreads();
    for (int o = 128; o > 0; o >>= 1) { if (tid < o) red[tid] += red[tid + o]; __syncthreads(); }
    float var = red[0] * (1.f / DM) - mean * mean;
    float rstd = rsqrtf(var + 1e-5f);
#pragma unroll
    for (int i = 0; i < 4; i++) {
        int j = tid + i * 256;
        size_t o = (size_t)r * DM + j;
        out[o] = (v[i] - mean) * rstd * lg[j] + lb[j];
    }
}

// ---------------- launch ----------------
extern "C" void kernel_launch(void* const* d_in, const int* in_sizes, int n_in,
                              void* d_out, int out_size) {
    const float* x      = (const float*)d_in[0];
    const float* fq_w   = (const float*)d_in[1];
    const float* fq_b   = (const float*)d_in[2];
    const float* fk_w   = (const float*)d_in[3];
    const float* fk_b   = (const float*)d_in[4];
    const float* fv_w   = (const float*)d_in[5];
    const float* fv_b   = (const float*)d_in[6];
    const float* bq_w   = (const float*)d_in[7];
    const float* bq_b   = (const float*)d_in[8];
    const float* bk_w   = (const float*)d_in[9];
    const float* bk_b   = (const float*)d_in[10];
    const float* bv_w   = (const float*)d_in[11];
    const float* bv_b   = (const float*)d_in[12];
    const float* gate_w = (const float*)d_in[13];
    const float* gate_b = (const float*)d_in[14];
    const float* gln_g  = (const float*)d_in[15];
    const float* gln_b  = (const float*)d_in[16];
    const float* bstr   = (const float*)d_in[17];
    const float* out_w  = (const float*)d_in[18];
    const float* out_b  = (const float*)d_in[19];
    const float* ln_g   = (const float*)d_in[20];
    const float* ln_b   = (const float*)d_in[21];

    unsigned short *xb, *gwt, *fwdb, *bwdb, *fusedb, *wt7, *hb16;
    float *unused, *gpre, *out2;
    cudaGetSymbolAddress((void**)&xb,     g_xb);
    cudaGetSymbolAddress((void**)&wt7,    g_wt7);
    cudaGetSymbolAddress((void**)&gwt,    g_gwt);
    cudaGetSymbolAddress((void**)&hb16,   g_hb16);
    cudaGetSymbolAddress((void**)&unused, g_unused);
    cudaGetSymbolAddress((void**)&fwdb,   g_fwdb);
    cudaGetSymbolAddress((void**)&bwdb,   g_bwdb);
    cudaGetSymbolAddress((void**)&fusedb, g_fusedb);
    cudaGetSymbolAddress((void**)&gpre,   g_gpre);
    cudaGetSymbolAddress((void**)&out2,   g_out2);

    const size_t span = (size_t)BHT * SEQ * HDIM;
    const int flashSmem = 73728;
    const int gemmSmem  = 3 * (GSTAGE_A + GSTAGE_B) * 2;   // 61440
    const int bwdSmem   = 2 * 96 * 65 * 4;                 // 49920
    cudaFuncSetAttribute(flash_fwd_kernel,
                         cudaFuncAttributeMaxDynamicSharedMemorySize, flashSmem);
    cudaFuncSetAttribute(gemm_bf<0>,
                         cudaFuncAttributeMaxDynamicSharedMemorySize, gemmSmem);
    cudaFuncSetAttribute(gemm_bf<1>,
                         cudaFuncAttributeMaxDynamicSharedMemorySize, gemmSmem);
    cudaFuncSetAttribute(bwd_attn_kernel,
                         cudaFuncAttributeMaxDynamicSharedMemorySize, bwdSmem);

    // conversions
    cvt_x_kernel<<<(MROWS * DM / 4) / 256, 256>>>((const float4*)x, (bf2*)xb);
    {
        TW t;
        const float* W[7] = {fq_w, fk_w, fv_w, bq_w, bk_w, bv_w, out_w};
        for (int i = 0; i < 7; i++) { t.W[i] = W[i]; t.Wt[i] = wt7 + (size_t)i * DM * DM; }
        transpose_w7<<<dim3(DM / 32, DM / 32, 7), dim3(32, 8)>>>(t);
        transpose_w_kernel<<<dim3(DM / 32, 2 * DM / 32), dim3(32, 8)>>>(gate_w, gwt, 2 * DM, DM);
    }

    // 6 fused projections: all outputs bf16 only
    {
        GB a = {};
        a.A0 = xb; a.K = DM; a.N = DM; a.KA0 = DM;
        a.maskF = 0; a.maskB = 0b111111;
        const float* Bb[6] = {fq_b, fk_b, fv_b, bq_b, bk_b, bv_b};
        for (int i = 0; i < 6; i++) {
            a.Bt6[i] = wt7 + (size_t)i * DM * DM;
            a.b6[i] = Bb[i];
            a.o6[i] = unused;
            a.ob6[i] = hb16 + (size_t)i * span;
        }
        gemm_bf<0><<<dim3(DM / BN, MROWS / BM, 6), 128, gemmSmem>>>(a);
    }

    // flash attention (all bf16)
    flash_fwd_kernel<<<dim3(SEQ / 128, BHT), 256, flashSmem>>>(
        hb16, hb16 + span, hb16 + 2 * span, fwdb);

    // window backward attention + last-row mean (bf16 in)
    bwd_attn_kernel<<<dim3(SEQ / 64, BHT), 256, bwdSmem>>>(
        hb16 + 3 * span, hb16 + 4 * span, hb16 + 5 * span, bwdb);
    vb_mean_kernel<<<BHT, 256>>>(hb16 + 5 * span, bwdb);

    // gate gemm
    {
        GB a = {};
        a.A0 = fwdb; a.A1 = bwdb; a.Bt = gwt; a.bias = gate_b; a.Cf = gpre;
        a.N = DM; a.K = 2 * DM; a.KA0 = DM;
        gemm_bf<1><<<dim3(DM / BN, MROWS / BM, 1), 128, gemmSmem>>>(a);
    }
    gate_fuse_kernel<<<MROWS, 256>>>(gpre, fwdb, bwdb, gln_g, gln_b, bstr, fusedb);

    // output projection
    {
        GB a = {};
        a.A0 = fusedb; a.A1 = fusedb; a.Bt = wt7 + (size_t)6 * DM * DM;
        a.bias = out_b; a.Cf = out2;
        a.N = DM; a.K = DM; a.KA0 = DM;
        gemm_bf<1><<<dim3(DM / BN, MROWS / BM, 1), 128, gemmSmem>>>(a);
    }
    final_ln_kernel<<<MROWS, 256>>>(x, out2, ln_g, ln_b, (float*)d_out);
}